// round 1
// baseline (speedup 1.0000x reference)
#include <cuda_runtime.h>
#include <math.h>

#define DM   2048
#define SEQ  2048
#define BATCH 2
#define NH   32
#define NG   8
#define DH   64

// Scratch (allocation-free rule: __device__ globals)
__device__ float g_q[BATCH * NH * SEQ * DH];    // [b][h][s][d]  32 MB
__device__ float g_k[BATCH * NG * SEQ * DH];    // [b][g][s][d]   8 MB
__device__ float g_v[BATCH * NG * SEQ * DH];    // [b][g][s][d]   8 MB
__device__ float g_ctx[BATCH * SEQ * NH * DH];  // [b][s][h*64+d] 32 MB

// ---------------------------------------------------------------------------
// Tiled SGEMM: C(MxN) = A(MxK) @ B(KxN), row-major.
// 64x64 block tile, 256 threads, 4x4 register tile, BK=16.
// mode 0: plain row-major out + bias.  mode 1: head layout [b][h][s][d].
// ---------------------------------------------------------------------------
__global__ void sgemm64(const float* __restrict__ A, const float* __restrict__ Bm,
                        float* __restrict__ C, int M, int N, int K,
                        int mode, const float* __restrict__ bias, int heads)
{
    __shared__ float As[16][68];   // A tile transposed [k][m], padded
    __shared__ float Bs[16][64];   // B tile [k][n]

    const int tid = threadIdx.x;
    const int tx = tid & 15, ty = tid >> 4;
    const int m0 = blockIdx.y << 6, n0 = blockIdx.x << 6;

    float acc[4][4] = {};

    const float* Aptr = A + (size_t)m0 * K;

    for (int k0 = 0; k0 < K; k0 += 16) {
#pragma unroll
        for (int i = 0; i < 4; i++) {
            int idx = tid + (i << 8);
            int r = idx >> 4, kk = idx & 15;
            As[kk][r] = Aptr[(size_t)r * K + k0 + kk];
        }
#pragma unroll
        for (int i = 0; i < 4; i++) {
            int idx = tid + (i << 8);
            int kk = idx >> 6, c = idx & 63;
            Bs[kk][c] = Bm[(size_t)(k0 + kk) * N + n0 + c];
        }
        __syncthreads();
#pragma unroll
        for (int kk = 0; kk < 16; kk++) {
            float4 av = *reinterpret_cast<const float4*>(&As[kk][ty << 2]);
            float4 bv = *reinterpret_cast<const float4*>(&Bs[kk][tx << 2]);
            float ar[4] = {av.x, av.y, av.z, av.w};
            float br[4] = {bv.x, bv.y, bv.z, bv.w};
#pragma unroll
            for (int i = 0; i < 4; i++)
#pragma unroll
                for (int j = 0; j < 4; j++)
                    acc[i][j] += ar[i] * br[j];
        }
        __syncthreads();
    }

#pragma unroll
    for (int i = 0; i < 4; i++) {
        int row = m0 + (ty << 2) + i;
#pragma unroll
        for (int j = 0; j < 4; j++) {
            int col = n0 + (tx << 2) + j;
            float val = acc[i][j];
            if (mode == 0) {
                C[(size_t)row * N + col] = val + bias[col];
            } else {
                int bb = row >> 11;       // row / SEQ
                int s  = row & (SEQ - 1);
                int hh = col >> 6;
                int d  = col & 63;
                C[(((size_t)(bb * heads + hh)) * SEQ + s) * DH + d] = val;
            }
        }
    }
}

// ---------------------------------------------------------------------------
// Interleaved RoPE, in-place, over buffer [rows][SEQ][64] where rows = B*heads.
// One thread per (row, s, pair).
// ---------------------------------------------------------------------------
__global__ void rope_kernel(float* __restrict__ x, int n_pairs)
{
    int idx = blockIdx.x * blockDim.x + threadIdx.x;
    if (idx >= n_pairs) return;
    int pair = idx & 31;
    int rs   = idx >> 5;           // (b*heads + h)*SEQ + s
    int s    = rs & (SEQ - 1);

    float inv = powf(10000.f, -(float)(2 * pair) * (1.f / 64.f));
    float ang = (float)s * inv;
    float sn, c;
    sincosf(ang, &sn, &c);

    float* p = x + ((size_t)rs << 6) + (pair << 1);
    float x0 = p[0], x1 = p[1];
    p[0] = x0 * c - x1 * sn;
    p[1] = x1 * c + x0 * sn;
}

// ---------------------------------------------------------------------------
// Flash-style causal attention with ALiBi + grok tanh-clamp.
// One CTA per (q_tile of 64, head, batch). 256 threads, 4x4 register tiles.
// Dynamic smem: Qs[64][64], Kst[64][65] (K transposed; reused as P[row][col]),
// Vs[64][64]  => 49408 bytes.
// ---------------------------------------------------------------------------
__global__ void attn64(const float* __restrict__ q, const float* __restrict__ k,
                       const float* __restrict__ v, float* __restrict__ ctx)
{
    extern __shared__ float sm[];
    float* Qs  = sm;                       // [64][64]
    float* Kst = sm + 64 * 64;             // [64][65]: Kst[d*65 + kpos]; later P[row*65 + col]
    float* Vs  = sm + 64 * 64 + 64 * 65;   // [64][64]: Vs[kpos*64 + d]

    const int tid = threadIdx.x;
    const int tx = tid & 15, ty = tid >> 4;
    const int qt = blockIdx.x, h = blockIdx.y, b = blockIdx.z;
    const int g = h >> 2;                  // n_rep = 4 (repeat_interleave)
    const int q0 = qt << 6;

    const float* qb = q + (((size_t)(b * NH + h)) * SEQ + q0) * DH;
    const float* kb = k + ((size_t)(b * NG + g)) * SEQ * DH;
    const float* vb = v + ((size_t)(b * NG + g)) * SEQ * DH;

#pragma unroll
    for (int i = 0; i < 16; i++) {
        int idx = tid + (i << 8);
        Qs[idx] = qb[idx];                 // [r][d] contiguous, no pad
    }

    float mrow[4], lrow[4], acc[4][4];
#pragma unroll
    for (int i = 0; i < 4; i++) {
        mrow[i] = -1e30f; lrow[i] = 0.f;
#pragma unroll
        for (int j = 0; j < 4; j++) acc[i][j] = 0.f;
    }
    const float slope = exp2f(-(float)(h + 1) * 0.25f);   // 2^(-(h+1)*8/32)

    for (int kt = 0; kt <= qt; kt++) {
        const int kpos0 = kt << 6;
        __syncthreads();   // previous PV done (and Qs visible on first iter)
#pragma unroll
        for (int i = 0; i < 16; i++) {
            int idx = tid + (i << 8);
            int r = idx >> 6, d = idx & 63;
            Kst[d * 65 + r] = kb[(size_t)kpos0 * DH + idx];
            Vs[idx]         = vb[(size_t)kpos0 * DH + idx];
        }
        __syncthreads();

        // S = Q @ K^T  (64x64 tile, 4x4 per thread)
        float sc[4][4] = {};
#pragma unroll 16
        for (int d = 0; d < 64; d++) {
            float qv[4], kv[4];
#pragma unroll
            for (int i = 0; i < 4; i++) qv[i] = Qs[(((ty << 2) + i) << 6) + d];
#pragma unroll
            for (int j = 0; j < 4; j++) kv[j] = Kst[d * 65 + (tx << 2) + j];
#pragma unroll
            for (int i = 0; i < 4; i++)
#pragma unroll
                for (int j = 0; j < 4; j++)
                    sc[i][j] += qv[i] * kv[j];
        }

        // ALiBi + scale + tanh clamp + causal mask + online softmax
        float pr[4][4];
#pragma unroll
        for (int i = 0; i < 4; i++) {
            int qpos = q0 + (ty << 2) + i;
            float tmax = -1e30f;
#pragma unroll
            for (int j = 0; j < 4; j++) {
                int kpos = kpos0 + (tx << 2) + j;
                float sv = (sc[i][j] - slope * (float)(qpos - kpos)) * 0.125f;
                sv = 30.f * tanhf(sv * (1.f / 30.f));
                if (kpos > qpos) sv = -1e30f;
                sc[i][j] = sv;
                tmax = fmaxf(tmax, sv);
            }
#pragma unroll
            for (int off = 8; off; off >>= 1)
                tmax = fmaxf(tmax, __shfl_xor_sync(0xffffffffu, tmax, off, 16));
            float mn   = fmaxf(mrow[i], tmax);
            float corr = __expf(mrow[i] - mn);
            mrow[i] = mn;
            float rsum = 0.f;
#pragma unroll
            for (int j = 0; j < 4; j++) {
                float p = __expf(sc[i][j] - mn);
                pr[i][j] = p;
                rsum += p;
            }
#pragma unroll
            for (int off = 8; off; off >>= 1)
                rsum += __shfl_xor_sync(0xffffffffu, rsum, off, 16);
            lrow[i] = lrow[i] * corr + rsum;
#pragma unroll
            for (int j = 0; j < 4; j++) acc[i][j] *= corr;
        }
        __syncthreads();   // done reading Kst as K

        // P into Kst buffer as [row][col] (pad 65)
#pragma unroll
        for (int i = 0; i < 4; i++)
#pragma unroll
            for (int j = 0; j < 4; j++)
                Kst[((ty << 2) + i) * 65 + (tx << 2) + j] = pr[i][j];
        __syncthreads();

        // O += P @ V
#pragma unroll 16
        for (int kk = 0; kk < 64; kk++) {
            float pv[4], vv[4];
#pragma unroll
            for (int i = 0; i < 4; i++) pv[i] = Kst[((ty << 2) + i) * 65 + kk];
#pragma unroll
            for (int j = 0; j < 4; j++) vv[j] = Vs[(kk << 6) + (tx << 2) + j];
#pragma unroll
            for (int i = 0; i < 4; i++)
#pragma unroll
                for (int j = 0; j < 4; j++)
                    acc[i][j] += pv[i] * vv[j];
        }
    }

    // Normalize and write ctx in [b][s][h*64+d] layout (A matrix of out-proj)
#pragma unroll
    for (int i = 0; i < 4; i++) {
        float inv = 1.f / lrow[i];
        int srow = q0 + (ty << 2) + i;
#pragma unroll
        for (int j = 0; j < 4; j++) {
            ctx[((size_t)b * SEQ + srow) * (NH * DH) + h * DH + (tx << 2) + j]
                = acc[i][j] * inv;
        }
    }
}

// ---------------------------------------------------------------------------
extern "C" void kernel_launch(void* const* d_in, const int* in_sizes, int n_in,
                              void* d_out, int out_size)
{
    const float* hs = (const float*)d_in[0];
    const float* Wq = (const float*)d_in[1];
    const float* Wk = (const float*)d_in[2];
    const float* Wv = (const float*)d_in[3];
    const float* Wo = (const float*)d_in[4];
    const float* bo = (const float*)d_in[5];
    float* out = (float*)d_out;

    float *q, *k, *v, *ctx;
    cudaGetSymbolAddress((void**)&q,   g_q);
    cudaGetSymbolAddress((void**)&k,   g_k);
    cudaGetSymbolAddress((void**)&v,   g_v);
    cudaGetSymbolAddress((void**)&ctx, g_ctx);

    const int M = BATCH * SEQ;   // 4096
    dim3 blk(256);

    // QKV projections with fused [b][h][s][d] layout epilogue
    sgemm64<<<dim3((NH * DH) / 64, M / 64), blk>>>(hs, Wq, q, M, NH * DH, DM, 1, nullptr, NH);
    sgemm64<<<dim3((NG * DH) / 64, M / 64), blk>>>(hs, Wk, k, M, NG * DH, DM, 1, nullptr, NG);
    sgemm64<<<dim3((NG * DH) / 64, M / 64), blk>>>(hs, Wv, v, M, NG * DH, DM, 1, nullptr, NG);

    // RoPE on q and k
    {
        int np_q = BATCH * NH * SEQ * 32;
        int np_k = BATCH * NG * SEQ * 32;
        rope_kernel<<<(np_q + 255) / 256, 256>>>(q, np_q);
        rope_kernel<<<(np_k + 255) / 256, 256>>>(k, np_k);
    }

    // Attention
    {
        const int smem = (64 * 64 + 64 * 65 + 64 * 64) * (int)sizeof(float); // 49408
        cudaFuncSetAttribute(attn64, cudaFuncAttributeMaxDynamicSharedMemorySize, smem);
        attn64<<<dim3(SEQ / 64, NH, BATCH), blk, smem>>>(q, k, v, ctx);
    }

    // Output projection + bias
    sgemm64<<<dim3(DM / 64, M / 64), blk>>>(ctx, Wo, out, M, DM, DM, 0, bo, 0);
}

// round 3
// speedup vs baseline: 1.9183x; 1.9183x over previous
#include <cuda_runtime.h>
#include <cuda_bf16.h>
#include <math.h>
#include <stdint.h>

#define DM    2048
#define SEQ   2048
#define BATCH 2
#define NH    32
#define NG    8
#define DH    64
#define MROWS (BATCH*SEQ)   // 4096

// ---------------- scratch (__device__ globals; no allocs allowed) ----------
__device__ float g_q[(size_t)BATCH*NH*SEQ*DH];     // [b][h][s][d]
__device__ float g_k[(size_t)BATCH*NG*SEQ*DH];
__device__ float g_v[(size_t)BATCH*NG*SEQ*DH];
__device__ float g_ctx[(size_t)BATCH*SEQ*NH*DH];   // [b][s][h*64+d]
__device__ __nv_bfloat16 g_ah[(size_t)MROWS*DM];
__device__ __nv_bfloat16 g_al[(size_t)MROWS*DM];
__device__ __nv_bfloat16 g_wqh[(size_t)DM*DM],  g_wql[(size_t)DM*DM];
__device__ __nv_bfloat16 g_wkh[(size_t)512*DM], g_wkl[(size_t)512*DM];
__device__ __nv_bfloat16 g_wvh[(size_t)512*DM], g_wvl[(size_t)512*DM];
__device__ __nv_bfloat16 g_woh[(size_t)DM*DM],  g_wol[(size_t)DM*DM];

// ---------------- helpers ---------------------------------------------------
__device__ __forceinline__ uint32_t smem_u32(const void* p) {
    uint32_t a;
    asm("{ .reg .u64 t; cvta.to.shared.u64 t, %1; cvt.u32.u64 %0, t; }" : "=r"(a) : "l"(p));
    return a;
}
__device__ __forceinline__ void ldsm4(uint32_t* r, uint32_t addr) {
    asm volatile("ldmatrix.sync.aligned.m8n8.x4.shared.b16 {%0,%1,%2,%3}, [%4];"
                 : "=r"(r[0]), "=r"(r[1]), "=r"(r[2]), "=r"(r[3]) : "r"(addr));
}
__device__ __forceinline__ void mma16816(float* c, const uint32_t* a, const uint32_t* b) {
    asm volatile("mma.sync.aligned.m16n8k16.row.col.f32.bf16.bf16.f32 "
                 "{%0,%1,%2,%3}, {%4,%5,%6,%7}, {%8,%9}, {%0,%1,%2,%3};"
                 : "+f"(c[0]), "+f"(c[1]), "+f"(c[2]), "+f"(c[3])
                 : "r"(a[0]), "r"(a[1]), "r"(a[2]), "r"(a[3]), "r"(b[0]), "r"(b[1]));
}
#define CP_ASYNC16(s, g) \
    asm volatile("cp.async.cg.shared.global [%0], [%1], 16;" :: "r"(s), "l"(g))
#define CP_COMMIT() asm volatile("cp.async.commit_group;" ::: "memory")
#define CP_WAIT1()  asm volatile("cp.async.wait_group 1;" ::: "memory")

// ---------------------------------------------------------------------------
// bf16x3 HMMA GEMM: C[M,Ntot] = A @ B^T.  A hi/lo [M,2048], B hi/lo [Ntot,2048].
// 128x128 CTA tile, BK=32, 256 threads (8 warps as 2x4, warp tile 64x32).
// SMEM stage = {Ah,Al,Bh,Bl} 128x32 bf16 tiles (8KB each), double buffered.
// Swizzle (store & ldmatrix): byteoff = r*64 + ((c ^ ((r>>1)&3))<<4), c=16B chunk.
// mode 0: row-major out + bias.  mode 1: head layout [b][h][s][d].
// ---------------------------------------------------------------------------
__global__ __launch_bounds__(256, 1)
void gemm_mma(const __nv_bfloat16* __restrict__ Ah, const __nv_bfloat16* __restrict__ Al,
              const __nv_bfloat16* __restrict__ Bh, const __nv_bfloat16* __restrict__ Bl,
              float* __restrict__ C, int Ntot, int mode,
              const float* __restrict__ bias, int heads)
{
    extern __shared__ __align__(128) char smc[];
    const uint32_t sbase = smem_u32(smc);
    const int tid = threadIdx.x, lane = tid & 31, wid = tid >> 5;
    const int wm = wid >> 2, wn = wid & 3;               // 2 x 4 warp grid
    const int n0 = blockIdx.x << 7, m0 = blockIdx.y << 7;

    // per-thread cp.async coords
    const int fr = tid >> 2;        // 0..63 (two rows per thread: fr, fr+64)
    const int fc = tid & 3;         // 16B chunk

    // ldmatrix per-lane offsets within a tile
    uint32_t offA[4][2], offB[2][2];
#pragma unroll
    for (int mf = 0; mf < 4; mf++)
#pragma unroll
        for (int ks = 0; ks < 2; ks++) {
            int row = wm * 64 + mf * 16 + (lane & 7) + ((lane >> 3) & 1) * 8;
            int ch  = ks * 2 + (lane >> 4);
            offA[mf][ks] = row * 64 + ((ch ^ ((row >> 1) & 3)) << 4);
        }
#pragma unroll
    for (int np = 0; np < 2; np++)
#pragma unroll
        for (int ks = 0; ks < 2; ks++) {
            int row = wn * 32 + np * 16 + (lane & 7) + (lane >> 4) * 8;
            int ch  = ks * 2 + ((lane >> 3) & 1);
            offB[np][ks] = row * 64 + ((ch ^ ((row >> 1) & 3)) << 4);
        }

    float acc[4][4][4];
#pragma unroll
    for (int i = 0; i < 4; i++)
#pragma unroll
        for (int j = 0; j < 4; j++)
#pragma unroll
            for (int l = 0; l < 4; l++) acc[i][j][l] = 0.f;

    // fill one stage for K-chunk kc
    auto fill = [&](int kc, int stage) {
        const uint32_t sb = sbase + stage * 32768;
#pragma unroll
        for (int i = 0; i < 2; i++) {
            const int r = fr + i * 64;
            const uint32_t so = r * 64 + ((fc ^ ((r >> 1) & 3)) << 4);
            const size_t gA = (size_t)(m0 + r) * DM + kc * 32 + fc * 8;
            const size_t gB = (size_t)(n0 + r) * DM + kc * 32 + fc * 8;
            CP_ASYNC16(sb +         so, Ah + gA);
            CP_ASYNC16(sb +  8192 + so, Al + gA);
            CP_ASYNC16(sb + 16384 + so, Bh + gB);
            CP_ASYNC16(sb + 24576 + so, Bl + gB);
        }
        CP_COMMIT();
    };

    fill(0, 0);
    fill(1, 1);

    const int NKC = DM / 32;   // 64
    for (int kc = 0; kc < NKC; kc++) {
        CP_WAIT1();
        __syncthreads();
        const uint32_t sA = sbase + (kc & 1) * 32768;
#pragma unroll
        for (int ks = 0; ks < 2; ks++) {
            uint32_t ah[4][4], al[4][4], bh[2][4], bl[2][4];
#pragma unroll
            for (int mf = 0; mf < 4; mf++) {
                ldsm4(ah[mf], sA +        offA[mf][ks]);
                ldsm4(al[mf], sA + 8192 + offA[mf][ks]);
            }
#pragma unroll
            for (int np = 0; np < 2; np++) {
                ldsm4(bh[np], sA + 16384 + offB[np][ks]);
                ldsm4(bl[np], sA + 24576 + offB[np][ks]);
            }
#pragma unroll
            for (int mf = 0; mf < 4; mf++)
#pragma unroll
                for (int nf = 0; nf < 4; nf++) {
                    const uint32_t* bhp = &bh[nf >> 1][(nf & 1) * 2];
                    const uint32_t* blp = &bl[nf >> 1][(nf & 1) * 2];
                    mma16816(acc[mf][nf], ah[mf], bhp);
                    mma16816(acc[mf][nf], ah[mf], blp);
                    mma16816(acc[mf][nf], al[mf], bhp);
                }
        }
        __syncthreads();
        if (kc + 2 < NKC) fill(kc + 2, kc & 1);
        else CP_COMMIT();   // empty group keeps wait_group accounting uniform
    }

    // epilogue: write accumulators
    const int g4 = lane >> 2, t4 = lane & 3;
#pragma unroll
    for (int mf = 0; mf < 4; mf++) {
#pragma unroll
        for (int nf = 0; nf < 4; nf++) {
            const int row = m0 + wm * 64 + mf * 16 + g4;
            const int col = n0 + wn * 32 + nf * 8 + t4 * 2;
            float2 v0 = make_float2(acc[mf][nf][0], acc[mf][nf][1]);
            float2 v1 = make_float2(acc[mf][nf][2], acc[mf][nf][3]);
            if (mode == 0) {
                const float b0 = bias[col], b1 = bias[col + 1];
                v0.x += b0; v0.y += b1; v1.x += b0; v1.y += b1;
                *reinterpret_cast<float2*>(C + (size_t)row * Ntot + col)       = v0;
                *reinterpret_cast<float2*>(C + (size_t)(row + 8) * Ntot + col) = v1;
            } else {
                const int hh = col >> 6, d = col & 63;
                const int bb0 = row >> 11, s0 = row & (SEQ - 1);
                const int bb1 = (row + 8) >> 11, s1 = (row + 8) & (SEQ - 1);
                *reinterpret_cast<float2*>(
                    C + (((size_t)(bb0 * heads + hh)) * SEQ + s0) * DH + d) = v0;
                *reinterpret_cast<float2*>(
                    C + (((size_t)(bb1 * heads + hh)) * SEQ + s1) * DH + d) = v1;
            }
        }
    }
}

// ---------------------------------------------------------------------------
// fp32 -> bf16 hi/lo split
// ---------------------------------------------------------------------------
__global__ void split_kernel(const float* __restrict__ x,
                             __nv_bfloat16* __restrict__ hi,
                             __nv_bfloat16* __restrict__ lo, int n4)
{
    int i = blockIdx.x * blockDim.x + threadIdx.x;
    if (i >= n4) return;
    float4 v = reinterpret_cast<const float4*>(x)[i];
    float f[4] = {v.x, v.y, v.z, v.w};
    __nv_bfloat16 h[4], l[4];
#pragma unroll
    for (int j = 0; j < 4; j++) {
        h[j] = __float2bfloat16_rn(f[j]);
        l[j] = __float2bfloat16_rn(f[j] - __bfloat162float(h[j]));
    }
    reinterpret_cast<uint2*>(hi)[i] = *reinterpret_cast<uint2*>(h);
    reinterpret_cast<uint2*>(lo)[i] = *reinterpret_cast<uint2*>(l);
}

// ---------------------------------------------------------------------------
// W [K,N] fp32 -> Wt hi/lo [N,K] bf16
// ---------------------------------------------------------------------------
__global__ void transpose_split(const float* __restrict__ W,
                                __nv_bfloat16* __restrict__ Th,
                                __nv_bfloat16* __restrict__ Tl, int K, int N)
{
    __shared__ float t[32][33];
    const int n0 = blockIdx.x * 32, k0 = blockIdx.y * 32;
    const int tx = threadIdx.x, ty = threadIdx.y;
#pragma unroll
    for (int i = 0; i < 4; i++)
        t[ty + 8 * i][tx] = W[(size_t)(k0 + ty + 8 * i) * N + n0 + tx];
    __syncthreads();
#pragma unroll
    for (int i = 0; i < 4; i++) {
        float v = t[tx][ty + 8 * i];
        __nv_bfloat16 h = __float2bfloat16_rn(v);
        __nv_bfloat16 l = __float2bfloat16_rn(v - __bfloat162float(h));
        size_t o = (size_t)(n0 + ty + 8 * i) * K + k0 + tx;
        Th[o] = h; Tl[o] = l;
    }
}

// ---------------------------------------------------------------------------
// Interleaved RoPE
// ---------------------------------------------------------------------------
__global__ void rope_kernel(float* __restrict__ x, int n_pairs)
{
    int idx = blockIdx.x * blockDim.x + threadIdx.x;
    if (idx >= n_pairs) return;
    int pair = idx & 31;
    int rs   = idx >> 5;
    int s    = rs & (SEQ - 1);
    float inv = powf(10000.f, -(float)(2 * pair) * (1.f / 64.f));
    float ang = (float)s * inv;
    float sn, c;
    sincosf(ang, &sn, &c);
    float* p = x + ((size_t)rs << 6) + (pair << 1);
    float x0 = p[0], x1 = p[1];
    p[0] = x0 * c - x1 * sn;
    p[1] = x1 * c + x0 * sn;
}

// ---------------------------------------------------------------------------
// Flash-style causal attention (SIMT fp32), exp-based tanh clamp.
// ---------------------------------------------------------------------------
__global__ void attn64(const float* __restrict__ q, const float* __restrict__ k,
                       const float* __restrict__ v, float* __restrict__ ctx)
{
    extern __shared__ float smf[];
    float* Qs  = smf;
    float* Kst = smf + 64 * 64;
    float* Vs  = smf + 64 * 64 + 64 * 65;

    const int tid = threadIdx.x;
    const int tx = tid & 15, ty = tid >> 4;
    const int qt = blockIdx.x, h = blockIdx.y, b = blockIdx.z;
    const int g = h >> 2;
    const int q0 = qt << 6;

    const float* qb = q + (((size_t)(b * NH + h)) * SEQ + q0) * DH;
    const float* kb = k + ((size_t)(b * NG + g)) * SEQ * DH;
    const float* vb = v + ((size_t)(b * NG + g)) * SEQ * DH;

#pragma unroll
    for (int i = 0; i < 16; i++) {
        int idx = tid + (i << 8);
        Qs[idx] = qb[idx];
    }

    float mrow[4], lrow[4], acc[4][4];
#pragma unroll
    for (int i = 0; i < 4; i++) {
        mrow[i] = -1e30f; lrow[i] = 0.f;
#pragma unroll
        for (int j = 0; j < 4; j++) acc[i][j] = 0.f;
    }
    const float slope = exp2f(-(float)(h + 1) * 0.25f);

    for (int kt = 0; kt <= qt; kt++) {
        const int kpos0 = kt << 6;
        __syncthreads();
#pragma unroll
        for (int i = 0; i < 16; i++) {
            int idx = tid + (i << 8);
            int r = idx >> 6, d = idx & 63;
            Kst[d * 65 + r] = kb[(size_t)kpos0 * DH + idx];
            Vs[idx]         = vb[(size_t)kpos0 * DH + idx];
        }
        __syncthreads();

        float sc[4][4] = {};
#pragma unroll 16
        for (int d = 0; d < 64; d++) {
            float qv[4], kv[4];
#pragma unroll
            for (int i = 0; i < 4; i++) qv[i] = Qs[(((ty << 2) + i) << 6) + d];
#pragma unroll
            for (int j = 0; j < 4; j++) kv[j] = Kst[d * 65 + (tx << 2) + j];
#pragma unroll
            for (int i = 0; i < 4; i++)
#pragma unroll
                for (int j = 0; j < 4; j++)
                    sc[i][j] += qv[i] * kv[j];
        }

        float pr[4][4];
#pragma unroll
        for (int i = 0; i < 4; i++) {
            int qpos = q0 + (ty << 2) + i;
            float tmax = -1e30f;
#pragma unroll
            for (int j = 0; j < 4; j++) {
                int kpos = kpos0 + (tx << 2) + j;
                float sv = (sc[i][j] - slope * (float)(qpos - kpos)) * 0.125f;
                float t2 = fminf(sv * (2.f / 30.f), 20.f);
                float e = __expf(t2);
                sv = 30.f * __fdividef(e - 1.f, e + 1.f);
                if (kpos > qpos) sv = -1e30f;
                sc[i][j] = sv;
                tmax = fmaxf(tmax, sv);
            }
#pragma unroll
            for (int off = 8; off; off >>= 1)
                tmax = fmaxf(tmax, __shfl_xor_sync(0xffffffffu, tmax, off, 16));
            float mn   = fmaxf(mrow[i], tmax);
            float corr = __expf(mrow[i] - mn);
            mrow[i] = mn;
            float rsum = 0.f;
#pragma unroll
            for (int j = 0; j < 4; j++) {
                float p = __expf(sc[i][j] - mn);
                pr[i][j] = p;
                rsum += p;
            }
#pragma unroll
            for (int off = 8; off; off >>= 1)
                rsum += __shfl_xor_sync(0xffffffffu, rsum, off, 16);
            lrow[i] = lrow[i] * corr + rsum;
#pragma unroll
            for (int j = 0; j < 4; j++) acc[i][j] *= corr;
        }
        __syncthreads();

#pragma unroll
        for (int i = 0; i < 4; i++)
#pragma unroll
            for (int j = 0; j < 4; j++)
                Kst[((ty << 2) + i) * 65 + (tx << 2) + j] = pr[i][j];
        __syncthreads();

#pragma unroll 16
        for (int kk = 0; kk < 64; kk++) {
            float pv[4], vv[4];
#pragma unroll
            for (int i = 0; i < 4; i++) pv[i] = Kst[((ty << 2) + i) * 65 + kk];
#pragma unroll
            for (int j = 0; j < 4; j++) vv[j] = Vs[(kk << 6) + (tx << 2) + j];
#pragma unroll
            for (int i = 0; i < 4; i++)
#pragma unroll
                for (int j = 0; j < 4; j++)
                    acc[i][j] += pv[i] * vv[j];
        }
    }

#pragma unroll
    for (int i = 0; i < 4; i++) {
        float inv = 1.f / lrow[i];
        int srow = q0 + (ty << 2) + i;
#pragma unroll
        for (int j = 0; j < 4; j++) {
            ctx[((size_t)b * SEQ + srow) * (NH * DH) + h * DH + (tx << 2) + j]
                = acc[i][j] * inv;
        }
    }
}

// ---------------------------------------------------------------------------
extern "C" void kernel_launch(void* const* d_in, const int* in_sizes, int n_in,
                              void* d_out, int out_size)
{
    const float* hs = (const float*)d_in[0];
    const float* Wq = (const float*)d_in[1];
    const float* Wk = (const float*)d_in[2];
    const float* Wv = (const float*)d_in[3];
    const float* Wo = (const float*)d_in[4];
    const float* bo = (const float*)d_in[5];
    float* out = (float*)d_out;

    float *q, *k, *v, *ctx;
    __nv_bfloat16 *ah, *al, *wqh, *wql, *wkh, *wkl, *wvh, *wvl, *woh, *wol;
    cudaGetSymbolAddress((void**)&q,   g_q);
    cudaGetSymbolAddress((void**)&k,   g_k);
    cudaGetSymbolAddress((void**)&v,   g_v);
    cudaGetSymbolAddress((void**)&ctx, g_ctx);
    cudaGetSymbolAddress((void**)&ah,  g_ah);
    cudaGetSymbolAddress((void**)&al,  g_al);
    cudaGetSymbolAddress((void**)&wqh, g_wqh);
    cudaGetSymbolAddress((void**)&wql, g_wql);
    cudaGetSymbolAddress((void**)&wkh, g_wkh);
    cudaGetSymbolAddress((void**)&wkl, g_wkl);
    cudaGetSymbolAddress((void**)&wvh, g_wvh);
    cudaGetSymbolAddress((void**)&wvl, g_wvl);
    cudaGetSymbolAddress((void**)&woh, g_woh);
    cudaGetSymbolAddress((void**)&wol, g_wol);

    const int gemm_smem = 2 * 32768;   // 64 KB
    cudaFuncSetAttribute(gemm_mma, cudaFuncAttributeMaxDynamicSharedMemorySize, gemm_smem);

    // 1) split hidden states; transpose+split weights
    {
        int n4 = MROWS * DM / 4;
        split_kernel<<<(n4 + 255) / 256, 256>>>(hs, ah, al, n4);
        dim3 tb(32, 8);
        transpose_split<<<dim3(DM / 32,  DM / 32), tb>>>(Wq, wqh, wql, DM, DM);
        transpose_split<<<dim3(512 / 32, DM / 32), tb>>>(Wk, wkh, wkl, DM, 512);
        transpose_split<<<dim3(512 / 32, DM / 32), tb>>>(Wv, wvh, wvl, DM, 512);
        transpose_split<<<dim3(DM / 32,  DM / 32), tb>>>(Wo, woh, wol, DM, DM);
    }

    // 2) Q/K/V projections on tensor cores (head-layout epilogue)
    gemm_mma<<<dim3(DM / 128,  MROWS / 128), 256, gemm_smem>>>(ah, al, wqh, wql, q, DM,  1, nullptr, NH);
    gemm_mma<<<dim3(512 / 128, MROWS / 128), 256, gemm_smem>>>(ah, al, wkh, wkl, k, 512, 1, nullptr, NG);
    gemm_mma<<<dim3(512 / 128, MROWS / 128), 256, gemm_smem>>>(ah, al, wvh, wvl, v, 512, 1, nullptr, NG);

    // 3) RoPE
    {
        int np_q = BATCH * NH * SEQ * 32;
        int np_k = BATCH * NG * SEQ * 32;
        rope_kernel<<<(np_q + 255) / 256, 256>>>(q, np_q);
        rope_kernel<<<(np_k + 255) / 256, 256>>>(k, np_k);
    }

    // 4) attention
    {
        const int smem = (64 * 64 + 64 * 65 + 64 * 64) * (int)sizeof(float);
        cudaFuncSetAttribute(attn64, cudaFuncAttributeMaxDynamicSharedMemorySize, smem);
        attn64<<<dim3(SEQ / 64, NH, BATCH), 256, smem>>>(q, k, v, ctx);
    }

    // 5) split ctx (reuse A buffers), output projection + bias
    {
        int n4 = MROWS * DM / 4;
        split_kernel<<<(n4 + 255) / 256, 256>>>(ctx, ah, al, n4);
        gemm_mma<<<dim3(DM / 128, MROWS / 128), 256, gemm_smem>>>(ah, al, woh, wol, out, DM, 0, bo, 0);
    }
}

// round 4
// speedup vs baseline: 2.7868x; 1.4527x over previous
#include <cuda_runtime.h>
#include <cuda_bf16.h>
#include <math.h>
#include <stdint.h>

#define DM    2048
#define SEQ   2048
#define BATCH 2
#define NH    32
#define NG    8
#define DH    64
#define MROWS (BATCH*SEQ)   // 4096

// ---------------- scratch (__device__ globals; no allocs allowed) ----------
__device__ __nv_bfloat16 g_ah[(size_t)MROWS*DM];   // A split (hs, later ctx)
__device__ __nv_bfloat16 g_al[(size_t)MROWS*DM];
__device__ __nv_bfloat16 g_wqh[(size_t)DM*DM],  g_wql[(size_t)DM*DM];
__device__ __nv_bfloat16 g_wkh[(size_t)512*DM], g_wkl[(size_t)512*DM];
__device__ __nv_bfloat16 g_wvh[(size_t)512*DM], g_wvl[(size_t)512*DM];
__device__ __nv_bfloat16 g_woh[(size_t)DM*DM],  g_wol[(size_t)DM*DM];
__device__ __nv_bfloat16 g_qh[(size_t)BATCH*NH*SEQ*DH], g_ql[(size_t)BATCH*NH*SEQ*DH];
__device__ __nv_bfloat16 g_kh[(size_t)BATCH*NG*SEQ*DH], g_kl[(size_t)BATCH*NG*SEQ*DH];
__device__ __nv_bfloat16 g_vh[(size_t)BATCH*NG*SEQ*DH], g_vl[(size_t)BATCH*NG*SEQ*DH];
__device__ float2 g_rope[SEQ * 32];

// ---------------- helpers ---------------------------------------------------
__device__ __forceinline__ uint32_t smem_u32(const void* p) {
    uint32_t a;
    asm("{ .reg .u64 t; cvta.to.shared.u64 t, %1; cvt.u32.u64 %0, t; }" : "=r"(a) : "l"(p));
    return a;
}
__device__ __forceinline__ void ldsm4(uint32_t* r, uint32_t addr) {
    asm volatile("ldmatrix.sync.aligned.m8n8.x4.shared.b16 {%0,%1,%2,%3}, [%4];"
                 : "=r"(r[0]), "=r"(r[1]), "=r"(r[2]), "=r"(r[3]) : "r"(addr));
}
__device__ __forceinline__ void ldsm4t(uint32_t* r, uint32_t addr) {
    asm volatile("ldmatrix.sync.aligned.m8n8.x4.trans.shared.b16 {%0,%1,%2,%3}, [%4];"
                 : "=r"(r[0]), "=r"(r[1]), "=r"(r[2]), "=r"(r[3]) : "r"(addr));
}
__device__ __forceinline__ void mma16816(float* c, const uint32_t* a, const uint32_t* b) {
    asm volatile("mma.sync.aligned.m16n8k16.row.col.f32.bf16.bf16.f32 "
                 "{%0,%1,%2,%3}, {%4,%5,%6,%7}, {%8,%9}, {%0,%1,%2,%3};"
                 : "+f"(c[0]), "+f"(c[1]), "+f"(c[2]), "+f"(c[3])
                 : "r"(a[0]), "r"(a[1]), "r"(a[2]), "r"(a[3]), "r"(b[0]), "r"(b[1]));
}
#define CP_ASYNC16(s, g) \
    asm volatile("cp.async.cg.shared.global [%0], [%1], 16;" :: "r"(s), "l"(g))
#define CP_COMMIT() asm volatile("cp.async.commit_group;" ::: "memory")
#define CP_WAIT1()  asm volatile("cp.async.wait_group 1;" ::: "memory")

__device__ __forceinline__ uint32_t packbf(float lo, float hi) {
    __nv_bfloat162 t = __floats2bfloat162_rn(lo, hi);
    return *reinterpret_cast<uint32_t*>(&t);
}

// ---------------------------------------------------------------------------
// bf16x3 HMMA GEMM: C[M,Ntot] = A @ B^T.  128x128 CTA tile, BK=32, 256 thr.
// mode 0: fp32 row-major + bias -> Cf.
// mode 1: rope + bf16 hi/lo split -> Oh/Ol in [b][head][s][64] layout.
// mode 2: bf16 hi/lo split (no rope) -> same layout.
// ---------------------------------------------------------------------------
__global__ __launch_bounds__(256, 1)
void gemm_mma(const __nv_bfloat16* __restrict__ Ah, const __nv_bfloat16* __restrict__ Al,
              const __nv_bfloat16* __restrict__ Bh, const __nv_bfloat16* __restrict__ Bl,
              float* __restrict__ Cf,
              __nv_bfloat16* __restrict__ Oh, __nv_bfloat16* __restrict__ Ol,
              const float2* __restrict__ rope,
              int Ntot, int mode, const float* __restrict__ bias, int heads)
{
    extern __shared__ __align__(128) char smc[];
    const uint32_t sbase = smem_u32(smc);
    const int tid = threadIdx.x, lane = tid & 31, wid = tid >> 5;
    const int wm = wid >> 2, wn = wid & 3;
    const int n0 = blockIdx.x << 7, m0 = blockIdx.y << 7;

    const int fr = tid >> 2;
    const int fc = tid & 3;

    uint32_t offA[4][2], offB[2][2];
#pragma unroll
    for (int mf = 0; mf < 4; mf++)
#pragma unroll
        for (int ks = 0; ks < 2; ks++) {
            int row = wm * 64 + mf * 16 + (lane & 7) + ((lane >> 3) & 1) * 8;
            int ch  = ks * 2 + (lane >> 4);
            offA[mf][ks] = row * 64 + ((ch ^ ((row >> 1) & 3)) << 4);
        }
#pragma unroll
    for (int np = 0; np < 2; np++)
#pragma unroll
        for (int ks = 0; ks < 2; ks++) {
            int row = wn * 32 + np * 16 + (lane & 7) + (lane >> 4) * 8;
            int ch  = ks * 2 + ((lane >> 3) & 1);
            offB[np][ks] = row * 64 + ((ch ^ ((row >> 1) & 3)) << 4);
        }

    float acc[4][4][4];
#pragma unroll
    for (int i = 0; i < 4; i++)
#pragma unroll
        for (int j = 0; j < 4; j++)
#pragma unroll
            for (int l = 0; l < 4; l++) acc[i][j][l] = 0.f;

    auto fill = [&](int kc, int stage) {
        const uint32_t sb = sbase + stage * 32768;
#pragma unroll
        for (int i = 0; i < 2; i++) {
            const int r = fr + i * 64;
            const uint32_t so = r * 64 + ((fc ^ ((r >> 1) & 3)) << 4);
            const size_t gA = (size_t)(m0 + r) * DM + kc * 32 + fc * 8;
            const size_t gB = (size_t)(n0 + r) * DM + kc * 32 + fc * 8;
            CP_ASYNC16(sb +         so, Ah + gA);
            CP_ASYNC16(sb +  8192 + so, Al + gA);
            CP_ASYNC16(sb + 16384 + so, Bh + gB);
            CP_ASYNC16(sb + 24576 + so, Bl + gB);
        }
        CP_COMMIT();
    };

    fill(0, 0);
    fill(1, 1);

    const int NKC = DM / 32;
    for (int kc = 0; kc < NKC; kc++) {
        CP_WAIT1();
        __syncthreads();
        const uint32_t sA = sbase + (kc & 1) * 32768;
#pragma unroll
        for (int ks = 0; ks < 2; ks++) {
            uint32_t ah[4][4], al[4][4], bh[2][4], bl[2][4];
#pragma unroll
            for (int mf = 0; mf < 4; mf++) {
                ldsm4(ah[mf], sA +        offA[mf][ks]);
                ldsm4(al[mf], sA + 8192 + offA[mf][ks]);
            }
#pragma unroll
            for (int np = 0; np < 2; np++) {
                ldsm4(bh[np], sA + 16384 + offB[np][ks]);
                ldsm4(bl[np], sA + 24576 + offB[np][ks]);
            }
#pragma unroll
            for (int mf = 0; mf < 4; mf++)
#pragma unroll
                for (int nf = 0; nf < 4; nf++) {
                    const uint32_t* bhp = &bh[nf >> 1][(nf & 1) * 2];
                    const uint32_t* blp = &bl[nf >> 1][(nf & 1) * 2];
                    mma16816(acc[mf][nf], ah[mf], bhp);
                    mma16816(acc[mf][nf], ah[mf], blp);
                    mma16816(acc[mf][nf], al[mf], bhp);
                }
        }
        __syncthreads();
        if (kc + 2 < NKC) fill(kc + 2, kc & 1);
        else CP_COMMIT();
    }

    const int g4 = lane >> 2, t4 = lane & 3;
#pragma unroll
    for (int mf = 0; mf < 4; mf++) {
#pragma unroll
        for (int nf = 0; nf < 4; nf++) {
            const int row = m0 + wm * 64 + mf * 16 + g4;
            const int col = n0 + wn * 32 + nf * 8 + t4 * 2;
            float2 v0 = make_float2(acc[mf][nf][0], acc[mf][nf][1]);
            float2 v1 = make_float2(acc[mf][nf][2], acc[mf][nf][3]);
            if (mode == 0) {
                const float b0 = bias[col], b1 = bias[col + 1];
                v0.x += b0; v0.y += b1; v1.x += b0; v1.y += b1;
                *reinterpret_cast<float2*>(Cf + (size_t)row * Ntot + col)       = v0;
                *reinterpret_cast<float2*>(Cf + (size_t)(row + 8) * Ntot + col) = v1;
            } else {
                const int hh = col >> 6, d = col & 63, pair = d >> 1;
                float2 vv[2] = {v0, v1};
#pragma unroll
                for (int t = 0; t < 2; t++) {
                    const int r = row + t * 8;
                    const int bb = r >> 11, s = r & (SEQ - 1);
                    float x0 = vv[t].x, x1 = vv[t].y;
                    if (mode == 1) {
                        float2 cs = rope[s * 32 + pair];
                        float r0 = x0 * cs.x - x1 * cs.y;
                        x1 = x1 * cs.x + x0 * cs.y;
                        x0 = r0;
                    }
                    __nv_bfloat16 h0 = __float2bfloat16_rn(x0);
                    __nv_bfloat16 h1 = __float2bfloat16_rn(x1);
                    float l0f = x0 - __bfloat162float(h0);
                    float l1f = x1 - __bfloat162float(h1);
                    size_t o32 = ((size_t)(bb * heads + hh) * SEQ + s) * 32 + pair;
                    reinterpret_cast<uint32_t*>(Oh)[o32] =
                        packbf(__bfloat162float(h0), __bfloat162float(h1));
                    reinterpret_cast<uint32_t*>(Ol)[o32] = packbf(l0f, l1f);
                }
            }
        }
    }
}

// ---------------------------------------------------------------------------
// fp32 -> bf16 hi/lo split (hidden states)
// ---------------------------------------------------------------------------
__global__ void split_kernel(const float* __restrict__ x,
                             __nv_bfloat16* __restrict__ hi,
                             __nv_bfloat16* __restrict__ lo, int n4)
{
    int i = blockIdx.x * blockDim.x + threadIdx.x;
    if (i >= n4) return;
    float4 v = reinterpret_cast<const float4*>(x)[i];
    float f[4] = {v.x, v.y, v.z, v.w};
    __nv_bfloat16 h[4], l[4];
#pragma unroll
    for (int j = 0; j < 4; j++) {
        h[j] = __float2bfloat16_rn(f[j]);
        l[j] = __float2bfloat16_rn(f[j] - __bfloat162float(h[j]));
    }
    reinterpret_cast<uint2*>(hi)[i] = *reinterpret_cast<uint2*>(h);
    reinterpret_cast<uint2*>(lo)[i] = *reinterpret_cast<uint2*>(l);
}

// ---------------------------------------------------------------------------
// W [K,N] fp32 -> Wt hi/lo [N,K] bf16
// ---------------------------------------------------------------------------
__global__ void transpose_split(const float* __restrict__ W,
                                __nv_bfloat16* __restrict__ Th,
                                __nv_bfloat16* __restrict__ Tl, int K, int N)
{
    __shared__ float t[32][33];
    const int n0 = blockIdx.x * 32, k0 = blockIdx.y * 32;
    const int tx = threadIdx.x, ty = threadIdx.y;
#pragma unroll
    for (int i = 0; i < 4; i++)
        t[ty + 8 * i][tx] = W[(size_t)(k0 + ty + 8 * i) * N + n0 + tx];
    __syncthreads();
#pragma unroll
    for (int i = 0; i < 4; i++) {
        float v = t[tx][ty + 8 * i];
        __nv_bfloat16 h = __float2bfloat16_rn(v);
        __nv_bfloat16 l = __float2bfloat16_rn(v - __bfloat162float(h));
        size_t o = (size_t)(n0 + ty + 8 * i) * K + k0 + tx;
        Th[o] = h; Tl[o] = l;
    }
}

// ---------------------------------------------------------------------------
// RoPE cos/sin table: g_rope[s][pair] = (cos, sin)
// ---------------------------------------------------------------------------
__global__ void rope_table(float2* __restrict__ tb)
{
    int idx = blockIdx.x * blockDim.x + threadIdx.x;
    if (idx >= SEQ * 32) return;
    int s = idx >> 5, pair = idx & 31;
    float inv = powf(10000.f, -(float)(2 * pair) * (1.f / 64.f));
    float sn, c;
    sincosf((float)s * inv, &sn, &c);
    tb[idx] = make_float2(c, sn);
}

// ---------------------------------------------------------------------------
// MMA flash attention, fixed-max softmax.
// CTA = (q-tile 128, h, b). 256 threads, 8 warps, warp = 16 q-rows.
// K/V tiles 128x64 bf16 hi/lo, cp.async double buffered.
// Writes ctx as split bf16 into Ch/Cl with [row=(b,s)][col=h*64+d] layout.
// ---------------------------------------------------------------------------
__global__ __launch_bounds__(256, 1)
void attn_mma(const __nv_bfloat16* __restrict__ Qh, const __nv_bfloat16* __restrict__ Ql,
              const __nv_bfloat16* __restrict__ Kh, const __nv_bfloat16* __restrict__ Kl,
              const __nv_bfloat16* __restrict__ Vh, const __nv_bfloat16* __restrict__ Vl,
              __nv_bfloat16* __restrict__ Ch, __nv_bfloat16* __restrict__ Cl)
{
    extern __shared__ __align__(128) char smc[];
    const uint32_t sb = smem_u32(smc);
    const int tid = threadIdx.x, lane = tid & 31, wid = tid >> 5;
    const int qt = (SEQ / 128 - 1) - blockIdx.x;   // longest tiles first
    const int h = blockIdx.y, b = blockIdx.z;
    const int g = h >> 2;
    const int q0 = qt << 7;
    const int wrow = wid * 16;

    const size_t qbase = ((size_t)(b * NH + h) * SEQ + q0) * DH;
    const size_t kbase = ((size_t)(b * NG + g) * SEQ) * DH;

    constexpr uint32_t SQH = 0, SQL = 16384, SST = 32768;

    // fill Q (group 0)
    {
#pragma unroll
        for (int i = 0; i < 4; i++) {
            int idx = tid + (i << 8);
            int r = idx >> 3, ch = idx & 7;
            uint32_t so = r * 128 + ((ch ^ (r & 7)) << 4);
            CP_ASYNC16(sb + SQH + so, Qh + qbase + r * 64 + ch * 8);
            CP_ASYNC16(sb + SQL + so, Ql + qbase + r * 64 + ch * 8);
        }
        CP_COMMIT();
    }
    auto fillkv = [&](int kt, int st) {
        const uint32_t s0 = sb + SST + st * 65536;
        const size_t kb = kbase + (size_t)kt * 128 * 64;
#pragma unroll
        for (int i = 0; i < 4; i++) {
            int idx = tid + (i << 8);
            int r = idx >> 3, ch = idx & 7;
            uint32_t so = r * 128 + ((ch ^ (r & 7)) << 4);
            size_t go = kb + r * 64 + ch * 8;
            CP_ASYNC16(s0 +         so, Kh + go);
            CP_ASYNC16(s0 + 16384 + so, Kl + go);
            CP_ASYNC16(s0 + 32768 + so, Vh + go);
            CP_ASYNC16(s0 + 49152 + so, Vl + go);
        }
        CP_COMMIT();
    };
    fillkv(0, 0);
    if (qt >= 1) fillkv(1, 1); else CP_COMMIT();

    CP_WAIT1();
    __syncthreads();

    // Q fragments held in registers for the whole kernel
    uint32_t qhf[4][4], qlf[4][4];
    {
        const int row = wrow + (lane & 7) + ((lane >> 3) & 1) * 8;
        const int chb = lane >> 4;
#pragma unroll
        for (int ks = 0; ks < 4; ks++) {
            uint32_t so = row * 128 + (((ks * 2 + chb) ^ (row & 7)) << 4);
            ldsm4(qhf[ks], sb + SQH + so);
            ldsm4(qlf[ks], sb + SQL + so);
        }
    }

    float oac[8][4];
#pragma unroll
    for (int i = 0; i < 8; i++)
#pragma unroll
        for (int j = 0; j < 4; j++) oac[i][j] = 0.f;
    float ls0 = 0.f, ls1 = 0.f;
    const float slope8 = exp2f(-(float)(h + 1) * 0.25f) * 0.125f;
    const int qr = q0 + wrow + (lane >> 2);   // seq pos of c0/c1 row

    const int klrow = (lane & 7) + ((lane >> 4) << 3);
    const int klchb = (lane >> 3) & 1;
    const int vlrow = (lane & 7) + (((lane >> 3) & 1) << 3);
    const int vlchb = lane >> 4;

    for (int kt = 0; kt <= qt; kt++) {
        const int st = kt & 1;
        const uint32_t sK = sb + SST + st * 65536;
        CP_WAIT1();
        __syncthreads();
        const bool diag = (kt == qt);
        const int kcol00 = kt * 128 + (lane & 3) * 2;

#pragma unroll
        for (int hf = 0; hf < 2; hf++) {
            float sc[8][4];
#pragma unroll
            for (int i = 0; i < 8; i++)
#pragma unroll
                for (int j = 0; j < 4; j++) sc[i][j] = 0.f;

            // S = Q @ K^T (bf16x3)
#pragma unroll
            for (int ks = 0; ks < 4; ks++) {
#pragma unroll
                for (int ng = 0; ng < 4; ng++) {
                    const int row = hf * 64 + ng * 16 + klrow;
                    const uint32_t so = row * 128 + (((ks * 2 + klchb) ^ (row & 7)) << 4);
                    uint32_t kfh[4], kfl[4];
                    ldsm4(kfh, sK + so);
                    ldsm4(kfl, sK + 16384 + so);
                    mma16816(sc[ng * 2],     qhf[ks], kfh);
                    mma16816(sc[ng * 2],     qhf[ks], kfl);
                    mma16816(sc[ng * 2],     qlf[ks], kfh);
                    mma16816(sc[ng * 2 + 1], qhf[ks], kfh + 2);
                    mma16816(sc[ng * 2 + 1], qhf[ks], kfl + 2);
                    mma16816(sc[ng * 2 + 1], qlf[ks], kfh + 2);
                }
            }

            // softmax: alibi+scale, p = exp(30*tanh(s/30) - 30) = exp(-60/(e^{s/15}+1))
#pragma unroll
            for (int nf = 0; nf < 8; nf++) {
                const int kc = kcol00 + hf * 64 + nf * 8;
                const float bias0 = slope8 * (float)(kc - qr);
                float s0 = fmaf(sc[nf][0], 0.125f, bias0);
                float s1 = fmaf(sc[nf][1], 0.125f, bias0 + slope8);
                float s2 = fmaf(sc[nf][2], 0.125f, bias0 - 8.f * slope8);
                float s3 = fmaf(sc[nf][3], 0.125f, bias0 - 7.f * slope8);
                float p0 = __expf(-60.f / (__expf(s0 * (1.f / 15.f)) + 1.f));
                float p1 = __expf(-60.f / (__expf(s1 * (1.f / 15.f)) + 1.f));
                float p2 = __expf(-60.f / (__expf(s2 * (1.f / 15.f)) + 1.f));
                float p3 = __expf(-60.f / (__expf(s3 * (1.f / 15.f)) + 1.f));
                if (diag) {
                    if (kc > qr)         p0 = 0.f;
                    if (kc + 1 > qr)     p1 = 0.f;
                    if (kc > qr + 8)     p2 = 0.f;
                    if (kc + 1 > qr + 8) p3 = 0.f;
                }
                ls0 += p0 + p1;
                ls1 += p2 + p3;
                sc[nf][0] = p0; sc[nf][1] = p1; sc[nf][2] = p2; sc[nf][3] = p3;
            }

            // O += P @ V (bf16x3, P in registers)
#pragma unroll
            for (int j = 0; j < 4; j++) {
                uint32_t pah[4], pal[4];
#pragma unroll
                for (int u = 0; u < 2; u++) {
                    const float* p = sc[2 * j + u];
                    __nv_bfloat16 h0 = __float2bfloat16_rn(p[0]);
                    __nv_bfloat16 h1 = __float2bfloat16_rn(p[1]);
                    __nv_bfloat16 h2 = __float2bfloat16_rn(p[2]);
                    __nv_bfloat16 h3 = __float2bfloat16_rn(p[3]);
                    pah[2 * u]     = packbf(__bfloat162float(h0), __bfloat162float(h1));
                    pah[2 * u + 1] = packbf(__bfloat162float(h2), __bfloat162float(h3));
                    pal[2 * u]     = packbf(p[0] - __bfloat162float(h0), p[1] - __bfloat162float(h1));
                    pal[2 * u + 1] = packbf(p[2] - __bfloat162float(h2), p[3] - __bfloat162float(h3));
                }
                // reorder: a-frag = {c01(nf=2j), c23(nf=2j), c01(nf=2j+1), c23(nf=2j+1)}
                // pah currently = {c01(2j), c23(2j), c01(2j+1), c23(2j+1)} -- already correct.
#pragma unroll
                for (int gD = 0; gD < 4; gD++) {
                    const int row = hf * 64 + j * 16 + vlrow;
                    const uint32_t so = row * 128 + (((gD * 2 + vlchb) ^ (row & 7)) << 4);
                    uint32_t vfh[4], vfl[4];
                    ldsm4t(vfh, sK + 32768 + so);
                    ldsm4t(vfl, sK + 49152 + so);
                    mma16816(oac[gD * 2],     pah, vfh);
                    mma16816(oac[gD * 2],     pah, vfl);
                    mma16816(oac[gD * 2],     pal, vfh);
                    mma16816(oac[gD * 2 + 1], pah, vfh + 2);
                    mma16816(oac[gD * 2 + 1], pah, vfl + 2);
                    mma16816(oac[gD * 2 + 1], pal, vfh + 2);
                }
            }
        }
        __syncthreads();
        if (kt + 2 <= qt) fillkv(kt + 2, st); else CP_COMMIT();
    }

    // row-sum reduction across the 4 lanes sharing each row
    ls0 += __shfl_xor_sync(0xffffffffu, ls0, 1);
    ls0 += __shfl_xor_sync(0xffffffffu, ls0, 2);
    ls1 += __shfl_xor_sync(0xffffffffu, ls1, 1);
    ls1 += __shfl_xor_sync(0xffffffffu, ls1, 2);
    const float inv0 = 1.f / ls0, inv1 = 1.f / ls1;

    const size_t rowM0 = (size_t)b * SEQ + qr;
#pragma unroll
    for (int nf = 0; nf < 8; nf++) {
        const int col = h * 64 + nf * 8 + (lane & 3) * 2;
        float x0 = oac[nf][0] * inv0, x1 = oac[nf][1] * inv0;
        float y0 = oac[nf][2] * inv1, y1 = oac[nf][3] * inv1;
        __nv_bfloat16 hx0 = __float2bfloat16_rn(x0), hx1 = __float2bfloat16_rn(x1);
        __nv_bfloat16 hy0 = __float2bfloat16_rn(y0), hy1 = __float2bfloat16_rn(y1);
        size_t o0 = (rowM0 * DM + col) >> 1;
        size_t o1 = ((rowM0 + 8) * DM + col) >> 1;
        reinterpret_cast<uint32_t*>(Ch)[o0] = packbf(__bfloat162float(hx0), __bfloat162float(hx1));
        reinterpret_cast<uint32_t*>(Cl)[o0] = packbf(x0 - __bfloat162float(hx0), x1 - __bfloat162float(hx1));
        reinterpret_cast<uint32_t*>(Ch)[o1] = packbf(__bfloat162float(hy0), __bfloat162float(hy1));
        reinterpret_cast<uint32_t*>(Cl)[o1] = packbf(y0 - __bfloat162float(hy0), y1 - __bfloat162float(hy1));
    }
}

// ---------------------------------------------------------------------------
extern "C" void kernel_launch(void* const* d_in, const int* in_sizes, int n_in,
                              void* d_out, int out_size)
{
    const float* hs = (const float*)d_in[0];
    const float* Wq = (const float*)d_in[1];
    const float* Wk = (const float*)d_in[2];
    const float* Wv = (const float*)d_in[3];
    const float* Wo = (const float*)d_in[4];
    const float* bo = (const float*)d_in[5];
    float* out = (float*)d_out;

    __nv_bfloat16 *ah, *al, *wqh, *wql, *wkh, *wkl, *wvh, *wvl, *woh, *wol;
    __nv_bfloat16 *qh, *ql, *kh, *kl, *vh, *vl;
    float2* rope;
    cudaGetSymbolAddress((void**)&ah,  g_ah);
    cudaGetSymbolAddress((void**)&al,  g_al);
    cudaGetSymbolAddress((void**)&wqh, g_wqh);
    cudaGetSymbolAddress((void**)&wql, g_wql);
    cudaGetSymbolAddress((void**)&wkh, g_wkh);
    cudaGetSymbolAddress((void**)&wkl, g_wkl);
    cudaGetSymbolAddress((void**)&wvh, g_wvh);
    cudaGetSymbolAddress((void**)&wvl, g_wvl);
    cudaGetSymbolAddress((void**)&woh, g_woh);
    cudaGetSymbolAddress((void**)&wol, g_wol);
    cudaGetSymbolAddress((void**)&qh,  g_qh);
    cudaGetSymbolAddress((void**)&ql,  g_ql);
    cudaGetSymbolAddress((void**)&kh,  g_kh);
    cudaGetSymbolAddress((void**)&kl,  g_kl);
    cudaGetSymbolAddress((void**)&vh,  g_vh);
    cudaGetSymbolAddress((void**)&vl,  g_vl);
    cudaGetSymbolAddress((void**)&rope, g_rope);

    const int gemm_smem = 2 * 32768;
    cudaFuncSetAttribute(gemm_mma, cudaFuncAttributeMaxDynamicSharedMemorySize, gemm_smem);
    const int attn_smem = 32768 + 2 * 65536;   // 163840
    cudaFuncSetAttribute(attn_mma, cudaFuncAttributeMaxDynamicSharedMemorySize, attn_smem);

    // 1) prep: split hs, transpose+split weights, rope table
    {
        int n4 = MROWS * DM / 4;
        split_kernel<<<(n4 + 255) / 256, 256>>>(hs, ah, al, n4);
        dim3 tb(32, 8);
        transpose_split<<<dim3(DM / 32,  DM / 32), tb>>>(Wq, wqh, wql, DM, DM);
        transpose_split<<<dim3(512 / 32, DM / 32), tb>>>(Wk, wkh, wkl, DM, 512);
        transpose_split<<<dim3(512 / 32, DM / 32), tb>>>(Wv, wvh, wvl, DM, 512);
        transpose_split<<<dim3(DM / 32,  DM / 32), tb>>>(Wo, woh, wol, DM, DM);
        rope_table<<<(SEQ * 32 + 255) / 256, 256>>>(rope);
    }

    // 2) projections: rope+split epilogue for q/k, split for v
    gemm_mma<<<dim3(DM / 128,  MROWS / 128), 256, gemm_smem>>>(
        ah, al, wqh, wql, nullptr, qh, ql, rope, DM,  1, nullptr, NH);
    gemm_mma<<<dim3(512 / 128, MROWS / 128), 256, gemm_smem>>>(
        ah, al, wkh, wkl, nullptr, kh, kl, rope, 512, 1, nullptr, NG);
    gemm_mma<<<dim3(512 / 128, MROWS / 128), 256, gemm_smem>>>(
        ah, al, wvh, wvl, nullptr, vh, vl, rope, 512, 2, nullptr, NG);

    // 3) attention (writes split ctx into ah/al, fully overwriting them)
    attn_mma<<<dim3(SEQ / 128, NH, BATCH), 256, attn_smem>>>(
        qh, ql, kh, kl, vh, vl, ah, al);

    // 4) output projection + bias
    gemm_mma<<<dim3(DM / 128, MROWS / 128), 256, gemm_smem>>>(
        ah, al, woh, wol, out, nullptr, nullptr, nullptr, DM, 0, bo, 0);
}

// round 5
// speedup vs baseline: 3.0130x; 1.0811x over previous
#include <cuda_runtime.h>
#include <cuda_bf16.h>
#include <math.h>
#include <stdint.h>

#define DM    2048
#define SEQ   2048
#define BATCH 2
#define NH    32
#define NG    8
#define DH    64
#define MROWS (BATCH*SEQ)   // 4096
#define NQKV  3072          // combined projection width

// ---------------- scratch (__device__ globals; no allocs allowed) ----------
__device__ __nv_bfloat16 g_ah[(size_t)MROWS*DM];   // A split (hs, later ctx)
__device__ __nv_bfloat16 g_al[(size_t)MROWS*DM];
__device__ __nv_bfloat16 g_wch[(size_t)NQKV*DM], g_wcl[(size_t)NQKV*DM];  // Wqkv^T split
__device__ __nv_bfloat16 g_woh[(size_t)DM*DM],   g_wol[(size_t)DM*DM];
__device__ __nv_bfloat16 g_qh[(size_t)BATCH*NH*SEQ*DH], g_ql[(size_t)BATCH*NH*SEQ*DH];
__device__ __nv_bfloat16 g_kh[(size_t)BATCH*NG*SEQ*DH], g_kl[(size_t)BATCH*NG*SEQ*DH];
__device__ __nv_bfloat16 g_vh[(size_t)BATCH*NG*SEQ*DH], g_vl[(size_t)BATCH*NG*SEQ*DH];
__device__ float2 g_rope[SEQ * 32];

// ---------------- helpers ---------------------------------------------------
__device__ __forceinline__ uint32_t smem_u32(const void* p) {
    uint32_t a;
    asm("{ .reg .u64 t; cvta.to.shared.u64 t, %1; cvt.u32.u64 %0, t; }" : "=r"(a) : "l"(p));
    return a;
}
__device__ __forceinline__ void ldsm4(uint32_t* r, uint32_t addr) {
    asm volatile("ldmatrix.sync.aligned.m8n8.x4.shared.b16 {%0,%1,%2,%3}, [%4];"
                 : "=r"(r[0]), "=r"(r[1]), "=r"(r[2]), "=r"(r[3]) : "r"(addr));
}
__device__ __forceinline__ void ldsm4t(uint32_t* r, uint32_t addr) {
    asm volatile("ldmatrix.sync.aligned.m8n8.x4.trans.shared.b16 {%0,%1,%2,%3}, [%4];"
                 : "=r"(r[0]), "=r"(r[1]), "=r"(r[2]), "=r"(r[3]) : "r"(addr));
}
__device__ __forceinline__ void mma16816(float* c, const uint32_t* a, const uint32_t* b) {
    asm volatile("mma.sync.aligned.m16n8k16.row.col.f32.bf16.bf16.f32 "
                 "{%0,%1,%2,%3}, {%4,%5,%6,%7}, {%8,%9}, {%0,%1,%2,%3};"
                 : "+f"(c[0]), "+f"(c[1]), "+f"(c[2]), "+f"(c[3])
                 : "r"(a[0]), "r"(a[1]), "r"(a[2]), "r"(a[3]), "r"(b[0]), "r"(b[1]));
}
#define CP_ASYNC16(s, g) \
    asm volatile("cp.async.cg.shared.global [%0], [%1], 16;" :: "r"(s), "l"(g))
#define CP_COMMIT() asm volatile("cp.async.commit_group;" ::: "memory")
#define CP_WAIT1()  asm volatile("cp.async.wait_group 1;" ::: "memory")

__device__ __forceinline__ uint32_t packbf(float lo, float hi) {
    __nv_bfloat162 t = __floats2bfloat162_rn(lo, hi);
    return *reinterpret_cast<uint32_t*>(&t);
}

// p = exp(30*tanh(s/30) - 30), Pade [5/4] tanh; p=0 for s<-15 (negligible tail)
__device__ __forceinline__ float softmax_p(float sv) {
    const float x2 = sv * sv * (1.f / 900.f);
    const float Nn = fmaf(x2, x2 + 105.f, 945.f);
    const float Dd = fmaf(x2, fmaf(x2, 15.f, 420.f), 945.f);
    const float ex = __fdividef(fmaf(-30.f, Dd, sv * Nn), Dd);
    float p = __expf(ex);
    return (sv < -15.f) ? 0.f : p;
}

// ---------------------------------------------------------------------------
// bf16x3 HMMA GEMM: C[M,Ntot] = A @ B^T.  128x128 CTA tile, BK=32, 256 thr.
// mode 0: fp32 row-major + bias -> Cf.
// mode 3: combined QKV epilogue: col<2048 -> Q(rope), <2560 -> K(rope), else V.
//         outputs split bf16 in [b][head][s][64] layout.
// ---------------------------------------------------------------------------
__global__ __launch_bounds__(256, 1)
void gemm_mma(const __nv_bfloat16* __restrict__ Ah, const __nv_bfloat16* __restrict__ Al,
              const __nv_bfloat16* __restrict__ Bh, const __nv_bfloat16* __restrict__ Bl,
              float* __restrict__ Cf,
              __nv_bfloat16* __restrict__ Qh, __nv_bfloat16* __restrict__ Ql,
              __nv_bfloat16* __restrict__ Kh, __nv_bfloat16* __restrict__ Kl,
              __nv_bfloat16* __restrict__ Vh, __nv_bfloat16* __restrict__ Vl,
              const float2* __restrict__ rope,
              int Ntot, int mode, const float* __restrict__ bias)
{
    extern __shared__ __align__(128) char smc[];
    const uint32_t sbase = smem_u32(smc);
    const int tid = threadIdx.x, lane = tid & 31, wid = tid >> 5;
    const int wm = wid >> 2, wn = wid & 3;
    const int n0 = blockIdx.x << 7, m0 = blockIdx.y << 7;

    const int fr = tid >> 2;
    const int fc = tid & 3;

    uint32_t offA[4][2], offB[2][2];
#pragma unroll
    for (int mf = 0; mf < 4; mf++)
#pragma unroll
        for (int ks = 0; ks < 2; ks++) {
            int row = wm * 64 + mf * 16 + (lane & 7) + ((lane >> 3) & 1) * 8;
            int ch  = ks * 2 + (lane >> 4);
            offA[mf][ks] = row * 64 + ((ch ^ ((row >> 1) & 3)) << 4);
        }
#pragma unroll
    for (int np = 0; np < 2; np++)
#pragma unroll
        for (int ks = 0; ks < 2; ks++) {
            int row = wn * 32 + np * 16 + (lane & 7) + (lane >> 4) * 8;
            int ch  = ks * 2 + ((lane >> 3) & 1);
            offB[np][ks] = row * 64 + ((ch ^ ((row >> 1) & 3)) << 4);
        }

    float acc[4][4][4];
#pragma unroll
    for (int i = 0; i < 4; i++)
#pragma unroll
        for (int j = 0; j < 4; j++)
#pragma unroll
            for (int l = 0; l < 4; l++) acc[i][j][l] = 0.f;

    auto fill = [&](int kc, int stage) {
        const uint32_t sb = sbase + stage * 32768;
#pragma unroll
        for (int i = 0; i < 2; i++) {
            const int r = fr + i * 64;
            const uint32_t so = r * 64 + ((fc ^ ((r >> 1) & 3)) << 4);
            const size_t gA = (size_t)(m0 + r) * DM + kc * 32 + fc * 8;
            const size_t gB = (size_t)(n0 + r) * DM + kc * 32 + fc * 8;
            CP_ASYNC16(sb +         so, Ah + gA);
            CP_ASYNC16(sb +  8192 + so, Al + gA);
            CP_ASYNC16(sb + 16384 + so, Bh + gB);
            CP_ASYNC16(sb + 24576 + so, Bl + gB);
        }
        CP_COMMIT();
    };

    fill(0, 0);
    fill(1, 1);

    const int NKC = DM / 32;
    for (int kc = 0; kc < NKC; kc++) {
        CP_WAIT1();
        __syncthreads();
        const uint32_t sA = sbase + (kc & 1) * 32768;
#pragma unroll
        for (int ks = 0; ks < 2; ks++) {
            uint32_t ah[4][4], al[4][4], bh[2][4], bl[2][4];
#pragma unroll
            for (int mf = 0; mf < 4; mf++) {
                ldsm4(ah[mf], sA +        offA[mf][ks]);
                ldsm4(al[mf], sA + 8192 + offA[mf][ks]);
            }
#pragma unroll
            for (int np = 0; np < 2; np++) {
                ldsm4(bh[np], sA + 16384 + offB[np][ks]);
                ldsm4(bl[np], sA + 24576 + offB[np][ks]);
            }
#pragma unroll
            for (int mf = 0; mf < 4; mf++)
#pragma unroll
                for (int nf = 0; nf < 4; nf++) {
                    const uint32_t* bhp = &bh[nf >> 1][(nf & 1) * 2];
                    const uint32_t* blp = &bl[nf >> 1][(nf & 1) * 2];
                    mma16816(acc[mf][nf], ah[mf], bhp);
                    mma16816(acc[mf][nf], ah[mf], blp);
                    mma16816(acc[mf][nf], al[mf], bhp);
                }
        }
        __syncthreads();
        if (kc + 2 < NKC) fill(kc + 2, kc & 1);
        else CP_COMMIT();
    }

    const int g4 = lane >> 2, t4 = lane & 3;
#pragma unroll
    for (int mf = 0; mf < 4; mf++) {
#pragma unroll
        for (int nf = 0; nf < 4; nf++) {
            const int row = m0 + wm * 64 + mf * 16 + g4;
            const int col = n0 + wn * 32 + nf * 8 + t4 * 2;
            float2 v0 = make_float2(acc[mf][nf][0], acc[mf][nf][1]);
            float2 v1 = make_float2(acc[mf][nf][2], acc[mf][nf][3]);
            if (mode == 0) {
                const float b0 = bias[col], b1 = bias[col + 1];
                v0.x += b0; v0.y += b1; v1.x += b0; v1.y += b1;
                *reinterpret_cast<float2*>(Cf + (size_t)row * Ntot + col)       = v0;
                *reinterpret_cast<float2*>(Cf + (size_t)(row + 8) * Ntot + col) = v1;
            } else {
                // combined QKV epilogue
                __nv_bfloat16 *Oh, *Ol;
                int hh, hcount;
                bool dorope;
                if (col < 2048)      { Oh = Qh; Ol = Ql; hh = col >> 6;          hcount = NH; dorope = true; }
                else if (col < 2560) { Oh = Kh; Ol = Kl; hh = (col - 2048) >> 6; hcount = NG; dorope = true; }
                else                 { Oh = Vh; Ol = Vl; hh = (col - 2560) >> 6; hcount = NG; dorope = false; }
                const int pair = (col & 63) >> 1;
                float2 vv[2] = {v0, v1};
#pragma unroll
                for (int t = 0; t < 2; t++) {
                    const int r = row + t * 8;
                    const int bb = r >> 11, s = r & (SEQ - 1);
                    float x0 = vv[t].x, x1 = vv[t].y;
                    if (dorope) {
                        float2 cs = rope[s * 32 + pair];
                        float r0 = x0 * cs.x - x1 * cs.y;
                        x1 = x1 * cs.x + x0 * cs.y;
                        x0 = r0;
                    }
                    __nv_bfloat16 h0 = __float2bfloat16_rn(x0);
                    __nv_bfloat16 h1 = __float2bfloat16_rn(x1);
                    float l0f = x0 - __bfloat162float(h0);
                    float l1f = x1 - __bfloat162float(h1);
                    size_t o32 = ((size_t)(bb * hcount + hh) * SEQ + s) * 32 + pair;
                    reinterpret_cast<uint32_t*>(Oh)[o32] =
                        packbf(__bfloat162float(h0), __bfloat162float(h1));
                    reinterpret_cast<uint32_t*>(Ol)[o32] = packbf(l0f, l1f);
                }
            }
        }
    }
}

// ---------------------------------------------------------------------------
// fp32 -> bf16 hi/lo split (hidden states)
// ---------------------------------------------------------------------------
__global__ void split_kernel(const float* __restrict__ x,
                             __nv_bfloat16* __restrict__ hi,
                             __nv_bfloat16* __restrict__ lo, int n4)
{
    int i = blockIdx.x * blockDim.x + threadIdx.x;
    if (i >= n4) return;
    float4 v = reinterpret_cast<const float4*>(x)[i];
    float f[4] = {v.x, v.y, v.z, v.w};
    __nv_bfloat16 h[4], l[4];
#pragma unroll
    for (int j = 0; j < 4; j++) {
        h[j] = __float2bfloat16_rn(f[j]);
        l[j] = __float2bfloat16_rn(f[j] - __bfloat162float(h[j]));
    }
    reinterpret_cast<uint2*>(hi)[i] = *reinterpret_cast<uint2*>(h);
    reinterpret_cast<uint2*>(lo)[i] = *reinterpret_cast<uint2*>(l);
}

// ---------------------------------------------------------------------------
// W [K,N] fp32 -> Wt hi/lo [N,K] bf16
// ---------------------------------------------------------------------------
__global__ void transpose_split(const float* __restrict__ W,
                                __nv_bfloat16* __restrict__ Th,
                                __nv_bfloat16* __restrict__ Tl, int K, int N)
{
    __shared__ float t[32][33];
    const int n0 = blockIdx.x * 32, k0 = blockIdx.y * 32;
    const int tx = threadIdx.x, ty = threadIdx.y;
#pragma unroll
    for (int i = 0; i < 4; i++)
        t[ty + 8 * i][tx] = W[(size_t)(k0 + ty + 8 * i) * N + n0 + tx];
    __syncthreads();
#pragma unroll
    for (int i = 0; i < 4; i++) {
        float v = t[tx][ty + 8 * i];
        __nv_bfloat16 h = __float2bfloat16_rn(v);
        __nv_bfloat16 l = __float2bfloat16_rn(v - __bfloat162float(h));
        size_t o = (size_t)(n0 + ty + 8 * i) * K + k0 + tx;
        Th[o] = h; Tl[o] = l;
    }
}

// ---------------------------------------------------------------------------
// RoPE cos/sin table
// ---------------------------------------------------------------------------
__global__ void rope_table(float2* __restrict__ tb)
{
    int idx = blockIdx.x * blockDim.x + threadIdx.x;
    if (idx >= SEQ * 32) return;
    int s = idx >> 5, pair = idx & 31;
    float inv = powf(10000.f, -(float)(2 * pair) * (1.f / 64.f));
    float sn, c;
    sincosf((float)s * inv, &sn, &c);
    tb[idx] = make_float2(c, sn);
}

// ---------------------------------------------------------------------------
// MMA flash attention, fixed-max softmax (Pade tanh, 2 MUFU per element).
// ---------------------------------------------------------------------------
__global__ __launch_bounds__(256, 1)
void attn_mma(const __nv_bfloat16* __restrict__ Qh, const __nv_bfloat16* __restrict__ Ql,
              const __nv_bfloat16* __restrict__ Kh, const __nv_bfloat16* __restrict__ Kl,
              const __nv_bfloat16* __restrict__ Vh, const __nv_bfloat16* __restrict__ Vl,
              __nv_bfloat16* __restrict__ Ch, __nv_bfloat16* __restrict__ Cl)
{
    extern __shared__ __align__(128) char smc[];
    const uint32_t sb = smem_u32(smc);
    const int tid = threadIdx.x, lane = tid & 31, wid = tid >> 5;
    const int qt = (SEQ / 128 - 1) - blockIdx.x;   // longest tiles first
    const int h = blockIdx.y, b = blockIdx.z;
    const int g = h >> 2;
    const int q0 = qt << 7;
    const int wrow = wid * 16;

    const size_t qbase = ((size_t)(b * NH + h) * SEQ + q0) * DH;
    const size_t kbase = ((size_t)(b * NG + g) * SEQ) * DH;

    constexpr uint32_t SQH = 0, SQL = 16384, SST = 32768;

    {
#pragma unroll
        for (int i = 0; i < 4; i++) {
            int idx = tid + (i << 8);
            int r = idx >> 3, ch = idx & 7;
            uint32_t so = r * 128 + ((ch ^ (r & 7)) << 4);
            CP_ASYNC16(sb + SQH + so, Qh + qbase + r * 64 + ch * 8);
            CP_ASYNC16(sb + SQL + so, Ql + qbase + r * 64 + ch * 8);
        }
        CP_COMMIT();
    }
    auto fillkv = [&](int kt, int st) {
        const uint32_t s0 = sb + SST + st * 65536;
        const size_t kb = kbase + (size_t)kt * 128 * 64;
#pragma unroll
        for (int i = 0; i < 4; i++) {
            int idx = tid + (i << 8);
            int r = idx >> 3, ch = idx & 7;
            uint32_t so = r * 128 + ((ch ^ (r & 7)) << 4);
            size_t go = kb + r * 64 + ch * 8;
            CP_ASYNC16(s0 +         so, Kh + go);
            CP_ASYNC16(s0 + 16384 + so, Kl + go);
            CP_ASYNC16(s0 + 32768 + so, Vh + go);
            CP_ASYNC16(s0 + 49152 + so, Vl + go);
        }
        CP_COMMIT();
    };
    fillkv(0, 0);
    if (qt >= 1) fillkv(1, 1); else CP_COMMIT();

    CP_WAIT1();
    __syncthreads();

    uint32_t qhf[4][4], qlf[4][4];
    {
        const int row = wrow + (lane & 7) + ((lane >> 3) & 1) * 8;
        const int chb = lane >> 4;
#pragma unroll
        for (int ks = 0; ks < 4; ks++) {
            uint32_t so = row * 128 + (((ks * 2 + chb) ^ (row & 7)) << 4);
            ldsm4(qhf[ks], sb + SQH + so);
            ldsm4(qlf[ks], sb + SQL + so);
        }
    }

    float oac[8][4];
#pragma unroll
    for (int i = 0; i < 8; i++)
#pragma unroll
        for (int j = 0; j < 4; j++) oac[i][j] = 0.f;
    float ls0 = 0.f, ls1 = 0.f;
    const float slope8 = exp2f(-(float)(h + 1) * 0.25f) * 0.125f;
    const int qr = q0 + wrow + (lane >> 2);

    const int klrow = (lane & 7) + ((lane >> 4) << 3);
    const int klchb = (lane >> 3) & 1;
    const int vlrow = (lane & 7) + (((lane >> 3) & 1) << 3);
    const int vlchb = lane >> 4;

    for (int kt = 0; kt <= qt; kt++) {
        const int st = kt & 1;
        const uint32_t sK = sb + SST + st * 65536;
        CP_WAIT1();
        __syncthreads();
        const bool diag = (kt == qt);
        const int kcol00 = kt * 128 + (lane & 3) * 2;

#pragma unroll
        for (int hf = 0; hf < 2; hf++) {
            float sc[8][4];
#pragma unroll
            for (int i = 0; i < 8; i++)
#pragma unroll
                for (int j = 0; j < 4; j++) sc[i][j] = 0.f;

#pragma unroll
            for (int ks = 0; ks < 4; ks++) {
#pragma unroll
                for (int ng = 0; ng < 4; ng++) {
                    const int row = hf * 64 + ng * 16 + klrow;
                    const uint32_t so = row * 128 + (((ks * 2 + klchb) ^ (row & 7)) << 4);
                    uint32_t kfh[4], kfl[4];
                    ldsm4(kfh, sK + so);
                    ldsm4(kfl, sK + 16384 + so);
                    mma16816(sc[ng * 2],     qhf[ks], kfh);
                    mma16816(sc[ng * 2],     qhf[ks], kfl);
                    mma16816(sc[ng * 2],     qlf[ks], kfh);
                    mma16816(sc[ng * 2 + 1], qhf[ks], kfh + 2);
                    mma16816(sc[ng * 2 + 1], qhf[ks], kfl + 2);
                    mma16816(sc[ng * 2 + 1], qlf[ks], kfh + 2);
                }
            }

#pragma unroll
            for (int nf = 0; nf < 8; nf++) {
                const int kc = kcol00 + hf * 64 + nf * 8;
                const float bias0 = slope8 * (float)(kc - qr);
                float p0 = softmax_p(fmaf(sc[nf][0], 0.125f, bias0));
                float p1 = softmax_p(fmaf(sc[nf][1], 0.125f, bias0 + slope8));
                float p2 = softmax_p(fmaf(sc[nf][2], 0.125f, bias0 - 8.f * slope8));
                float p3 = softmax_p(fmaf(sc[nf][3], 0.125f, bias0 - 7.f * slope8));
                if (diag) {
                    if (kc > qr)         p0 = 0.f;
                    if (kc + 1 > qr)     p1 = 0.f;
                    if (kc > qr + 8)     p2 = 0.f;
                    if (kc + 1 > qr + 8) p3 = 0.f;
                }
                ls0 += p0 + p1;
                ls1 += p2 + p3;
                sc[nf][0] = p0; sc[nf][1] = p1; sc[nf][2] = p2; sc[nf][3] = p3;
            }

#pragma unroll
            for (int j = 0; j < 4; j++) {
                uint32_t pah[4], pal[4];
#pragma unroll
                for (int u = 0; u < 2; u++) {
                    const float* p = sc[2 * j + u];
                    __nv_bfloat16 h0 = __float2bfloat16_rn(p[0]);
                    __nv_bfloat16 h1 = __float2bfloat16_rn(p[1]);
                    __nv_bfloat16 h2 = __float2bfloat16_rn(p[2]);
                    __nv_bfloat16 h3 = __float2bfloat16_rn(p[3]);
                    pah[2 * u]     = packbf(__bfloat162float(h0), __bfloat162float(h1));
                    pah[2 * u + 1] = packbf(__bfloat162float(h2), __bfloat162float(h3));
                    pal[2 * u]     = packbf(p[0] - __bfloat162float(h0), p[1] - __bfloat162float(h1));
                    pal[2 * u + 1] = packbf(p[2] - __bfloat162float(h2), p[3] - __bfloat162float(h3));
                }
#pragma unroll
                for (int gD = 0; gD < 4; gD++) {
                    const int row = hf * 64 + j * 16 + vlrow;
                    const uint32_t so = row * 128 + (((gD * 2 + vlchb) ^ (row & 7)) << 4);
                    uint32_t vfh[4], vfl[4];
                    ldsm4t(vfh, sK + 32768 + so);
                    ldsm4t(vfl, sK + 49152 + so);
                    mma16816(oac[gD * 2],     pah, vfh);
                    mma16816(oac[gD * 2],     pah, vfl);
                    mma16816(oac[gD * 2],     pal, vfh);
                    mma16816(oac[gD * 2 + 1], pah, vfh + 2);
                    mma16816(oac[gD * 2 + 1], pah, vfl + 2);
                    mma16816(oac[gD * 2 + 1], pal, vfh + 2);
                }
            }
        }
        __syncthreads();
        if (kt + 2 <= qt) fillkv(kt + 2, st); else CP_COMMIT();
    }

    ls0 += __shfl_xor_sync(0xffffffffu, ls0, 1);
    ls0 += __shfl_xor_sync(0xffffffffu, ls0, 2);
    ls1 += __shfl_xor_sync(0xffffffffu, ls1, 1);
    ls1 += __shfl_xor_sync(0xffffffffu, ls1, 2);
    const float inv0 = 1.f / ls0, inv1 = 1.f / ls1;

    const size_t rowM0 = (size_t)b * SEQ + qr;
#pragma unroll
    for (int nf = 0; nf < 8; nf++) {
        const int col = h * 64 + nf * 8 + (lane & 3) * 2;
        float x0 = oac[nf][0] * inv0, x1 = oac[nf][1] * inv0;
        float y0 = oac[nf][2] * inv1, y1 = oac[nf][3] * inv1;
        __nv_bfloat16 hx0 = __float2bfloat16_rn(x0), hx1 = __float2bfloat16_rn(x1);
        __nv_bfloat16 hy0 = __float2bfloat16_rn(y0), hy1 = __float2bfloat16_rn(y1);
        size_t o0 = (rowM0 * DM + col) >> 1;
        size_t o1 = ((rowM0 + 8) * DM + col) >> 1;
        reinterpret_cast<uint32_t*>(Ch)[o0] = packbf(__bfloat162float(hx0), __bfloat162float(hx1));
        reinterpret_cast<uint32_t*>(Cl)[o0] = packbf(x0 - __bfloat162float(hx0), x1 - __bfloat162float(hx1));
        reinterpret_cast<uint32_t*>(Ch)[o1] = packbf(__bfloat162float(hy0), __bfloat162float(hy1));
        reinterpret_cast<uint32_t*>(Cl)[o1] = packbf(y0 - __bfloat162float(hy0), y1 - __bfloat162float(hy1));
    }
}

// ---------------------------------------------------------------------------
extern "C" void kernel_launch(void* const* d_in, const int* in_sizes, int n_in,
                              void* d_out, int out_size)
{
    const float* hs = (const float*)d_in[0];
    const float* Wq = (const float*)d_in[1];
    const float* Wk = (const float*)d_in[2];
    const float* Wv = (const float*)d_in[3];
    const float* Wo = (const float*)d_in[4];
    const float* bo = (const float*)d_in[5];
    float* out = (float*)d_out;

    __nv_bfloat16 *ah, *al, *wch, *wcl, *woh, *wol;
    __nv_bfloat16 *qh, *ql, *kh, *kl, *vh, *vl;
    float2* rope;
    cudaGetSymbolAddress((void**)&ah,  g_ah);
    cudaGetSymbolAddress((void**)&al,  g_al);
    cudaGetSymbolAddress((void**)&wch, g_wch);
    cudaGetSymbolAddress((void**)&wcl, g_wcl);
    cudaGetSymbolAddress((void**)&woh, g_woh);
    cudaGetSymbolAddress((void**)&wol, g_wol);
    cudaGetSymbolAddress((void**)&qh,  g_qh);
    cudaGetSymbolAddress((void**)&ql,  g_ql);
    cudaGetSymbolAddress((void**)&kh,  g_kh);
    cudaGetSymbolAddress((void**)&kl,  g_kl);
    cudaGetSymbolAddress((void**)&vh,  g_vh);
    cudaGetSymbolAddress((void**)&vl,  g_vl);
    cudaGetSymbolAddress((void**)&rope, g_rope);

    const int gemm_smem = 2 * 32768;
    cudaFuncSetAttribute(gemm_mma, cudaFuncAttributeMaxDynamicSharedMemorySize, gemm_smem);
    const int attn_smem = 32768 + 2 * 65536;   // 163840
    cudaFuncSetAttribute(attn_mma, cudaFuncAttributeMaxDynamicSharedMemorySize, attn_smem);

    // 1) prep: split hs; transpose+split weights into combined QKV + O; rope table
    {
        int n4 = MROWS * DM / 4;
        split_kernel<<<(n4 + 255) / 256, 256>>>(hs, ah, al, n4);
        dim3 tb(32, 8);
        transpose_split<<<dim3(DM / 32,  DM / 32), tb>>>(Wq, wch,                    wcl,                    DM, DM);
        transpose_split<<<dim3(512 / 32, DM / 32), tb>>>(Wk, wch + (size_t)2048*DM,  wcl + (size_t)2048*DM,  DM, 512);
        transpose_split<<<dim3(512 / 32, DM / 32), tb>>>(Wv, wch + (size_t)2560*DM,  wcl + (size_t)2560*DM,  DM, 512);
        transpose_split<<<dim3(DM / 32,  DM / 32), tb>>>(Wo, woh, wol, DM, DM);
        rope_table<<<(SEQ * 32 + 255) / 256, 256>>>(rope);
    }

    // 2) combined QKV projection (rope + split epilogue)
    gemm_mma<<<dim3(NQKV / 128, MROWS / 128), 256, gemm_smem>>>(
        ah, al, wch, wcl, nullptr, qh, ql, kh, kl, vh, vl, rope, NQKV, 3, nullptr);

    // 3) attention (writes split ctx into ah/al)
    attn_mma<<<dim3(SEQ / 128, NH, BATCH), 256, attn_smem>>>(
        qh, ql, kh, kl, vh, vl, ah, al);

    // 4) output projection + bias
    gemm_mma<<<dim3(DM / 128, MROWS / 128), 256, gemm_smem>>>(
        ah, al, woh, wol, out, nullptr, nullptr, nullptr, nullptr, nullptr, nullptr,
        nullptr, DM, 0, bo);
}

// round 6
// speedup vs baseline: 3.3586x; 1.1147x over previous
#include <cuda_runtime.h>
#include <cuda_bf16.h>
#include <math.h>
#include <stdint.h>

#define DM    2048
#define SEQ   2048
#define BATCH 2
#define NH    32
#define NG    8
#define DH    64
#define MROWS (BATCH*SEQ)   // 4096
#define NQKV  3072          // combined projection width

// ---------------- scratch (__device__ globals; no allocs allowed) ----------
__device__ __nv_bfloat16 g_ah[(size_t)MROWS*DM];   // A split (hs, later ctx)
__device__ __nv_bfloat16 g_al[(size_t)MROWS*DM];
__device__ __nv_bfloat16 g_wch[(size_t)NQKV*DM], g_wcl[(size_t)NQKV*DM];  // Wqkv^T split
__device__ __nv_bfloat16 g_woh[(size_t)DM*DM],   g_wol[(size_t)DM*DM];
__device__ __nv_bfloat16 g_qh[(size_t)BATCH*NH*SEQ*DH], g_ql[(size_t)BATCH*NH*SEQ*DH];
__device__ __nv_bfloat16 g_kh[(size_t)BATCH*NG*SEQ*DH], g_kl[(size_t)BATCH*NG*SEQ*DH];
__device__ __nv_bfloat16 g_vh[(size_t)BATCH*NG*SEQ*DH], g_vl[(size_t)BATCH*NG*SEQ*DH];
__device__ float2 g_rope[SEQ * 32];

// ---------------- helpers ---------------------------------------------------
__device__ __forceinline__ uint32_t smem_u32(const void* p) {
    uint32_t a;
    asm("{ .reg .u64 t; cvta.to.shared.u64 t, %1; cvt.u32.u64 %0, t; }" : "=r"(a) : "l"(p));
    return a;
}
__device__ __forceinline__ void ldsm4(uint32_t* r, uint32_t addr) {
    asm volatile("ldmatrix.sync.aligned.m8n8.x4.shared.b16 {%0,%1,%2,%3}, [%4];"
                 : "=r"(r[0]), "=r"(r[1]), "=r"(r[2]), "=r"(r[3]) : "r"(addr));
}
__device__ __forceinline__ void ldsm4t(uint32_t* r, uint32_t addr) {
    asm volatile("ldmatrix.sync.aligned.m8n8.x4.trans.shared.b16 {%0,%1,%2,%3}, [%4];"
                 : "=r"(r[0]), "=r"(r[1]), "=r"(r[2]), "=r"(r[3]) : "r"(addr));
}
__device__ __forceinline__ void mma16816(float* c, const uint32_t* a, const uint32_t* b) {
    asm volatile("mma.sync.aligned.m16n8k16.row.col.f32.bf16.bf16.f32 "
                 "{%0,%1,%2,%3}, {%4,%5,%6,%7}, {%8,%9}, {%0,%1,%2,%3};"
                 : "+f"(c[0]), "+f"(c[1]), "+f"(c[2]), "+f"(c[3])
                 : "r"(a[0]), "r"(a[1]), "r"(a[2]), "r"(a[3]), "r"(b[0]), "r"(b[1]));
}
#define CP_ASYNC16(s, g) \
    asm volatile("cp.async.cg.shared.global [%0], [%1], 16;" :: "r"(s), "l"(g))
#define CP_COMMIT() asm volatile("cp.async.commit_group;" ::: "memory")
#define CP_WAIT1()  asm volatile("cp.async.wait_group 1;" ::: "memory")

__device__ __forceinline__ uint32_t packbf(float lo, float hi) {
    __nv_bfloat162 t = __floats2bfloat162_rn(lo, hi);
    return *reinterpret_cast<uint32_t*>(&t);
}

// p = exp(30*tanh(s/30) - 30). |s|<=~7 for real scores => |x|<=0.25,
// deg-5 odd Taylor error < 4e-5 in exponent. For large-negative alibi tail the
// x^5 term dominates with the correct sign => p underflows to 0 correctly.
__device__ __forceinline__ float softmax_p(float sv) {
    const float x  = sv * (1.f / 30.f);
    const float x2 = x * x;
    const float t  = x * fmaf(x2, fmaf(x2, 2.f / 15.f, -1.f / 3.f), 1.f);
    return __expf(fmaf(30.f, t, -30.f));
}

// ---------------------------------------------------------------------------
// bf16x3 HMMA GEMM: C[M,Ntot] = A @ B^T.  128x128 CTA tile, BK=32, 256 thr.
// mode 0: fp32 row-major + bias -> Cf.
// mode 3: combined QKV epilogue: col<2048 -> Q(rope), <2560 -> K(rope), else V.
// ---------------------------------------------------------------------------
__global__ __launch_bounds__(256, 1)
void gemm_mma(const __nv_bfloat16* __restrict__ Ah, const __nv_bfloat16* __restrict__ Al,
              const __nv_bfloat16* __restrict__ Bh, const __nv_bfloat16* __restrict__ Bl,
              float* __restrict__ Cf,
              __nv_bfloat16* __restrict__ Qh, __nv_bfloat16* __restrict__ Ql,
              __nv_bfloat16* __restrict__ Kh, __nv_bfloat16* __restrict__ Kl,
              __nv_bfloat16* __restrict__ Vh, __nv_bfloat16* __restrict__ Vl,
              const float2* __restrict__ rope,
              int Ntot, int mode, const float* __restrict__ bias)
{
    extern __shared__ __align__(128) char smc[];
    const uint32_t sbase = smem_u32(smc);
    const int tid = threadIdx.x, lane = tid & 31, wid = tid >> 5;
    const int wm = wid >> 2, wn = wid & 3;
    const int n0 = blockIdx.x << 7, m0 = blockIdx.y << 7;

    const int fr = tid >> 2;
    const int fc = tid & 3;

    uint32_t offA[4][2], offB[2][2];
#pragma unroll
    for (int mf = 0; mf < 4; mf++)
#pragma unroll
        for (int ks = 0; ks < 2; ks++) {
            int row = wm * 64 + mf * 16 + (lane & 7) + ((lane >> 3) & 1) * 8;
            int ch  = ks * 2 + (lane >> 4);
            offA[mf][ks] = row * 64 + ((ch ^ ((row >> 1) & 3)) << 4);
        }
#pragma unroll
    for (int np = 0; np < 2; np++)
#pragma unroll
        for (int ks = 0; ks < 2; ks++) {
            int row = wn * 32 + np * 16 + (lane & 7) + (lane >> 4) * 8;
            int ch  = ks * 2 + ((lane >> 3) & 1);
            offB[np][ks] = row * 64 + ((ch ^ ((row >> 1) & 3)) << 4);
        }

    float acc[4][4][4];
#pragma unroll
    for (int i = 0; i < 4; i++)
#pragma unroll
        for (int j = 0; j < 4; j++)
#pragma unroll
            for (int l = 0; l < 4; l++) acc[i][j][l] = 0.f;

    auto fill = [&](int kc, int stage) {
        const uint32_t sb = sbase + stage * 32768;
#pragma unroll
        for (int i = 0; i < 2; i++) {
            const int r = fr + i * 64;
            const uint32_t so = r * 64 + ((fc ^ ((r >> 1) & 3)) << 4);
            const size_t gA = (size_t)(m0 + r) * DM + kc * 32 + fc * 8;
            const size_t gB = (size_t)(n0 + r) * DM + kc * 32 + fc * 8;
            CP_ASYNC16(sb +         so, Ah + gA);
            CP_ASYNC16(sb +  8192 + so, Al + gA);
            CP_ASYNC16(sb + 16384 + so, Bh + gB);
            CP_ASYNC16(sb + 24576 + so, Bl + gB);
        }
        CP_COMMIT();
    };

    fill(0, 0);
    fill(1, 1);

    const int NKC = DM / 32;
    for (int kc = 0; kc < NKC; kc++) {
        CP_WAIT1();
        __syncthreads();
        const uint32_t sA = sbase + (kc & 1) * 32768;
#pragma unroll
        for (int ks = 0; ks < 2; ks++) {
            uint32_t ah[4][4], al[4][4], bh[2][4], bl[2][4];
#pragma unroll
            for (int mf = 0; mf < 4; mf++) {
                ldsm4(ah[mf], sA +        offA[mf][ks]);
                ldsm4(al[mf], sA + 8192 + offA[mf][ks]);
            }
#pragma unroll
            for (int np = 0; np < 2; np++) {
                ldsm4(bh[np], sA + 16384 + offB[np][ks]);
                ldsm4(bl[np], sA + 24576 + offB[np][ks]);
            }
#pragma unroll
            for (int mf = 0; mf < 4; mf++)
#pragma unroll
                for (int nf = 0; nf < 4; nf++) {
                    const uint32_t* bhp = &bh[nf >> 1][(nf & 1) * 2];
                    const uint32_t* blp = &bl[nf >> 1][(nf & 1) * 2];
                    mma16816(acc[mf][nf], ah[mf], bhp);
                    mma16816(acc[mf][nf], ah[mf], blp);
                    mma16816(acc[mf][nf], al[mf], bhp);
                }
        }
        __syncthreads();
        if (kc + 2 < NKC) fill(kc + 2, kc & 1);
        else CP_COMMIT();
    }

    const int g4 = lane >> 2, t4 = lane & 3;
#pragma unroll
    for (int mf = 0; mf < 4; mf++) {
#pragma unroll
        for (int nf = 0; nf < 4; nf++) {
            const int row = m0 + wm * 64 + mf * 16 + g4;
            const int col = n0 + wn * 32 + nf * 8 + t4 * 2;
            float2 v0 = make_float2(acc[mf][nf][0], acc[mf][nf][1]);
            float2 v1 = make_float2(acc[mf][nf][2], acc[mf][nf][3]);
            if (mode == 0) {
                const float b0 = bias[col], b1 = bias[col + 1];
                v0.x += b0; v0.y += b1; v1.x += b0; v1.y += b1;
                *reinterpret_cast<float2*>(Cf + (size_t)row * Ntot + col)       = v0;
                *reinterpret_cast<float2*>(Cf + (size_t)(row + 8) * Ntot + col) = v1;
            } else {
                __nv_bfloat16 *Oh, *Ol;
                int hh, hcount;
                bool dorope;
                if (col < 2048)      { Oh = Qh; Ol = Ql; hh = col >> 6;          hcount = NH; dorope = true; }
                else if (col < 2560) { Oh = Kh; Ol = Kl; hh = (col - 2048) >> 6; hcount = NG; dorope = true; }
                else                 { Oh = Vh; Ol = Vl; hh = (col - 2560) >> 6; hcount = NG; dorope = false; }
                const int pair = (col & 63) >> 1;
                float2 vv[2] = {v0, v1};
#pragma unroll
                for (int t = 0; t < 2; t++) {
                    const int r = row + t * 8;
                    const int bb = r >> 11, s = r & (SEQ - 1);
                    float x0 = vv[t].x, x1 = vv[t].y;
                    if (dorope) {
                        float2 cs = rope[s * 32 + pair];
                        float r0 = x0 * cs.x - x1 * cs.y;
                        x1 = x1 * cs.x + x0 * cs.y;
                        x0 = r0;
                    }
                    __nv_bfloat16 h0 = __float2bfloat16_rn(x0);
                    __nv_bfloat16 h1 = __float2bfloat16_rn(x1);
                    float l0f = x0 - __bfloat162float(h0);
                    float l1f = x1 - __bfloat162float(h1);
                    size_t o32 = ((size_t)(bb * hcount + hh) * SEQ + s) * 32 + pair;
                    reinterpret_cast<uint32_t*>(Oh)[o32] =
                        packbf(__bfloat162float(h0), __bfloat162float(h1));
                    reinterpret_cast<uint32_t*>(Ol)[o32] = packbf(l0f, l1f);
                }
            }
        }
    }
}

// ---------------------------------------------------------------------------
// fp32 -> bf16 hi/lo split (hidden states)
// ---------------------------------------------------------------------------
__global__ void split_kernel(const float* __restrict__ x,
                             __nv_bfloat16* __restrict__ hi,
                             __nv_bfloat16* __restrict__ lo, int n4)
{
    int i = blockIdx.x * blockDim.x + threadIdx.x;
    if (i >= n4) return;
    float4 v = reinterpret_cast<const float4*>(x)[i];
    float f[4] = {v.x, v.y, v.z, v.w};
    __nv_bfloat16 h[4], l[4];
#pragma unroll
    for (int j = 0; j < 4; j++) {
        h[j] = __float2bfloat16_rn(f[j]);
        l[j] = __float2bfloat16_rn(f[j] - __bfloat162float(h[j]));
    }
    reinterpret_cast<uint2*>(hi)[i] = *reinterpret_cast<uint2*>(h);
    reinterpret_cast<uint2*>(lo)[i] = *reinterpret_cast<uint2*>(l);
}

// ---------------------------------------------------------------------------
// Combined QKV weight transpose+split into the fused [NQKV, DM] buffer.
// ---------------------------------------------------------------------------
__global__ void qkv_transpose(const float* __restrict__ Wq, const float* __restrict__ Wk,
                              const float* __restrict__ Wv,
                              __nv_bfloat16* __restrict__ Th, __nv_bfloat16* __restrict__ Tl)
{
    __shared__ float t[32][33];
    int bx = blockIdx.x;                 // 0..95
    const float* W; int N, rowoff;
    if (bx < 64)      { W = Wq; N = 2048; rowoff = 0; }
    else if (bx < 80) { W = Wk; N = 512;  rowoff = 2048; bx -= 64; }
    else              { W = Wv; N = 512;  rowoff = 2560; bx -= 80; }
    const int n0 = bx * 32, k0 = blockIdx.y * 32;
    const int tx = threadIdx.x, ty = threadIdx.y;
#pragma unroll
    for (int i = 0; i < 4; i++)
        t[ty + 8 * i][tx] = W[(size_t)(k0 + ty + 8 * i) * N + n0 + tx];
    __syncthreads();
#pragma unroll
    for (int i = 0; i < 4; i++) {
        float v = t[tx][ty + 8 * i];
        __nv_bfloat16 h = __float2bfloat16_rn(v);
        __nv_bfloat16 l = __float2bfloat16_rn(v - __bfloat162float(h));
        size_t o = (size_t)(rowoff + n0 + ty + 8 * i) * DM + k0 + tx;
        Th[o] = h; Tl[o] = l;
    }
}

// ---------------------------------------------------------------------------
// W [K,N] fp32 -> Wt hi/lo [N,K] bf16 (for Wo)
// ---------------------------------------------------------------------------
__global__ void transpose_split(const float* __restrict__ W,
                                __nv_bfloat16* __restrict__ Th,
                                __nv_bfloat16* __restrict__ Tl, int K, int N)
{
    __shared__ float t[32][33];
    const int n0 = blockIdx.x * 32, k0 = blockIdx.y * 32;
    const int tx = threadIdx.x, ty = threadIdx.y;
#pragma unroll
    for (int i = 0; i < 4; i++)
        t[ty + 8 * i][tx] = W[(size_t)(k0 + ty + 8 * i) * N + n0 + tx];
    __syncthreads();
#pragma unroll
    for (int i = 0; i < 4; i++) {
        float v = t[tx][ty + 8 * i];
        __nv_bfloat16 h = __float2bfloat16_rn(v);
        __nv_bfloat16 l = __float2bfloat16_rn(v - __bfloat162float(h));
        size_t o = (size_t)(n0 + ty + 8 * i) * K + k0 + tx;
        Th[o] = h; Tl[o] = l;
    }
}

// ---------------------------------------------------------------------------
// RoPE cos/sin table
// ---------------------------------------------------------------------------
__global__ void rope_table(float2* __restrict__ tb)
{
    int idx = blockIdx.x * blockDim.x + threadIdx.x;
    if (idx >= SEQ * 32) return;
    int s = idx >> 5, pair = idx & 31;
    float inv = powf(10000.f, -(float)(2 * pair) * (1.f / 64.f));
    float sn, c;
    sincosf((float)s * inv, &sn, &c);
    tb[idx] = make_float2(c, sn);
}

// ---------------------------------------------------------------------------
// MMA flash attention, fixed-max softmax (poly tanh, 1 MUFU per element).
// 1D grid sorted by descending work (all longest q-tiles first).
// ---------------------------------------------------------------------------
__global__ __launch_bounds__(256, 1)
void attn_mma(const __nv_bfloat16* __restrict__ Qh, const __nv_bfloat16* __restrict__ Ql,
              const __nv_bfloat16* __restrict__ Kh, const __nv_bfloat16* __restrict__ Kl,
              const __nv_bfloat16* __restrict__ Vh, const __nv_bfloat16* __restrict__ Vl,
              __nv_bfloat16* __restrict__ Ch, __nv_bfloat16* __restrict__ Cl)
{
    extern __shared__ __align__(128) char smc[];
    const uint32_t sb = smem_u32(smc);
    const int tid = threadIdx.x, lane = tid & 31, wid = tid >> 5;
    // work-sorted decode: all qt=15 CTAs first, then qt=14, ...
    const int bid = blockIdx.x;
    const int qt  = (SEQ / 128 - 1) - (bid >> 6);
    const int sub = bid & 63;
    const int h = sub >> 1, b = sub & 1;
    const int g = h >> 2;
    const int q0 = qt << 7;
    const int wrow = wid * 16;

    const size_t qbase = ((size_t)(b * NH + h) * SEQ + q0) * DH;
    const size_t kbase = ((size_t)(b * NG + g) * SEQ) * DH;

    constexpr uint32_t SQH = 0, SQL = 16384, SST = 32768;

    {
#pragma unroll
        for (int i = 0; i < 4; i++) {
            int idx = tid + (i << 8);
            int r = idx >> 3, ch = idx & 7;
            uint32_t so = r * 128 + ((ch ^ (r & 7)) << 4);
            CP_ASYNC16(sb + SQH + so, Qh + qbase + r * 64 + ch * 8);
            CP_ASYNC16(sb + SQL + so, Ql + qbase + r * 64 + ch * 8);
        }
        CP_COMMIT();
    }
    auto fillkv = [&](int kt, int st) {
        const uint32_t s0 = sb + SST + st * 65536;
        const size_t kb = kbase + (size_t)kt * 128 * 64;
#pragma unroll
        for (int i = 0; i < 4; i++) {
            int idx = tid + (i << 8);
            int r = idx >> 3, ch = idx & 7;
            uint32_t so = r * 128 + ((ch ^ (r & 7)) << 4);
            size_t go = kb + r * 64 + ch * 8;
            CP_ASYNC16(s0 +         so, Kh + go);
            CP_ASYNC16(s0 + 16384 + so, Kl + go);
            CP_ASYNC16(s0 + 32768 + so, Vh + go);
            CP_ASYNC16(s0 + 49152 + so, Vl + go);
        }
        CP_COMMIT();
    };
    fillkv(0, 0);
    if (qt >= 1) fillkv(1, 1); else CP_COMMIT();

    CP_WAIT1();
    __syncthreads();

    uint32_t qhf[4][4], qlf[4][4];
    {
        const int row = wrow + (lane & 7) + ((lane >> 3) & 1) * 8;
        const int chb = lane >> 4;
#pragma unroll
        for (int ks = 0; ks < 4; ks++) {
            uint32_t so = row * 128 + (((ks * 2 + chb) ^ (row & 7)) << 4);
            ldsm4(qhf[ks], sb + SQH + so);
            ldsm4(qlf[ks], sb + SQL + so);
        }
    }

    float oac[8][4];
#pragma unroll
    for (int i = 0; i < 8; i++)
#pragma unroll
        for (int j = 0; j < 4; j++) oac[i][j] = 0.f;
    float ls0 = 0.f, ls1 = 0.f;
    const float slope8 = exp2f(-(float)(h + 1) * 0.25f) * 0.125f;
    const int qr = q0 + wrow + (lane >> 2);

    const int klrow = (lane & 7) + ((lane >> 4) << 3);
    const int klchb = (lane >> 3) & 1;
    const int vlrow = (lane & 7) + (((lane >> 3) & 1) << 3);
    const int vlchb = lane >> 4;

    for (int kt = 0; kt <= qt; kt++) {
        const int st = kt & 1;
        const uint32_t sK = sb + SST + st * 65536;
        CP_WAIT1();
        __syncthreads();
        const bool diag = (kt == qt);
        const int kcol00 = kt * 128 + (lane & 3) * 2;

#pragma unroll
        for (int hf = 0; hf < 2; hf++) {
            float sc[8][4];
#pragma unroll
            for (int i = 0; i < 8; i++)
#pragma unroll
                for (int j = 0; j < 4; j++) sc[i][j] = 0.f;

#pragma unroll
            for (int ks = 0; ks < 4; ks++) {
#pragma unroll
                for (int ng = 0; ng < 4; ng++) {
                    const int row = hf * 64 + ng * 16 + klrow;
                    const uint32_t so = row * 128 + (((ks * 2 + klchb) ^ (row & 7)) << 4);
                    uint32_t kfh[4], kfl[4];
                    ldsm4(kfh, sK + so);
                    ldsm4(kfl, sK + 16384 + so);
                    mma16816(sc[ng * 2],     qhf[ks], kfh);
                    mma16816(sc[ng * 2],     qhf[ks], kfl);
                    mma16816(sc[ng * 2],     qlf[ks], kfh);
                    mma16816(sc[ng * 2 + 1], qhf[ks], kfh + 2);
                    mma16816(sc[ng * 2 + 1], qhf[ks], kfl + 2);
                    mma16816(sc[ng * 2 + 1], qlf[ks], kfh + 2);
                }
            }

#pragma unroll
            for (int nf = 0; nf < 8; nf++) {
                const int kc = kcol00 + hf * 64 + nf * 8;
                const float bias0 = slope8 * (float)(kc - qr);
                float p0 = softmax_p(fmaf(sc[nf][0], 0.125f, bias0));
                float p1 = softmax_p(fmaf(sc[nf][1], 0.125f, bias0 + slope8));
                float p2 = softmax_p(fmaf(sc[nf][2], 0.125f, bias0 - 8.f * slope8));
                float p3 = softmax_p(fmaf(sc[nf][3], 0.125f, bias0 - 7.f * slope8));
                if (diag) {
                    if (kc > qr)         p0 = 0.f;
                    if (kc + 1 > qr)     p1 = 0.f;
                    if (kc > qr + 8)     p2 = 0.f;
                    if (kc + 1 > qr + 8) p3 = 0.f;
                }
                ls0 += p0 + p1;
                ls1 += p2 + p3;
                sc[nf][0] = p0; sc[nf][1] = p1; sc[nf][2] = p2; sc[nf][3] = p3;
            }

#pragma unroll
            for (int j = 0; j < 4; j++) {
                uint32_t pah[4], pal[4];
#pragma unroll
                for (int u = 0; u < 2; u++) {
                    const float* p = sc[2 * j + u];
                    __nv_bfloat16 h0 = __float2bfloat16_rn(p[0]);
                    __nv_bfloat16 h1 = __float2bfloat16_rn(p[1]);
                    __nv_bfloat16 h2 = __float2bfloat16_rn(p[2]);
                    __nv_bfloat16 h3 = __float2bfloat16_rn(p[3]);
                    pah[2 * u]     = packbf(__bfloat162float(h0), __bfloat162float(h1));
                    pah[2 * u + 1] = packbf(__bfloat162float(h2), __bfloat162float(h3));
                    pal[2 * u]     = packbf(p[0] - __bfloat162float(h0), p[1] - __bfloat162float(h1));
                    pal[2 * u + 1] = packbf(p[2] - __bfloat162float(h2), p[3] - __bfloat162float(h3));
                }
#pragma unroll
                for (int gD = 0; gD < 4; gD++) {
                    const int row = hf * 64 + j * 16 + vlrow;
                    const uint32_t so = row * 128 + (((gD * 2 + vlchb) ^ (row & 7)) << 4);
                    uint32_t vfh[4], vfl[4];
                    ldsm4t(vfh, sK + 32768 + so);
                    ldsm4t(vfl, sK + 49152 + so);
                    mma16816(oac[gD * 2],     pah, vfh);
                    mma16816(oac[gD * 2],     pah, vfl);
                    mma16816(oac[gD * 2],     pal, vfh);
                    mma16816(oac[gD * 2 + 1], pah, vfh + 2);
                    mma16816(oac[gD * 2 + 1], pah, vfl + 2);
                    mma16816(oac[gD * 2 + 1], pal, vfh + 2);
                }
            }
        }
        __syncthreads();
        if (kt + 2 <= qt) fillkv(kt + 2, st); else CP_COMMIT();
    }

    ls0 += __shfl_xor_sync(0xffffffffu, ls0, 1);
    ls0 += __shfl_xor_sync(0xffffffffu, ls0, 2);
    ls1 += __shfl_xor_sync(0xffffffffu, ls1, 1);
    ls1 += __shfl_xor_sync(0xffffffffu, ls1, 2);
    const float inv0 = 1.f / ls0, inv1 = 1.f / ls1;

    const size_t rowM0 = (size_t)b * SEQ + qr;
#pragma unroll
    for (int nf = 0; nf < 8; nf++) {
        const int col = h * 64 + nf * 8 + (lane & 3) * 2;
        float x0 = oac[nf][0] * inv0, x1 = oac[nf][1] * inv0;
        float y0 = oac[nf][2] * inv1, y1 = oac[nf][3] * inv1;
        __nv_bfloat16 hx0 = __float2bfloat16_rn(x0), hx1 = __float2bfloat16_rn(x1);
        __nv_bfloat16 hy0 = __float2bfloat16_rn(y0), hy1 = __float2bfloat16_rn(y1);
        size_t o0 = (rowM0 * DM + col) >> 1;
        size_t o1 = ((rowM0 + 8) * DM + col) >> 1;
        reinterpret_cast<uint32_t*>(Ch)[o0] = packbf(__bfloat162float(hx0), __bfloat162float(hx1));
        reinterpret_cast<uint32_t*>(Cl)[o0] = packbf(x0 - __bfloat162float(hx0), x1 - __bfloat162float(hx1));
        reinterpret_cast<uint32_t*>(Ch)[o1] = packbf(__bfloat162float(hy0), __bfloat162float(hy1));
        reinterpret_cast<uint32_t*>(Cl)[o1] = packbf(y0 - __bfloat162float(hy0), y1 - __bfloat162float(hy1));
    }
}

// ---------------------------------------------------------------------------
extern "C" void kernel_launch(void* const* d_in, const int* in_sizes, int n_in,
                              void* d_out, int out_size)
{
    const float* hs = (const float*)d_in[0];
    const float* Wq = (const float*)d_in[1];
    const float* Wk = (const float*)d_in[2];
    const float* Wv = (const float*)d_in[3];
    const float* Wo = (const float*)d_in[4];
    const float* bo = (const float*)d_in[5];
    float* out = (float*)d_out;

    __nv_bfloat16 *ah, *al, *wch, *wcl, *woh, *wol;
    __nv_bfloat16 *qh, *ql, *kh, *kl, *vh, *vl;
    float2* rope;
    cudaGetSymbolAddress((void**)&ah,  g_ah);
    cudaGetSymbolAddress((void**)&al,  g_al);
    cudaGetSymbolAddress((void**)&wch, g_wch);
    cudaGetSymbolAddress((void**)&wcl, g_wcl);
    cudaGetSymbolAddress((void**)&woh, g_woh);
    cudaGetSymbolAddress((void**)&wol, g_wol);
    cudaGetSymbolAddress((void**)&qh,  g_qh);
    cudaGetSymbolAddress((void**)&ql,  g_ql);
    cudaGetSymbolAddress((void**)&kh,  g_kh);
    cudaGetSymbolAddress((void**)&kl,  g_kl);
    cudaGetSymbolAddress((void**)&vh,  g_vh);
    cudaGetSymbolAddress((void**)&vl,  g_vl);
    cudaGetSymbolAddress((void**)&rope, g_rope);

    const int gemm_smem = 2 * 32768;
    cudaFuncSetAttribute(gemm_mma, cudaFuncAttributeMaxDynamicSharedMemorySize, gemm_smem);
    const int attn_smem = 32768 + 2 * 65536;   // 163840
    cudaFuncSetAttribute(attn_mma, cudaFuncAttributeMaxDynamicSharedMemorySize, attn_smem);

    // launch order fixed so ncu (-s 5 -c 1) profiles attn_mma (index 5)
    // 0) split hs
    {
        int n4 = MROWS * DM / 4;
        split_kernel<<<(n4 + 255) / 256, 256>>>(hs, ah, al, n4);
    }
    // 1) combined QKV weight transpose+split
    {
        dim3 tb(32, 8);
        qkv_transpose<<<dim3(96, 64), tb>>>(Wq, Wk, Wv, wch, wcl);
        // 2) Wo transpose+split
        transpose_split<<<dim3(DM / 32, DM / 32), tb>>>(Wo, woh, wol, DM, DM);
    }
    // 3) rope table
    rope_table<<<(SEQ * 32 + 255) / 256, 256>>>(rope);

    // 4) combined QKV projection (rope + split epilogue)
    gemm_mma<<<dim3(NQKV / 128, MROWS / 128), 256, gemm_smem>>>(
        ah, al, wch, wcl, nullptr, qh, ql, kh, kl, vh, vl, rope, NQKV, 3, nullptr);

    // 5) attention (writes split ctx into ah/al) -- profiled launch
    attn_mma<<<dim3(16 * 64), 256, attn_smem>>>(
        qh, ql, kh, kl, vh, vl, ah, al);

    // 6) output projection + bias
    gemm_mma<<<dim3(DM / 128, MROWS / 128), 256, gemm_smem>>>(
        ah, al, woh, wol, out, nullptr, nullptr, nullptr, nullptr, nullptr, nullptr,
        nullptr, DM, 0, bo);
}

// round 7
// speedup vs baseline: 3.8963x; 1.1601x over previous
#include <cuda_runtime.h>
#include <cuda_bf16.h>
#include <math.h>
#include <stdint.h>

#define DM    2048
#define SEQ   2048
#define BATCH 2
#define NH    32
#define NG    8
#define DH    64
#define MROWS (BATCH*SEQ)   // 4096
#define NQKV  3072          // combined projection width

// ---------------- scratch (__device__ globals; no allocs allowed) ----------
__device__ __nv_bfloat16 g_ah[(size_t)MROWS*DM];   // A split (hs, later ctx)
__device__ __nv_bfloat16 g_al[(size_t)MROWS*DM];
__device__ __nv_bfloat16 g_wch[(size_t)NQKV*DM], g_wcl[(size_t)NQKV*DM];  // Wqkv^T split
__device__ __nv_bfloat16 g_woh[(size_t)DM*DM],   g_wol[(size_t)DM*DM];
__device__ __nv_bfloat16 g_qh[(size_t)BATCH*NH*SEQ*DH], g_ql[(size_t)BATCH*NH*SEQ*DH];
__device__ __nv_bfloat16 g_kh[(size_t)BATCH*NG*SEQ*DH], g_kl[(size_t)BATCH*NG*SEQ*DH];
__device__ __nv_bfloat16 g_vh[(size_t)BATCH*NG*SEQ*DH], g_vl[(size_t)BATCH*NG*SEQ*DH];
__device__ float2 g_rope[SEQ * 32];

// ---------------- helpers ---------------------------------------------------
__device__ __forceinline__ uint32_t smem_u32(const void* p) {
    uint32_t a;
    asm("{ .reg .u64 t; cvta.to.shared.u64 t, %1; cvt.u32.u64 %0, t; }" : "=r"(a) : "l"(p));
    return a;
}
__device__ __forceinline__ void ldsm4(uint32_t* r, uint32_t addr) {
    asm volatile("ldmatrix.sync.aligned.m8n8.x4.shared.b16 {%0,%1,%2,%3}, [%4];"
                 : "=r"(r[0]), "=r"(r[1]), "=r"(r[2]), "=r"(r[3]) : "r"(addr));
}
__device__ __forceinline__ void ldsm4t(uint32_t* r, uint32_t addr) {
    asm volatile("ldmatrix.sync.aligned.m8n8.x4.trans.shared.b16 {%0,%1,%2,%3}, [%4];"
                 : "=r"(r[0]), "=r"(r[1]), "=r"(r[2]), "=r"(r[3]) : "r"(addr));
}
__device__ __forceinline__ void mma16816(float* c, const uint32_t* a, const uint32_t* b) {
    asm volatile("mma.sync.aligned.m16n8k16.row.col.f32.bf16.bf16.f32 "
                 "{%0,%1,%2,%3}, {%4,%5,%6,%7}, {%8,%9}, {%0,%1,%2,%3};"
                 : "+f"(c[0]), "+f"(c[1]), "+f"(c[2]), "+f"(c[3])
                 : "r"(a[0]), "r"(a[1]), "r"(a[2]), "r"(a[3]), "r"(b[0]), "r"(b[1]));
}
#define CP_ASYNC16(s, g) \
    asm volatile("cp.async.cg.shared.global [%0], [%1], 16;" :: "r"(s), "l"(g))
#define CP_COMMIT() asm volatile("cp.async.commit_group;" ::: "memory")
#define CP_WAIT1()  asm volatile("cp.async.wait_group 1;" ::: "memory")

__device__ __forceinline__ uint32_t packbf(float lo, float hi) {
    __nv_bfloat162 t = __floats2bfloat162_rn(lo, hi);
    return *reinterpret_cast<uint32_t*>(&t);
}

// p = exp(30*tanh(s/30) - 30). |s|<=~7 for real scores => |x|<=0.25,
// deg-5 odd Taylor error < 4e-5 in exponent; large-negative tail keeps sign.
__device__ __forceinline__ float softmax_p(float sv) {
    const float x  = sv * (1.f / 30.f);
    const float x2 = x * x;
    const float t  = x * fmaf(x2, fmaf(x2, 2.f / 15.f, -1.f / 3.f), 1.f);
    return __expf(fmaf(30.f, t, -30.f));
}

// ---------------------------------------------------------------------------
// bf16x3 HMMA GEMM: C[M,Ntot] = A @ B^T.  128x128 CTA tile, BK=32, 256 thr.
// 2 CTAs/SM. A-fragments loaded per-mf to keep regs <= 128.
// mode 0: fp32 row-major + bias -> Cf.
// mode 3: combined QKV epilogue.
// ---------------------------------------------------------------------------
__global__ __launch_bounds__(256, 2)
void gemm_mma(const __nv_bfloat16* __restrict__ Ah, const __nv_bfloat16* __restrict__ Al,
              const __nv_bfloat16* __restrict__ Bh, const __nv_bfloat16* __restrict__ Bl,
              float* __restrict__ Cf,
              __nv_bfloat16* __restrict__ Qh, __nv_bfloat16* __restrict__ Ql,
              __nv_bfloat16* __restrict__ Kh, __nv_bfloat16* __restrict__ Kl,
              __nv_bfloat16* __restrict__ Vh, __nv_bfloat16* __restrict__ Vl,
              const float2* __restrict__ rope,
              int Ntot, int mode, const float* __restrict__ bias)
{
    extern __shared__ __align__(128) char smc[];
    const uint32_t sbase = smem_u32(smc);
    const int tid = threadIdx.x, lane = tid & 31, wid = tid >> 5;
    const int wm = wid >> 2, wn = wid & 3;
    const int n0 = blockIdx.x << 7, m0 = blockIdx.y << 7;

    const int fr = tid >> 2;
    const int fc = tid & 3;

    uint32_t offA[4][2], offB[2][2];
#pragma unroll
    for (int mf = 0; mf < 4; mf++)
#pragma unroll
        for (int ks = 0; ks < 2; ks++) {
            int row = wm * 64 + mf * 16 + (lane & 7) + ((lane >> 3) & 1) * 8;
            int ch  = ks * 2 + (lane >> 4);
            offA[mf][ks] = row * 64 + ((ch ^ ((row >> 1) & 3)) << 4);
        }
#pragma unroll
    for (int np = 0; np < 2; np++)
#pragma unroll
        for (int ks = 0; ks < 2; ks++) {
            int row = wn * 32 + np * 16 + (lane & 7) + (lane >> 4) * 8;
            int ch  = ks * 2 + ((lane >> 3) & 1);
            offB[np][ks] = row * 64 + ((ch ^ ((row >> 1) & 3)) << 4);
        }

    float acc[4][4][4];
#pragma unroll
    for (int i = 0; i < 4; i++)
#pragma unroll
        for (int j = 0; j < 4; j++)
#pragma unroll
            for (int l = 0; l < 4; l++) acc[i][j][l] = 0.f;

    auto fill = [&](int kc, int stage) {
        const uint32_t sb = sbase + stage * 32768;
#pragma unroll
        for (int i = 0; i < 2; i++) {
            const int r = fr + i * 64;
            const uint32_t so = r * 64 + ((fc ^ ((r >> 1) & 3)) << 4);
            const size_t gA = (size_t)(m0 + r) * DM + kc * 32 + fc * 8;
            const size_t gB = (size_t)(n0 + r) * DM + kc * 32 + fc * 8;
            CP_ASYNC16(sb +         so, Ah + gA);
            CP_ASYNC16(sb +  8192 + so, Al + gA);
            CP_ASYNC16(sb + 16384 + so, Bh + gB);
            CP_ASYNC16(sb + 24576 + so, Bl + gB);
        }
        CP_COMMIT();
    };

    fill(0, 0);
    fill(1, 1);

    const int NKC = DM / 32;
    for (int kc = 0; kc < NKC; kc++) {
        CP_WAIT1();
        __syncthreads();
        const uint32_t sA = sbase + (kc & 1) * 32768;
#pragma unroll
        for (int ks = 0; ks < 2; ks++) {
            uint32_t bh[2][4], bl[2][4];
#pragma unroll
            for (int np = 0; np < 2; np++) {
                ldsm4(bh[np], sA + 16384 + offB[np][ks]);
                ldsm4(bl[np], sA + 24576 + offB[np][ks]);
            }
#pragma unroll
            for (int mf = 0; mf < 4; mf++) {
                uint32_t ah[4], al[4];
                ldsm4(ah, sA +        offA[mf][ks]);
                ldsm4(al, sA + 8192 + offA[mf][ks]);
#pragma unroll
                for (int nf = 0; nf < 4; nf++) {
                    const uint32_t* bhp = &bh[nf >> 1][(nf & 1) * 2];
                    const uint32_t* blp = &bl[nf >> 1][(nf & 1) * 2];
                    mma16816(acc[mf][nf], ah, bhp);
                    mma16816(acc[mf][nf], ah, blp);
                    mma16816(acc[mf][nf], al, bhp);
                }
            }
        }
        __syncthreads();
        if (kc + 2 < NKC) fill(kc + 2, kc & 1);
        else CP_COMMIT();
    }

    const int g4 = lane >> 2, t4 = lane & 3;
#pragma unroll
    for (int mf = 0; mf < 4; mf++) {
#pragma unroll
        for (int nf = 0; nf < 4; nf++) {
            const int row = m0 + wm * 64 + mf * 16 + g4;
            const int col = n0 + wn * 32 + nf * 8 + t4 * 2;
            float2 v0 = make_float2(acc[mf][nf][0], acc[mf][nf][1]);
            float2 v1 = make_float2(acc[mf][nf][2], acc[mf][nf][3]);
            if (mode == 0) {
                const float b0 = bias[col], b1 = bias[col + 1];
                v0.x += b0; v0.y += b1; v1.x += b0; v1.y += b1;
                *reinterpret_cast<float2*>(Cf + (size_t)row * Ntot + col)       = v0;
                *reinterpret_cast<float2*>(Cf + (size_t)(row + 8) * Ntot + col) = v1;
            } else {
                __nv_bfloat16 *Oh, *Ol;
                int hh, hcount;
                bool dorope;
                if (col < 2048)      { Oh = Qh; Ol = Ql; hh = col >> 6;          hcount = NH; dorope = true; }
                else if (col < 2560) { Oh = Kh; Ol = Kl; hh = (col - 2048) >> 6; hcount = NG; dorope = true; }
                else                 { Oh = Vh; Ol = Vl; hh = (col - 2560) >> 6; hcount = NG; dorope = false; }
                const int pair = (col & 63) >> 1;
                float2 vv[2] = {v0, v1};
#pragma unroll
                for (int t = 0; t < 2; t++) {
                    const int r = row + t * 8;
                    const int bb = r >> 11, s = r & (SEQ - 1);
                    float x0 = vv[t].x, x1 = vv[t].y;
                    if (dorope) {
                        float2 cs = rope[s * 32 + pair];
                        float r0 = x0 * cs.x - x1 * cs.y;
                        x1 = x1 * cs.x + x0 * cs.y;
                        x0 = r0;
                    }
                    __nv_bfloat16 h0 = __float2bfloat16_rn(x0);
                    __nv_bfloat16 h1 = __float2bfloat16_rn(x1);
                    float l0f = x0 - __bfloat162float(h0);
                    float l1f = x1 - __bfloat162float(h1);
                    size_t o32 = ((size_t)(bb * hcount + hh) * SEQ + s) * 32 + pair;
                    reinterpret_cast<uint32_t*>(Oh)[o32] =
                        packbf(__bfloat162float(h0), __bfloat162float(h1));
                    reinterpret_cast<uint32_t*>(Ol)[o32] = packbf(l0f, l1f);
                }
            }
        }
    }
}

// ---------------------------------------------------------------------------
// fp32 -> bf16 hi/lo split (hidden states)
// ---------------------------------------------------------------------------
__global__ void split_kernel(const float* __restrict__ x,
                             __nv_bfloat16* __restrict__ hi,
                             __nv_bfloat16* __restrict__ lo, int n4)
{
    int i = blockIdx.x * blockDim.x + threadIdx.x;
    if (i >= n4) return;
    float4 v = reinterpret_cast<const float4*>(x)[i];
    float f[4] = {v.x, v.y, v.z, v.w};
    __nv_bfloat16 h[4], l[4];
#pragma unroll
    for (int j = 0; j < 4; j++) {
        h[j] = __float2bfloat16_rn(f[j]);
        l[j] = __float2bfloat16_rn(f[j] - __bfloat162float(h[j]));
    }
    reinterpret_cast<uint2*>(hi)[i] = *reinterpret_cast<uint2*>(h);
    reinterpret_cast<uint2*>(lo)[i] = *reinterpret_cast<uint2*>(l);
}

// ---------------------------------------------------------------------------
// Combined QKV weight transpose+split into the fused [NQKV, DM] buffer.
// ---------------------------------------------------------------------------
__global__ void qkv_transpose(const float* __restrict__ Wq, const float* __restrict__ Wk,
                              const float* __restrict__ Wv,
                              __nv_bfloat16* __restrict__ Th, __nv_bfloat16* __restrict__ Tl)
{
    __shared__ float t[32][33];
    int bx = blockIdx.x;                 // 0..95
    const float* W; int N, rowoff;
    if (bx < 64)      { W = Wq; N = 2048; rowoff = 0; }
    else if (bx < 80) { W = Wk; N = 512;  rowoff = 2048; bx -= 64; }
    else              { W = Wv; N = 512;  rowoff = 2560; bx -= 80; }
    const int n0 = bx * 32, k0 = blockIdx.y * 32;
    const int tx = threadIdx.x, ty = threadIdx.y;
#pragma unroll
    for (int i = 0; i < 4; i++)
        t[ty + 8 * i][tx] = W[(size_t)(k0 + ty + 8 * i) * N + n0 + tx];
    __syncthreads();
#pragma unroll
    for (int i = 0; i < 4; i++) {
        float v = t[tx][ty + 8 * i];
        __nv_bfloat16 h = __float2bfloat16_rn(v);
        __nv_bfloat16 l = __float2bfloat16_rn(v - __bfloat162float(h));
        size_t o = (size_t)(rowoff + n0 + ty + 8 * i) * DM + k0 + tx;
        Th[o] = h; Tl[o] = l;
    }
}

// ---------------------------------------------------------------------------
// W [K,N] fp32 -> Wt hi/lo [N,K] bf16 (for Wo)
// ---------------------------------------------------------------------------
__global__ void transpose_split(const float* __restrict__ W,
                                __nv_bfloat16* __restrict__ Th,
                                __nv_bfloat16* __restrict__ Tl, int K, int N)
{
    __shared__ float t[32][33];
    const int n0 = blockIdx.x * 32, k0 = blockIdx.y * 32;
    const int tx = threadIdx.x, ty = threadIdx.y;
#pragma unroll
    for (int i = 0; i < 4; i++)
        t[ty + 8 * i][tx] = W[(size_t)(k0 + ty + 8 * i) * N + n0 + tx];
    __syncthreads();
#pragma unroll
    for (int i = 0; i < 4; i++) {
        float v = t[tx][ty + 8 * i];
        __nv_bfloat16 h = __float2bfloat16_rn(v);
        __nv_bfloat16 l = __float2bfloat16_rn(v - __bfloat162float(h));
        size_t o = (size_t)(n0 + ty + 8 * i) * K + k0 + tx;
        Th[o] = h; Tl[o] = l;
    }
}

// ---------------------------------------------------------------------------
// RoPE cos/sin table
// ---------------------------------------------------------------------------
__global__ void rope_table(float2* __restrict__ tb)
{
    int idx = blockIdx.x * blockDim.x + threadIdx.x;
    if (idx >= SEQ * 32) return;
    int s = idx >> 5, pair = idx & 31;
    float inv = powf(10000.f, -(float)(2 * pair) * (1.f / 64.f));
    float sn, c;
    sincosf((float)s * inv, &sn, &c);
    tb[idx] = make_float2(c, sn);
}

// ---------------------------------------------------------------------------
// MMA flash attention, 64-row KV tiles, 2 CTAs/SM (96KB smem, <=128 regs).
// Q stays in smem (re-ldsm'd per iter). Per-warp causal skip.
// ---------------------------------------------------------------------------
__global__ __launch_bounds__(256, 2)
void attn_mma(const __nv_bfloat16* __restrict__ Qh, const __nv_bfloat16* __restrict__ Ql,
              const __nv_bfloat16* __restrict__ Kh, const __nv_bfloat16* __restrict__ Kl,
              const __nv_bfloat16* __restrict__ Vh, const __nv_bfloat16* __restrict__ Vl,
              __nv_bfloat16* __restrict__ Ch, __nv_bfloat16* __restrict__ Cl)
{
    extern __shared__ __align__(128) char smc[];
    const uint32_t sb = smem_u32(smc);
    const int tid = threadIdx.x, lane = tid & 31, wid = tid >> 5;
    const int bid = blockIdx.x;
    const int qt  = (SEQ / 128 - 1) - (bid >> 6);   // work-sorted, longest first
    const int sub = bid & 63;
    const int h = sub >> 1, b = sub & 1;
    const int g = h >> 2;
    const int q0 = qt << 7;
    const int wrow = wid * 16;

    const size_t qbase = ((size_t)(b * NH + h) * SEQ + q0) * DH;
    const size_t kbase = ((size_t)(b * NG + g) * SEQ) * DH;

    // smem: Qh 16K @0, Ql 16K @16384, stages @32768 (32K each: Kh,Kl,Vh,Vl 8K)
    constexpr uint32_t SQH = 0, SQL = 16384, SST = 32768, STAGE = 32768;

    {
#pragma unroll
        for (int i = 0; i < 4; i++) {
            int idx = tid + (i << 8);
            int r = idx >> 3, ch = idx & 7;
            uint32_t so = r * 128 + ((ch ^ (r & 7)) << 4);
            CP_ASYNC16(sb + SQH + so, Qh + qbase + r * 64 + ch * 8);
            CP_ASYNC16(sb + SQL + so, Ql + qbase + r * 64 + ch * 8);
        }
        CP_COMMIT();
    }
    auto fillkv = [&](int kt, int st) {
        const uint32_t s0 = sb + SST + st * STAGE;
        const size_t kb = kbase + (size_t)kt * 64 * 64;
#pragma unroll
        for (int i = 0; i < 2; i++) {
            int idx = tid + (i << 8);
            int r = idx >> 3, ch = idx & 7;
            uint32_t so = r * 128 + ((ch ^ (r & 7)) << 4);
            size_t go = kb + r * 64 + ch * 8;
            CP_ASYNC16(s0 +         so, Kh + go);
            CP_ASYNC16(s0 +  8192 + so, Kl + go);
            CP_ASYNC16(s0 + 16384 + so, Vh + go);
            CP_ASYNC16(s0 + 24576 + so, Vl + go);
        }
        CP_COMMIT();
    };
    const int nkt = (qt + 1) * 2;   // 64-row tiles
    fillkv(0, 0);
    fillkv(1, 1);

    // Q ldsm offsets (Q tile 128x64, this warp's 16 rows)
    uint32_t qoff[4];
    {
        const int row = wrow + (lane & 7) + ((lane >> 3) & 1) * 8;
        const int chb = lane >> 4;
#pragma unroll
        for (int ks = 0; ks < 4; ks++)
            qoff[ks] = row * 128 + (((ks * 2 + chb) ^ (row & 7)) << 4);
    }

    float oac[8][4];
#pragma unroll
    for (int i = 0; i < 8; i++)
#pragma unroll
        for (int j = 0; j < 4; j++) oac[i][j] = 0.f;
    float ls0 = 0.f, ls1 = 0.f;
    const float slope8 = exp2f(-(float)(h + 1) * 0.25f) * 0.125f;
    const int qr = q0 + wrow + (lane >> 2);

    const int klrow = (lane & 7) + ((lane >> 4) << 3);
    const int klchb = (lane >> 3) & 1;
    const int vlrow = (lane & 7) + (((lane >> 3) & 1) << 3);
    const int vlchb = lane >> 4;

    for (int kt = 0; kt < nkt; kt++) {
        const int st = kt & 1;
        const uint32_t sK = sb + SST + st * STAGE;
        CP_WAIT1();
        __syncthreads();

        if ((kt << 6) <= q0 + wrow + 15) {   // warp has at least one unmasked col
            float sc[8][4];
#pragma unroll
            for (int i = 0; i < 8; i++)
#pragma unroll
                for (int j = 0; j < 4; j++) sc[i][j] = 0.f;

            // S = Q @ K^T (bf16x3), K tile 64 positions
#pragma unroll
            for (int ks = 0; ks < 4; ks++) {
                uint32_t qh_t[4], ql_t[4];
                ldsm4(qh_t, sb + SQH + qoff[ks]);
                ldsm4(ql_t, sb + SQL + qoff[ks]);
#pragma unroll
                for (int ng = 0; ng < 4; ng++) {
                    const int row = ng * 16 + klrow;
                    const uint32_t so = row * 128 + (((ks * 2 + klchb) ^ (row & 7)) << 4);
                    uint32_t kfh[4], kfl[4];
                    ldsm4(kfh, sK + so);
                    ldsm4(kfl, sK + 8192 + so);
                    mma16816(sc[ng * 2],     qh_t, kfh);
                    mma16816(sc[ng * 2],     qh_t, kfl);
                    mma16816(sc[ng * 2],     ql_t, kfh);
                    mma16816(sc[ng * 2 + 1], qh_t, kfh + 2);
                    mma16816(sc[ng * 2 + 1], qh_t, kfl + 2);
                    mma16816(sc[ng * 2 + 1], ql_t, kfh + 2);
                }
            }

            // softmax (fixed max)
            const int kcol0 = (kt << 6) + (lane & 3) * 2;
            const bool tail = ((kt << 6) + 63 > q0 + wrow);
#pragma unroll
            for (int nf = 0; nf < 8; nf++) {
                const int kc = kcol0 + nf * 8;
                const float bias0 = slope8 * (float)(kc - qr);
                float p0 = softmax_p(fmaf(sc[nf][0], 0.125f, bias0));
                float p1 = softmax_p(fmaf(sc[nf][1], 0.125f, bias0 + slope8));
                float p2 = softmax_p(fmaf(sc[nf][2], 0.125f, bias0 - 8.f * slope8));
                float p3 = softmax_p(fmaf(sc[nf][3], 0.125f, bias0 - 7.f * slope8));
                if (tail) {
                    if (kc > qr)         p0 = 0.f;
                    if (kc + 1 > qr)     p1 = 0.f;
                    if (kc > qr + 8)     p2 = 0.f;
                    if (kc + 1 > qr + 8) p3 = 0.f;
                }
                ls0 += p0 + p1;
                ls1 += p2 + p3;
                sc[nf][0] = p0; sc[nf][1] = p1; sc[nf][2] = p2; sc[nf][3] = p3;
            }

            // O += P @ V (bf16x3, P in registers)
#pragma unroll
            for (int j = 0; j < 4; j++) {
                uint32_t pah[4], pal[4];
#pragma unroll
                for (int u = 0; u < 2; u++) {
                    const float* p = sc[2 * j + u];
                    __nv_bfloat16 h0 = __float2bfloat16_rn(p[0]);
                    __nv_bfloat16 h1 = __float2bfloat16_rn(p[1]);
                    __nv_bfloat16 h2 = __float2bfloat16_rn(p[2]);
                    __nv_bfloat16 h3 = __float2bfloat16_rn(p[3]);
                    pah[2 * u]     = packbf(__bfloat162float(h0), __bfloat162float(h1));
                    pah[2 * u + 1] = packbf(__bfloat162float(h2), __bfloat162float(h3));
                    pal[2 * u]     = packbf(p[0] - __bfloat162float(h0), p[1] - __bfloat162float(h1));
                    pal[2 * u + 1] = packbf(p[2] - __bfloat162float(h2), p[3] - __bfloat162float(h3));
                }
#pragma unroll
                for (int gD = 0; gD < 4; gD++) {
                    const int row = j * 16 + vlrow;
                    const uint32_t so = row * 128 + (((gD * 2 + vlchb) ^ (row & 7)) << 4);
                    uint32_t vfh[4], vfl[4];
                    ldsm4t(vfh, sK + 16384 + so);
                    ldsm4t(vfl, sK + 24576 + so);
                    mma16816(oac[gD * 2],     pah, vfh);
                    mma16816(oac[gD * 2],     pah, vfl);
                    mma16816(oac[gD * 2],     pal, vfh);
                    mma16816(oac[gD * 2 + 1], pah, vfh + 2);
                    mma16816(oac[gD * 2 + 1], pah, vfl + 2);
                    mma16816(oac[gD * 2 + 1], pal, vfh + 2);
                }
            }
        }
        __syncthreads();
        if (kt + 2 < nkt) fillkv(kt + 2, st); else CP_COMMIT();
    }

    ls0 += __shfl_xor_sync(0xffffffffu, ls0, 1);
    ls0 += __shfl_xor_sync(0xffffffffu, ls0, 2);
    ls1 += __shfl_xor_sync(0xffffffffu, ls1, 1);
    ls1 += __shfl_xor_sync(0xffffffffu, ls1, 2);
    const float inv0 = 1.f / ls0, inv1 = 1.f / ls1;

    const size_t rowM0 = (size_t)b * SEQ + qr;
#pragma unroll
    for (int nf = 0; nf < 8; nf++) {
        const int col = h * 64 + nf * 8 + (lane & 3) * 2;
        float x0 = oac[nf][0] * inv0, x1 = oac[nf][1] * inv0;
        float y0 = oac[nf][2] * inv1, y1 = oac[nf][3] * inv1;
        __nv_bfloat16 hx0 = __float2bfloat16_rn(x0), hx1 = __float2bfloat16_rn(x1);
        __nv_bfloat16 hy0 = __float2bfloat16_rn(y0), hy1 = __float2bfloat16_rn(y1);
        size_t o0 = (rowM0 * DM + col) >> 1;
        size_t o1 = ((rowM0 + 8) * DM + col) >> 1;
        reinterpret_cast<uint32_t*>(Ch)[o0] = packbf(__bfloat162float(hx0), __bfloat162float(hx1));
        reinterpret_cast<uint32_t*>(Cl)[o0] = packbf(x0 - __bfloat162float(hx0), x1 - __bfloat162float(hx1));
        reinterpret_cast<uint32_t*>(Ch)[o1] = packbf(__bfloat162float(hy0), __bfloat162float(hy1));
        reinterpret_cast<uint32_t*>(Cl)[o1] = packbf(y0 - __bfloat162float(hy0), y1 - __bfloat162float(hy1));
    }
}

// ---------------------------------------------------------------------------
extern "C" void kernel_launch(void* const* d_in, const int* in_sizes, int n_in,
                              void* d_out, int out_size)
{
    const float* hs = (const float*)d_in[0];
    const float* Wq = (const float*)d_in[1];
    const float* Wk = (const float*)d_in[2];
    const float* Wv = (const float*)d_in[3];
    const float* Wo = (const float*)d_in[4];
    const float* bo = (const float*)d_in[5];
    float* out = (float*)d_out;

    __nv_bfloat16 *ah, *al, *wch, *wcl, *woh, *wol;
    __nv_bfloat16 *qh, *ql, *kh, *kl, *vh, *vl;
    float2* rope;
    cudaGetSymbolAddress((void**)&ah,  g_ah);
    cudaGetSymbolAddress((void**)&al,  g_al);
    cudaGetSymbolAddress((void**)&wch, g_wch);
    cudaGetSymbolAddress((void**)&wcl, g_wcl);
    cudaGetSymbolAddress((void**)&woh, g_woh);
    cudaGetSymbolAddress((void**)&wol, g_wol);
    cudaGetSymbolAddress((void**)&qh,  g_qh);
    cudaGetSymbolAddress((void**)&ql,  g_ql);
    cudaGetSymbolAddress((void**)&kh,  g_kh);
    cudaGetSymbolAddress((void**)&kl,  g_kl);
    cudaGetSymbolAddress((void**)&vh,  g_vh);
    cudaGetSymbolAddress((void**)&vl,  g_vl);
    cudaGetSymbolAddress((void**)&rope, g_rope);

    const int gemm_smem = 2 * 32768;   // 64 KB
    cudaFuncSetAttribute(gemm_mma, cudaFuncAttributeMaxDynamicSharedMemorySize, gemm_smem);
    const int attn_smem = 32768 + 2 * 32768;   // 96 KB -> 2 CTAs/SM
    cudaFuncSetAttribute(attn_mma, cudaFuncAttributeMaxDynamicSharedMemorySize, attn_smem);

    // 0) split hs
    {
        int n4 = MROWS * DM / 4;
        split_kernel<<<(n4 + 255) / 256, 256>>>(hs, ah, al, n4);
    }
    // 1-2) weight transposes
    {
        dim3 tb(32, 8);
        qkv_transpose<<<dim3(96, 64), tb>>>(Wq, Wk, Wv, wch, wcl);
        transpose_split<<<dim3(DM / 32, DM / 32), tb>>>(Wo, woh, wol, DM, DM);
    }
    // 3) rope table
    rope_table<<<(SEQ * 32 + 255) / 256, 256>>>(rope);

    // 4) combined QKV projection (rope + split epilogue)
    gemm_mma<<<dim3(NQKV / 128, MROWS / 128), 256, gemm_smem>>>(
        ah, al, wch, wcl, nullptr, qh, ql, kh, kl, vh, vl, rope, NQKV, 3, nullptr);

    // 5) attention (writes split ctx into ah/al)
    attn_mma<<<dim3(16 * 64), 256, attn_smem>>>(
        qh, ql, kh, kl, vh, vl, ah, al);

    // 6) output projection + bias
    gemm_mma<<<dim3(DM / 128, MROWS / 128), 256, gemm_smem>>>(
        ah, al, woh, wol, out, nullptr, nullptr, nullptr, nullptr, nullptr, nullptr,
        nullptr, DM, 0, bo);
}

// round 9
// speedup vs baseline: 4.0971x; 1.0516x over previous
#include <cuda_runtime.h>
#include <cuda_bf16.h>
#include <math.h>
#include <stdint.h>

#define DM    2048
#define SEQ   2048
#define BATCH 2
#define NH    32
#define NG    8
#define DH    64
#define MROWS (BATCH*SEQ)   // 4096
#define NQKV  3072          // combined projection width

// ---------------- scratch (__device__ globals; no allocs allowed) ----------
__device__ __nv_bfloat16 g_ah[(size_t)MROWS*DM];   // A split (hs, later ctx)
__device__ __nv_bfloat16 g_al[(size_t)MROWS*DM];
__device__ __nv_bfloat16 g_wch[(size_t)NQKV*DM], g_wcl[(size_t)NQKV*DM];  // Wqkv^T split
__device__ __nv_bfloat16 g_woh[(size_t)DM*DM],   g_wol[(size_t)DM*DM];
__device__ __nv_bfloat16 g_qh[(size_t)BATCH*NH*SEQ*DH], g_ql[(size_t)BATCH*NH*SEQ*DH];
__device__ __nv_bfloat16 g_kh[(size_t)BATCH*NG*SEQ*DH], g_kl[(size_t)BATCH*NG*SEQ*DH];
__device__ __nv_bfloat16 g_vh[(size_t)BATCH*NG*SEQ*DH], g_vl[(size_t)BATCH*NG*SEQ*DH];
__device__ float2 g_rope[SEQ * 32];

// ---------------- helpers ---------------------------------------------------
__device__ __forceinline__ uint32_t smem_u32(const void* p) {
    uint32_t a;
    asm("{ .reg .u64 t; cvta.to.shared.u64 t, %1; cvt.u32.u64 %0, t; }" : "=r"(a) : "l"(p));
    return a;
}
__device__ __forceinline__ void ldsm4(uint32_t* r, uint32_t addr) {
    asm volatile("ldmatrix.sync.aligned.m8n8.x4.shared.b16 {%0,%1,%2,%3}, [%4];"
                 : "=r"(r[0]), "=r"(r[1]), "=r"(r[2]), "=r"(r[3]) : "r"(addr));
}
__device__ __forceinline__ void ldsm4t(uint32_t* r, uint32_t addr) {
    asm volatile("ldmatrix.sync.aligned.m8n8.x4.trans.shared.b16 {%0,%1,%2,%3}, [%4];"
                 : "=r"(r[0]), "=r"(r[1]), "=r"(r[2]), "=r"(r[3]) : "r"(addr));
}
__device__ __forceinline__ void mma16816(float* c, const uint32_t* a, const uint32_t* b) {
    asm volatile("mma.sync.aligned.m16n8k16.row.col.f32.bf16.bf16.f32 "
                 "{%0,%1,%2,%3}, {%4,%5,%6,%7}, {%8,%9}, {%0,%1,%2,%3};"
                 : "+f"(c[0]), "+f"(c[1]), "+f"(c[2]), "+f"(c[3])
                 : "r"(a[0]), "r"(a[1]), "r"(a[2]), "r"(a[3]), "r"(b[0]), "r"(b[1]));
}
#define CP_ASYNC16(s, g) \
    asm volatile("cp.async.cg.shared.global [%0], [%1], 16;" :: "r"(s), "l"(g))
#define CP_COMMIT() asm volatile("cp.async.commit_group;" ::: "memory")
#define CP_WAIT1()  asm volatile("cp.async.wait_group 1;" ::: "memory")

__device__ __forceinline__ uint32_t packbf(float lo, float hi) {
    __nv_bfloat162 t = __floats2bfloat162_rn(lo, hi);
    return *reinterpret_cast<uint32_t*>(&t);
}

// p = exp(30*tanh(s/30) - 30). |s|<=~7 for real scores => |x|<=0.25,
// deg-5 odd Taylor error < 4e-5 in exponent; large-negative tail keeps sign.
__device__ __forceinline__ float softmax_p(float sv) {
    const float x  = sv * (1.f / 30.f);
    const float x2 = x * x;
    const float t  = x * fmaf(x2, fmaf(x2, 2.f / 15.f, -1.f / 3.f), 1.f);
    return __expf(fmaf(30.f, t, -30.f));
}

// ---------------------------------------------------------------------------
// bf16x3 HMMA GEMM: C[M,Ntot] = A @ B^T.  128x128 CTA tile, BK=32, 256 thr.
// 3-stage cp.async ring, fill-ahead-2 + wait_group 1, ONE syncthreads per iter
// (write stage (kc+2)%3 never aliases read stage kc%3). 2 CTAs/SM.
// mode 0: fp32 row-major + bias -> Cf.   mode 3: combined QKV epilogue.
// ---------------------------------------------------------------------------
__global__ __launch_bounds__(256, 2)
void gemm_mma(const __nv_bfloat16* __restrict__ Ah, const __nv_bfloat16* __restrict__ Al,
              const __nv_bfloat16* __restrict__ Bh, const __nv_bfloat16* __restrict__ Bl,
              float* __restrict__ Cf,
              __nv_bfloat16* __restrict__ Qh, __nv_bfloat16* __restrict__ Ql,
              __nv_bfloat16* __restrict__ Kh, __nv_bfloat16* __restrict__ Kl,
              __nv_bfloat16* __restrict__ Vh, __nv_bfloat16* __restrict__ Vl,
              const float2* __restrict__ rope,
              int Ntot, int mode, const float* __restrict__ bias)
{
    extern __shared__ __align__(128) char smc[];
    const uint32_t sbase = smem_u32(smc);
    const int tid = threadIdx.x, lane = tid & 31, wid = tid >> 5;
    const int wm = wid >> 2, wn = wid & 3;
    const int n0 = blockIdx.x << 7, m0 = blockIdx.y << 7;

    const int fr = tid >> 2;
    const int fc = tid & 3;

    uint32_t offA[4][2], offB[2][2];
#pragma unroll
    for (int mf = 0; mf < 4; mf++)
#pragma unroll
        for (int ks = 0; ks < 2; ks++) {
            int row = wm * 64 + mf * 16 + (lane & 7) + ((lane >> 3) & 1) * 8;
            int ch  = ks * 2 + (lane >> 4);
            offA[mf][ks] = row * 64 + ((ch ^ ((row >> 1) & 3)) << 4);
        }
#pragma unroll
    for (int np = 0; np < 2; np++)
#pragma unroll
        for (int ks = 0; ks < 2; ks++) {
            int row = wn * 32 + np * 16 + (lane & 7) + (lane >> 4) * 8;
            int ch  = ks * 2 + ((lane >> 3) & 1);
            offB[np][ks] = row * 64 + ((ch ^ ((row >> 1) & 3)) << 4);
        }

    float acc[4][4][4];
#pragma unroll
    for (int i = 0; i < 4; i++)
#pragma unroll
        for (int j = 0; j < 4; j++)
#pragma unroll
            for (int l = 0; l < 4; l++) acc[i][j][l] = 0.f;

    auto fill = [&](int kc, int stage) {
        const uint32_t sb = sbase + stage * 32768;
#pragma unroll
        for (int i = 0; i < 2; i++) {
            const int r = fr + i * 64;
            const uint32_t so = r * 64 + ((fc ^ ((r >> 1) & 3)) << 4);
            const size_t gA = (size_t)(m0 + r) * DM + kc * 32 + fc * 8;
            const size_t gB = (size_t)(n0 + r) * DM + kc * 32 + fc * 8;
            CP_ASYNC16(sb +         so, Ah + gA);
            CP_ASYNC16(sb +  8192 + so, Al + gA);
            CP_ASYNC16(sb + 16384 + so, Bh + gB);
            CP_ASYNC16(sb + 24576 + so, Bl + gB);
        }
        CP_COMMIT();
    };

    fill(0, 0);
    fill(1, 1);

    const int NKC = DM / 32;
    int rd = 0, wr = 2;                 // rotating stage indices
    for (int kc = 0; kc < NKC; kc++) {
        CP_WAIT1();                     // oldest pending fill (stage rd) complete
        __syncthreads();
        const uint32_t sA = sbase + rd * 32768;
#pragma unroll
        for (int ks = 0; ks < 2; ks++) {
            uint32_t bh[2][4], bl[2][4];
#pragma unroll
            for (int np = 0; np < 2; np++) {
                ldsm4(bh[np], sA + 16384 + offB[np][ks]);
                ldsm4(bl[np], sA + 24576 + offB[np][ks]);
            }
#pragma unroll
            for (int mf = 0; mf < 4; mf++) {
                uint32_t ah[4], al[4];
                ldsm4(ah, sA +        offA[mf][ks]);
                ldsm4(al, sA + 8192 + offA[mf][ks]);
#pragma unroll
                for (int nf = 0; nf < 4; nf++) {
                    const uint32_t* bhp = &bh[nf >> 1][(nf & 1) * 2];
                    const uint32_t* blp = &bl[nf >> 1][(nf & 1) * 2];
                    mma16816(acc[mf][nf], ah, bhp);
                    mma16816(acc[mf][nf], ah, blp);
                    mma16816(acc[mf][nf], al, bhp);
                }
            }
        }
        if (kc + 2 < NKC) fill(kc + 2, wr);
        else CP_COMMIT();
        rd = (rd == 2) ? 0 : rd + 1;
        wr = (wr == 2) ? 0 : wr + 1;
    }

    const int g4 = lane >> 2, t4 = lane & 3;
#pragma unroll
    for (int mf = 0; mf < 4; mf++) {
#pragma unroll
        for (int nf = 0; nf < 4; nf++) {
            const int row = m0 + wm * 64 + mf * 16 + g4;
            const int col = n0 + wn * 32 + nf * 8 + t4 * 2;
            float2 v0 = make_float2(acc[mf][nf][0], acc[mf][nf][1]);
            float2 v1 = make_float2(acc[mf][nf][2], acc[mf][nf][3]);
            if (mode == 0) {
                const float b0 = bias[col], b1 = bias[col + 1];
                v0.x += b0; v0.y += b1; v1.x += b0; v1.y += b1;
                *reinterpret_cast<float2*>(Cf + (size_t)row * Ntot + col)       = v0;
                *reinterpret_cast<float2*>(Cf + (size_t)(row + 8) * Ntot + col) = v1;
            } else {
                __nv_bfloat16 *Oh, *Ol;
                int hh, hcount;
                bool dorope;
                if (col < 2048)      { Oh = Qh; Ol = Ql; hh = col >> 6;          hcount = NH; dorope = true; }
                else if (col < 2560) { Oh = Kh; Ol = Kl; hh = (col - 2048) >> 6; hcount = NG; dorope = true; }
                else                 { Oh = Vh; Ol = Vl; hh = (col - 2560) >> 6; hcount = NG; dorope = false; }
                const int pair = (col & 63) >> 1;
                float2 vv[2] = {v0, v1};
#pragma unroll
                for (int t = 0; t < 2; t++) {
                    const int r = row + t * 8;
                    const int bb = r >> 11, s = r & (SEQ - 1);
                    float x0 = vv[t].x, x1 = vv[t].y;
                    if (dorope) {
                        float2 cs = rope[s * 32 + pair];
                        float r0 = x0 * cs.x - x1 * cs.y;
                        x1 = x1 * cs.x + x0 * cs.y;
                        x0 = r0;
                    }
                    __nv_bfloat16 h0 = __float2bfloat16_rn(x0);
                    __nv_bfloat16 h1 = __float2bfloat16_rn(x1);
                    float l0f = x0 - __bfloat162float(h0);
                    float l1f = x1 - __bfloat162float(h1);
                    size_t o32 = ((size_t)(bb * hcount + hh) * SEQ + s) * 32 + pair;
                    reinterpret_cast<uint32_t*>(Oh)[o32] =
                        packbf(__bfloat162float(h0), __bfloat162float(h1));
                    reinterpret_cast<uint32_t*>(Ol)[o32] = packbf(l0f, l1f);
                }
            }
        }
    }
}

// ---------------------------------------------------------------------------
// fp32 -> bf16 hi/lo split (hidden states)
// ---------------------------------------------------------------------------
__global__ void split_kernel(const float* __restrict__ x,
                             __nv_bfloat16* __restrict__ hi,
                             __nv_bfloat16* __restrict__ lo, int n4)
{
    int i = blockIdx.x * blockDim.x + threadIdx.x;
    if (i >= n4) return;
    float4 v = reinterpret_cast<const float4*>(x)[i];
    float f[4] = {v.x, v.y, v.z, v.w};
    __nv_bfloat16 h[4], l[4];
#pragma unroll
    for (int j = 0; j < 4; j++) {
        h[j] = __float2bfloat16_rn(f[j]);
        l[j] = __float2bfloat16_rn(f[j] - __bfloat162float(h[j]));
    }
    reinterpret_cast<uint2*>(hi)[i] = *reinterpret_cast<uint2*>(h);
    reinterpret_cast<uint2*>(lo)[i] = *reinterpret_cast<uint2*>(l);
}

// ---------------------------------------------------------------------------
// All weight transposes + rope table in ONE launch.
// grid (161, 64): bx<96 -> QKV transpose; bx<160 -> Wo transpose; bx==160 -> rope.
// ---------------------------------------------------------------------------
__global__ void prep_weights(const float* __restrict__ Wq, const float* __restrict__ Wk,
                             const float* __restrict__ Wv, const float* __restrict__ Wo,
                             __nv_bfloat16* __restrict__ Tch, __nv_bfloat16* __restrict__ Tcl,
                             __nv_bfloat16* __restrict__ Toh, __nv_bfloat16* __restrict__ Tol,
                             float2* __restrict__ rope)
{
    int bx = blockIdx.x;
    const int tid = threadIdx.y * 32 + threadIdx.x;
    if (bx == 160) {
        int idx = (blockIdx.y * 256 + tid) * 4;
#pragma unroll
        for (int j = 0; j < 4; j++) {
            int id = idx + j;
            int s = id >> 5, pair = id & 31;
            float inv = powf(10000.f, -(float)(2 * pair) * (1.f / 64.f));
            float sn, c;
            sincosf((float)s * inv, &sn, &c);
            rope[id] = make_float2(c, sn);
        }
        return;
    }
    __shared__ float t[32][33];
    const float* W;
    __nv_bfloat16 *Th, *Tl;
    int N, rowoff;
    if (bx < 64)       { W = Wq; N = 2048; rowoff = 0;    Th = Tch; Tl = Tcl; }
    else if (bx < 80)  { W = Wk; N = 512;  rowoff = 2048; Th = Tch; Tl = Tcl; bx -= 64; }
    else if (bx < 96)  { W = Wv; N = 512;  rowoff = 2560; Th = Tch; Tl = Tcl; bx -= 80; }
    else               { W = Wo; N = 2048; rowoff = 0;    Th = Toh; Tl = Tol; bx -= 96; }
    const int n0 = bx * 32, k0 = blockIdx.y * 32;
    const int tx = threadIdx.x, ty = threadIdx.y;
#pragma unroll
    for (int i = 0; i < 4; i++)
        t[ty + 8 * i][tx] = W[(size_t)(k0 + ty + 8 * i) * N + n0 + tx];
    __syncthreads();
#pragma unroll
    for (int i = 0; i < 4; i++) {
        float v = t[tx][ty + 8 * i];
        __nv_bfloat16 h = __float2bfloat16_rn(v);
        __nv_bfloat16 l = __float2bfloat16_rn(v - __bfloat162float(h));
        size_t o = (size_t)(rowoff + n0 + ty + 8 * i) * DM + k0 + tx;
        Th[o] = h; Tl[o] = l;
    }
}

// ---------------------------------------------------------------------------
// MMA flash attention, 64-row KV tiles, 2 CTAs/SM (96KB smem, <=128 regs).
// Q stays in smem (re-ldsm'd per iter). Per-warp causal skip.
// ---------------------------------------------------------------------------
__global__ __launch_bounds__(256, 2)
void attn_mma(const __nv_bfloat16* __restrict__ Qh, const __nv_bfloat16* __restrict__ Ql,
              const __nv_bfloat16* __restrict__ Kh, const __nv_bfloat16* __restrict__ Kl,
              const __nv_bfloat16* __restrict__ Vh, const __nv_bfloat16* __restrict__ Vl,
              __nv_bfloat16* __restrict__ Ch, __nv_bfloat16* __restrict__ Cl)
{
    extern __shared__ __align__(128) char smc[];
    const uint32_t sb = smem_u32(smc);
    const int tid = threadIdx.x, lane = tid & 31, wid = tid >> 5;
    const int bid = blockIdx.x;
    const int qt  = (SEQ / 128 - 1) - (bid >> 6);   // work-sorted, longest first
    const int sub = bid & 63;
    const int h = sub >> 1, b = sub & 1;
    const int g = h >> 2;
    const int q0 = qt << 7;
    const int wrow = wid * 16;

    const size_t qbase = ((size_t)(b * NH + h) * SEQ + q0) * DH;
    const size_t kbase = ((size_t)(b * NG + g) * SEQ) * DH;

    constexpr uint32_t SQH = 0, SQL = 16384, SST = 32768, STAGE = 32768;

    {
#pragma unroll
        for (int i = 0; i < 4; i++) {
            int idx = tid + (i << 8);
            int r = idx >> 3, ch = idx & 7;
            uint32_t so = r * 128 + ((ch ^ (r & 7)) << 4);
            CP_ASYNC16(sb + SQH + so, Qh + qbase + r * 64 + ch * 8);
            CP_ASYNC16(sb + SQL + so, Ql + qbase + r * 64 + ch * 8);
        }
        CP_COMMIT();
    }
    auto fillkv = [&](int kt, int st) {
        const uint32_t s0 = sb + SST + st * STAGE;
        const size_t kb = kbase + (size_t)kt * 64 * 64;
#pragma unroll
        for (int i = 0; i < 2; i++) {
            int idx = tid + (i << 8);
            int r = idx >> 3, ch = idx & 7;
            uint32_t so = r * 128 + ((ch ^ (r & 7)) << 4);
            size_t go = kb + r * 64 + ch * 8;
            CP_ASYNC16(s0 +         so, Kh + go);
            CP_ASYNC16(s0 +  8192 + so, Kl + go);
            CP_ASYNC16(s0 + 16384 + so, Vh + go);
            CP_ASYNC16(s0 + 24576 + so, Vl + go);
        }
        CP_COMMIT();
    };
    const int nkt = (qt + 1) * 2;   // 64-row tiles
    fillkv(0, 0);
    fillkv(1, 1);

    uint32_t qoff[4];
    {
        const int row = wrow + (lane & 7) + ((lane >> 3) & 1) * 8;
        const int chb = lane >> 4;
#pragma unroll
        for (int ks = 0; ks < 4; ks++)
            qoff[ks] = row * 128 + (((ks * 2 + chb) ^ (row & 7)) << 4);
    }

    float oac[8][4];
#pragma unroll
    for (int i = 0; i < 8; i++)
#pragma unroll
        for (int j = 0; j < 4; j++) oac[i][j] = 0.f;
    float ls0 = 0.f, ls1 = 0.f;
    const float slope8 = exp2f(-(float)(h + 1) * 0.25f) * 0.125f;
    const int qr = q0 + wrow + (lane >> 2);

    const int klrow = (lane & 7) + ((lane >> 4) << 3);
    const int klchb = (lane >> 3) & 1;
    const int vlrow = (lane & 7) + (((lane >> 3) & 1) << 3);
    const int vlchb = lane >> 4;

    for (int kt = 0; kt < nkt; kt++) {
        const int st = kt & 1;
        const uint32_t sK = sb + SST + st * STAGE;
        CP_WAIT1();
        __syncthreads();

        if ((kt << 6) <= q0 + wrow + 15) {
            float sc[8][4];
#pragma unroll
            for (int i = 0; i < 8; i++)
#pragma unroll
                for (int j = 0; j < 4; j++) sc[i][j] = 0.f;

#pragma unroll
            for (int ks = 0; ks < 4; ks++) {
                uint32_t qh_t[4], ql_t[4];
                ldsm4(qh_t, sb + SQH + qoff[ks]);
                ldsm4(ql_t, sb + SQL + qoff[ks]);
#pragma unroll
                for (int ng = 0; ng < 4; ng++) {
                    const int row = ng * 16 + klrow;
                    const uint32_t so = row * 128 + (((ks * 2 + klchb) ^ (row & 7)) << 4);
                    uint32_t kfh[4], kfl[4];
                    ldsm4(kfh, sK + so);
                    ldsm4(kfl, sK + 8192 + so);
                    mma16816(sc[ng * 2],     qh_t, kfh);
                    mma16816(sc[ng * 2],     qh_t, kfl);
                    mma16816(sc[ng * 2],     ql_t, kfh);
                    mma16816(sc[ng * 2 + 1], qh_t, kfh + 2);
                    mma16816(sc[ng * 2 + 1], qh_t, kfl + 2);
                    mma16816(sc[ng * 2 + 1], ql_t, kfh + 2);
                }
            }

            const int kcol0 = (kt << 6) + (lane & 3) * 2;
            const bool tail = ((kt << 6) + 63 > q0 + wrow);
#pragma unroll
            for (int nf = 0; nf < 8; nf++) {
                const int kc = kcol0 + nf * 8;
                const float bias0 = slope8 * (float)(kc - qr);
                float p0 = softmax_p(fmaf(sc[nf][0], 0.125f, bias0));
                float p1 = softmax_p(fmaf(sc[nf][1], 0.125f, bias0 + slope8));
                float p2 = softmax_p(fmaf(sc[nf][2], 0.125f, bias0 - 8.f * slope8));
                float p3 = softmax_p(fmaf(sc[nf][3], 0.125f, bias0 - 7.f * slope8));
                if (tail) {
                    if (kc > qr)         p0 = 0.f;
                    if (kc + 1 > qr)     p1 = 0.f;
                    if (kc > qr + 8)     p2 = 0.f;
                    if (kc + 1 > qr + 8) p3 = 0.f;
                }
                ls0 += p0 + p1;
                ls1 += p2 + p3;
                sc[nf][0] = p0; sc[nf][1] = p1; sc[nf][2] = p2; sc[nf][3] = p3;
            }

#pragma unroll
            for (int j = 0; j < 4; j++) {
                uint32_t pah[4], pal[4];
#pragma unroll
                for (int u = 0; u < 2; u++) {
                    const float* p = sc[2 * j + u];
                    __nv_bfloat16 h0 = __float2bfloat16_rn(p[0]);
                    __nv_bfloat16 h1 = __float2bfloat16_rn(p[1]);
                    __nv_bfloat16 h2 = __float2bfloat16_rn(p[2]);
                    __nv_bfloat16 h3 = __float2bfloat16_rn(p[3]);
                    pah[2 * u]     = packbf(__bfloat162float(h0), __bfloat162float(h1));
                    pah[2 * u + 1] = packbf(__bfloat162float(h2), __bfloat162float(h3));
                    pal[2 * u]     = packbf(p[0] - __bfloat162float(h0), p[1] - __bfloat162float(h1));
                    pal[2 * u + 1] = packbf(p[2] - __bfloat162float(h2), p[3] - __bfloat162float(h3));
                }
#pragma unroll
                for (int gD = 0; gD < 4; gD++) {
                    const int row = j * 16 + vlrow;
                    const uint32_t so = row * 128 + (((gD * 2 + vlchb) ^ (row & 7)) << 4);
                    uint32_t vfh[4], vfl[4];
                    ldsm4t(vfh, sK + 16384 + so);
                    ldsm4t(vfl, sK + 24576 + so);
                    mma16816(oac[gD * 2],     pah, vfh);
                    mma16816(oac[gD * 2],     pah, vfl);
                    mma16816(oac[gD * 2],     pal, vfh);
                    mma16816(oac[gD * 2 + 1], pah, vfh + 2);
                    mma16816(oac[gD * 2 + 1], pah, vfl + 2);
                    mma16816(oac[gD * 2 + 1], pal, vfh + 2);
                }
            }
        }
        __syncthreads();
        if (kt + 2 < nkt) fillkv(kt + 2, st); else CP_COMMIT();
    }

    ls0 += __shfl_xor_sync(0xffffffffu, ls0, 1);
    ls0 += __shfl_xor_sync(0xffffffffu, ls0, 2);
    ls1 += __shfl_xor_sync(0xffffffffu, ls1, 1);
    ls1 += __shfl_xor_sync(0xffffffffu, ls1, 2);
    const float inv0 = 1.f / ls0, inv1 = 1.f / ls1;

    const size_t rowM0 = (size_t)b * SEQ + qr;
#pragma unroll
    for (int nf = 0; nf < 8; nf++) {
        const int col = h * 64 + nf * 8 + (lane & 3) * 2;
        float x0 = oac[nf][0] * inv0, x1 = oac[nf][1] * inv0;
        float y0 = oac[nf][2] * inv1, y1 = oac[nf][3] * inv1;
        __nv_bfloat16 hx0 = __float2bfloat16_rn(x0), hx1 = __float2bfloat16_rn(x1);
        __nv_bfloat16 hy0 = __float2bfloat16_rn(y0), hy1 = __float2bfloat16_rn(y1);
        size_t o0 = (rowM0 * DM + col) >> 1;
        size_t o1 = ((rowM0 + 8) * DM + col) >> 1;
        reinterpret_cast<uint32_t*>(Ch)[o0] = packbf(__bfloat162float(hx0), __bfloat162float(hx1));
        reinterpret_cast<uint32_t*>(Cl)[o0] = packbf(x0 - __bfloat162float(hx0), x1 - __bfloat162float(hx1));
        reinterpret_cast<uint32_t*>(Ch)[o1] = packbf(__bfloat162float(hy0), __bfloat162float(hy1));
        reinterpret_cast<uint32_t*>(Cl)[o1] = packbf(y0 - __bfloat162float(hy0), y1 - __bfloat162float(hy1));
    }
}

// ---------------------------------------------------------------------------
extern "C" void kernel_launch(void* const* d_in, const int* in_sizes, int n_in,
                              void* d_out, int out_size)
{
    const float* hs = (const float*)d_in[0];
    const float* Wq = (const float*)d_in[1];
    const float* Wk = (const float*)d_in[2];
    const float* Wv = (const float*)d_in[3];
    const float* Wo = (const float*)d_in[4];
    const float* bo = (const float*)d_in[5];
    float* out = (float*)d_out;

    __nv_bfloat16 *ah, *al, *wch, *wcl, *woh, *wol;
    __nv_bfloat16 *qh, *ql, *kh, *kl, *vh, *vl;
    float2* rope;
    cudaGetSymbolAddress((void**)&ah,  g_ah);
    cudaGetSymbolAddress((void**)&al,  g_al);
    cudaGetSymbolAddress((void**)&wch, g_wch);
    cudaGetSymbolAddress((void**)&wcl, g_wcl);
    cudaGetSymbolAddress((void**)&woh, g_woh);
    cudaGetSymbolAddress((void**)&wol, g_wol);
    cudaGetSymbolAddress((void**)&qh,  g_qh);
    cudaGetSymbolAddress((void**)&ql,  g_ql);
    cudaGetSymbolAddress((void**)&kh,  g_kh);
    cudaGetSymbolAddress((void**)&kl,  g_kl);
    cudaGetSymbolAddress((void**)&vh,  g_vh);
    cudaGetSymbolAddress((void**)&vl,  g_vl);
    cudaGetSymbolAddress((void**)&rope, g_rope);

    const int gemm_smem = 3 * 32768;   // 96 KB, 3-stage ring
    cudaFuncSetAttribute(gemm_mma, cudaFuncAttributeMaxDynamicSharedMemorySize, gemm_smem);
    const int attn_smem = 32768 + 2 * 32768;   // 96 KB -> 2 CTAs/SM
    cudaFuncSetAttribute(attn_mma, cudaFuncAttributeMaxDynamicSharedMemorySize, attn_smem);

    // launch 1: split hs
    {
        int n4 = MROWS * DM / 4;
        split_kernel<<<(n4 + 255) / 256, 256>>>(hs, ah, al, n4);
    }
    // launch 2: all weight transposes + rope table
    prep_weights<<<dim3(161, 64), dim3(32, 8)>>>(Wq, Wk, Wv, Wo, wch, wcl, woh, wol, rope);

    // launch 3: combined QKV projection (rope + split epilogue)
    gemm_mma<<<dim3(NQKV / 128, MROWS / 128), 256, gemm_smem>>>(
        ah, al, wch, wcl, nullptr, qh, ql, kh, kl, vh, vl, rope, NQKV, 3, nullptr);

    // launch 4: attention (PROFILED SLOT) - writes split ctx into ah/al
    attn_mma<<<dim3(16 * 64), 256, attn_smem>>>(
        qh, ql, kh, kl, vh, vl, ah, al);

    // launch 5: output projection + bias
    gemm_mma<<<dim3(DM / 128, MROWS / 128), 256, gemm_smem>>>(
        ah, al, woh, wol, out, nullptr, nullptr, nullptr, nullptr, nullptr, nullptr,
        nullptr, DM, 0, bo);
}

// round 10
// speedup vs baseline: 4.2095x; 1.0274x over previous
#include <cuda_runtime.h>
#include <cuda_bf16.h>
#include <math.h>
#include <stdint.h>

#define DM    2048
#define SEQ   2048
#define BATCH 2
#define NH    32
#define NG    8
#define DH    64
#define MROWS (BATCH*SEQ)   // 4096
#define NQKV  3072          // combined projection width

// ---------------- scratch (__device__ globals; no allocs allowed) ----------
__device__ __nv_bfloat16 g_ah[(size_t)MROWS*DM];   // A split (hs, later ctx)
__device__ __nv_bfloat16 g_al[(size_t)MROWS*DM];
__device__ __nv_bfloat16 g_wch[(size_t)NQKV*DM], g_wcl[(size_t)NQKV*DM];  // Wqkv^T split
__device__ __nv_bfloat16 g_woh[(size_t)DM*DM],   g_wol[(size_t)DM*DM];
__device__ __nv_bfloat16 g_qh[(size_t)BATCH*NH*SEQ*DH], g_ql[(size_t)BATCH*NH*SEQ*DH];
__device__ __nv_bfloat16 g_kh[(size_t)BATCH*NG*SEQ*DH], g_kl[(size_t)BATCH*NG*SEQ*DH];
__device__ __nv_bfloat16 g_vh[(size_t)BATCH*NG*SEQ*DH], g_vl[(size_t)BATCH*NG*SEQ*DH];
__device__ float2 g_rope[SEQ * 32];

// ---------------- helpers ---------------------------------------------------
__device__ __forceinline__ uint32_t smem_u32(const void* p) {
    uint32_t a;
    asm("{ .reg .u64 t; cvta.to.shared.u64 t, %1; cvt.u32.u64 %0, t; }" : "=r"(a) : "l"(p));
    return a;
}
__device__ __forceinline__ void ldsm4(uint32_t* r, uint32_t addr) {
    asm volatile("ldmatrix.sync.aligned.m8n8.x4.shared.b16 {%0,%1,%2,%3}, [%4];"
                 : "=r"(r[0]), "=r"(r[1]), "=r"(r[2]), "=r"(r[3]) : "r"(addr));
}
__device__ __forceinline__ void ldsm4t(uint32_t* r, uint32_t addr) {
    asm volatile("ldmatrix.sync.aligned.m8n8.x4.trans.shared.b16 {%0,%1,%2,%3}, [%4];"
                 : "=r"(r[0]), "=r"(r[1]), "=r"(r[2]), "=r"(r[3]) : "r"(addr));
}
__device__ __forceinline__ void mma16816(float* c, const uint32_t* a, const uint32_t* b) {
    asm volatile("mma.sync.aligned.m16n8k16.row.col.f32.bf16.bf16.f32 "
                 "{%0,%1,%2,%3}, {%4,%5,%6,%7}, {%8,%9}, {%0,%1,%2,%3};"
                 : "+f"(c[0]), "+f"(c[1]), "+f"(c[2]), "+f"(c[3])
                 : "r"(a[0]), "r"(a[1]), "r"(a[2]), "r"(a[3]), "r"(b[0]), "r"(b[1]));
}
#define CP_ASYNC16(s, g) \
    asm volatile("cp.async.cg.shared.global [%0], [%1], 16;" :: "r"(s), "l"(g))
#define CP_COMMIT() asm volatile("cp.async.commit_group;" ::: "memory")
#define CP_WAIT1()  asm volatile("cp.async.wait_group 1;" ::: "memory")

__device__ __forceinline__ uint32_t packbf(float lo, float hi) {
    __nv_bfloat162 t = __floats2bfloat162_rn(lo, hi);
    return *reinterpret_cast<uint32_t*>(&t);
}
__device__ __forceinline__ float ex2f(float x) {
    float r;
    asm("ex2.approx.ftz.f32 %0, %1;" : "=f"(r) : "f"(x));
    return r;
}
// Truncation-based bf16 hi/lo split of a pair (for P fragments).
// hi = high 16 bits of each fp32 (1 PRMT); lo absorbs the truncation residual.
__device__ __forceinline__ void split_pair(float p0, float p1,
                                           uint32_t& hi, uint32_t& lo) {
    uint32_t b0 = __float_as_uint(p0), b1 = __float_as_uint(p1);
    asm("prmt.b32 %0, %1, %2, 0x7632;" : "=r"(hi) : "r"(b0), "r"(b1));
    float h0 = __uint_as_float(b0 & 0xffff0000u);
    float h1 = __uint_as_float(b1 & 0xffff0000u);
    lo = packbf(p0 - h0, p1 - h1);
}

// p = exp(30*tanh(s/30) - 30) with log2e folded into the Taylor constants:
// p = ex2( s * (L + s2*c1 + s2^2*c2) - 30L ), identical poly to prior rounds.
__device__ __forceinline__ float softmax_p(float sv) {
    const float s2 = sv * sv;
    const float P = fmaf(s2, fmaf(s2, 2.3748002e-7f, -5.3433150e-4f), 1.44269504f);
    return ex2f(fmaf(sv, P, -43.2808512f));
}

// ---------------------------------------------------------------------------
// bf16x3 HMMA GEMM: C[M,Ntot] = A @ B^T.  128x128 CTA tile, BK=32, 256 thr.
// 3-stage cp.async ring, fill-ahead-2 + wait_group 1, one syncthreads/iter.
// 2 CTAs/SM. mode 0: fp32 row-major + bias.  mode 3: combined QKV epilogue.
// ---------------------------------------------------------------------------
__global__ __launch_bounds__(256, 2)
void gemm_mma(const __nv_bfloat16* __restrict__ Ah, const __nv_bfloat16* __restrict__ Al,
              const __nv_bfloat16* __restrict__ Bh, const __nv_bfloat16* __restrict__ Bl,
              float* __restrict__ Cf,
              __nv_bfloat16* __restrict__ Qh, __nv_bfloat16* __restrict__ Ql,
              __nv_bfloat16* __restrict__ Kh, __nv_bfloat16* __restrict__ Kl,
              __nv_bfloat16* __restrict__ Vh, __nv_bfloat16* __restrict__ Vl,
              const float2* __restrict__ rope,
              int Ntot, int mode, const float* __restrict__ bias)
{
    extern __shared__ __align__(128) char smc[];
    const uint32_t sbase = smem_u32(smc);
    const int tid = threadIdx.x, lane = tid & 31, wid = tid >> 5;
    const int wm = wid >> 2, wn = wid & 3;
    const int n0 = blockIdx.x << 7, m0 = blockIdx.y << 7;

    const int fr = tid >> 2;
    const int fc = tid & 3;

    uint32_t offA[4][2], offB[2][2];
#pragma unroll
    for (int mf = 0; mf < 4; mf++)
#pragma unroll
        for (int ks = 0; ks < 2; ks++) {
            int row = wm * 64 + mf * 16 + (lane & 7) + ((lane >> 3) & 1) * 8;
            int ch  = ks * 2 + (lane >> 4);
            offA[mf][ks] = row * 64 + ((ch ^ ((row >> 1) & 3)) << 4);
        }
#pragma unroll
    for (int np = 0; np < 2; np++)
#pragma unroll
        for (int ks = 0; ks < 2; ks++) {
            int row = wn * 32 + np * 16 + (lane & 7) + (lane >> 4) * 8;
            int ch  = ks * 2 + ((lane >> 3) & 1);
            offB[np][ks] = row * 64 + ((ch ^ ((row >> 1) & 3)) << 4);
        }

    float acc[4][4][4];
#pragma unroll
    for (int i = 0; i < 4; i++)
#pragma unroll
        for (int j = 0; j < 4; j++)
#pragma unroll
            for (int l = 0; l < 4; l++) acc[i][j][l] = 0.f;

    auto fill = [&](int kc, int stage) {
        const uint32_t sb = sbase + stage * 32768;
#pragma unroll
        for (int i = 0; i < 2; i++) {
            const int r = fr + i * 64;
            const uint32_t so = r * 64 + ((fc ^ ((r >> 1) & 3)) << 4);
            const size_t gA = (size_t)(m0 + r) * DM + kc * 32 + fc * 8;
            const size_t gB = (size_t)(n0 + r) * DM + kc * 32 + fc * 8;
            CP_ASYNC16(sb +         so, Ah + gA);
            CP_ASYNC16(sb +  8192 + so, Al + gA);
            CP_ASYNC16(sb + 16384 + so, Bh + gB);
            CP_ASYNC16(sb + 24576 + so, Bl + gB);
        }
        CP_COMMIT();
    };

    fill(0, 0);
    fill(1, 1);

    const int NKC = DM / 32;
    int rd = 0, wr = 2;
    for (int kc = 0; kc < NKC; kc++) {
        CP_WAIT1();
        __syncthreads();
        const uint32_t sA = sbase + rd * 32768;
#pragma unroll
        for (int ks = 0; ks < 2; ks++) {
            uint32_t bh[2][4], bl[2][4];
#pragma unroll
            for (int np = 0; np < 2; np++) {
                ldsm4(bh[np], sA + 16384 + offB[np][ks]);
                ldsm4(bl[np], sA + 24576 + offB[np][ks]);
            }
#pragma unroll
            for (int mf = 0; mf < 4; mf++) {
                uint32_t ah[4], al[4];
                ldsm4(ah, sA +        offA[mf][ks]);
                ldsm4(al, sA + 8192 + offA[mf][ks]);
#pragma unroll
                for (int nf = 0; nf < 4; nf++) {
                    const uint32_t* bhp = &bh[nf >> 1][(nf & 1) * 2];
                    const uint32_t* blp = &bl[nf >> 1][(nf & 1) * 2];
                    mma16816(acc[mf][nf], ah, bhp);
                    mma16816(acc[mf][nf], ah, blp);
                    mma16816(acc[mf][nf], al, bhp);
                }
            }
        }
        if (kc + 2 < NKC) fill(kc + 2, wr);
        else CP_COMMIT();
        rd = (rd == 2) ? 0 : rd + 1;
        wr = (wr == 2) ? 0 : wr + 1;
    }

    const int g4 = lane >> 2, t4 = lane & 3;
#pragma unroll
    for (int mf = 0; mf < 4; mf++) {
#pragma unroll
        for (int nf = 0; nf < 4; nf++) {
            const int row = m0 + wm * 64 + mf * 16 + g4;
            const int col = n0 + wn * 32 + nf * 8 + t4 * 2;
            float2 v0 = make_float2(acc[mf][nf][0], acc[mf][nf][1]);
            float2 v1 = make_float2(acc[mf][nf][2], acc[mf][nf][3]);
            if (mode == 0) {
                const float b0 = bias[col], b1 = bias[col + 1];
                v0.x += b0; v0.y += b1; v1.x += b0; v1.y += b1;
                *reinterpret_cast<float2*>(Cf + (size_t)row * Ntot + col)       = v0;
                *reinterpret_cast<float2*>(Cf + (size_t)(row + 8) * Ntot + col) = v1;
            } else {
                __nv_bfloat16 *Oh, *Ol;
                int hh, hcount;
                bool dorope;
                if (col < 2048)      { Oh = Qh; Ol = Ql; hh = col >> 6;          hcount = NH; dorope = true; }
                else if (col < 2560) { Oh = Kh; Ol = Kl; hh = (col - 2048) >> 6; hcount = NG; dorope = true; }
                else                 { Oh = Vh; Ol = Vl; hh = (col - 2560) >> 6; hcount = NG; dorope = false; }
                const int pair = (col & 63) >> 1;
                float2 vv[2] = {v0, v1};
#pragma unroll
                for (int t = 0; t < 2; t++) {
                    const int r = row + t * 8;
                    const int bb = r >> 11, s = r & (SEQ - 1);
                    float x0 = vv[t].x, x1 = vv[t].y;
                    if (dorope) {
                        float2 cs = rope[s * 32 + pair];
                        float r0 = x0 * cs.x - x1 * cs.y;
                        x1 = x1 * cs.x + x0 * cs.y;
                        x0 = r0;
                    }
                    __nv_bfloat16 h0 = __float2bfloat16_rn(x0);
                    __nv_bfloat16 h1 = __float2bfloat16_rn(x1);
                    float l0f = x0 - __bfloat162float(h0);
                    float l1f = x1 - __bfloat162float(h1);
                    size_t o32 = ((size_t)(bb * hcount + hh) * SEQ + s) * 32 + pair;
                    reinterpret_cast<uint32_t*>(Oh)[o32] =
                        packbf(__bfloat162float(h0), __bfloat162float(h1));
                    reinterpret_cast<uint32_t*>(Ol)[o32] = packbf(l0f, l1f);
                }
            }
        }
    }
}

// ---------------------------------------------------------------------------
// fp32 -> bf16 hi/lo split (hidden states)
// ---------------------------------------------------------------------------
__global__ void split_kernel(const float* __restrict__ x,
                             __nv_bfloat16* __restrict__ hi,
                             __nv_bfloat16* __restrict__ lo, int n4)
{
    int i = blockIdx.x * blockDim.x + threadIdx.x;
    if (i >= n4) return;
    float4 v = reinterpret_cast<const float4*>(x)[i];
    float f[4] = {v.x, v.y, v.z, v.w};
    __nv_bfloat16 h[4], l[4];
#pragma unroll
    for (int j = 0; j < 4; j++) {
        h[j] = __float2bfloat16_rn(f[j]);
        l[j] = __float2bfloat16_rn(f[j] - __bfloat162float(h[j]));
    }
    reinterpret_cast<uint2*>(hi)[i] = *reinterpret_cast<uint2*>(h);
    reinterpret_cast<uint2*>(lo)[i] = *reinterpret_cast<uint2*>(l);
}

// ---------------------------------------------------------------------------
// All weight transposes + rope table in ONE launch.
// ---------------------------------------------------------------------------
__global__ void prep_weights(const float* __restrict__ Wq, const float* __restrict__ Wk,
                             const float* __restrict__ Wv, const float* __restrict__ Wo,
                             __nv_bfloat16* __restrict__ Tch, __nv_bfloat16* __restrict__ Tcl,
                             __nv_bfloat16* __restrict__ Toh, __nv_bfloat16* __restrict__ Tol,
                             float2* __restrict__ rope)
{
    int bx = blockIdx.x;
    const int tid = threadIdx.y * 32 + threadIdx.x;
    if (bx == 160) {
        int idx = (blockIdx.y * 256 + tid) * 4;
#pragma unroll
        for (int j = 0; j < 4; j++) {
            int id = idx + j;
            int s = id >> 5, pair = id & 31;
            float inv = powf(10000.f, -(float)(2 * pair) * (1.f / 64.f));
            float sn, c;
            sincosf((float)s * inv, &sn, &c);
            rope[id] = make_float2(c, sn);
        }
        return;
    }
    __shared__ float t[32][33];
    const float* W;
    __nv_bfloat16 *Th, *Tl;
    int N, rowoff;
    if (bx < 64)       { W = Wq; N = 2048; rowoff = 0;    Th = Tch; Tl = Tcl; }
    else if (bx < 80)  { W = Wk; N = 512;  rowoff = 2048; Th = Tch; Tl = Tcl; bx -= 64; }
    else if (bx < 96)  { W = Wv; N = 512;  rowoff = 2560; Th = Tch; Tl = Tcl; bx -= 80; }
    else               { W = Wo; N = 2048; rowoff = 0;    Th = Toh; Tl = Tol; bx -= 96; }
    const int n0 = bx * 32, k0 = blockIdx.y * 32;
    const int tx = threadIdx.x, ty = threadIdx.y;
#pragma unroll
    for (int i = 0; i < 4; i++)
        t[ty + 8 * i][tx] = W[(size_t)(k0 + ty + 8 * i) * N + n0 + tx];
    __syncthreads();
#pragma unroll
    for (int i = 0; i < 4; i++) {
        float v = t[tx][ty + 8 * i];
        __nv_bfloat16 h = __float2bfloat16_rn(v);
        __nv_bfloat16 l = __float2bfloat16_rn(v - __bfloat162float(h));
        size_t o = (size_t)(rowoff + n0 + ty + 8 * i) * DM + k0 + tx;
        Th[o] = h; Tl[o] = l;
    }
}

// ---------------------------------------------------------------------------
// MMA flash attention, 64-row KV tiles, 2 CTAs/SM (96KB smem, <=128 regs).
// Lean softmax (5 slots/elem) + truncation P-split (PRMT).
// ---------------------------------------------------------------------------
__global__ __launch_bounds__(256, 2)
void attn_mma(const __nv_bfloat16* __restrict__ Qh, const __nv_bfloat16* __restrict__ Ql,
              const __nv_bfloat16* __restrict__ Kh, const __nv_bfloat16* __restrict__ Kl,
              const __nv_bfloat16* __restrict__ Vh, const __nv_bfloat16* __restrict__ Vl,
              __nv_bfloat16* __restrict__ Ch, __nv_bfloat16* __restrict__ Cl)
{
    extern __shared__ __align__(128) char smc[];
    const uint32_t sb = smem_u32(smc);
    const int tid = threadIdx.x, lane = tid & 31, wid = tid >> 5;
    const int bid = blockIdx.x;
    const int qt  = (SEQ / 128 - 1) - (bid >> 6);
    const int sub = bid & 63;
    const int h = sub >> 1, b = sub & 1;
    const int g = h >> 2;
    const int q0 = qt << 7;
    const int wrow = wid * 16;

    const size_t qbase = ((size_t)(b * NH + h) * SEQ + q0) * DH;
    const size_t kbase = ((size_t)(b * NG + g) * SEQ) * DH;

    constexpr uint32_t SQH = 0, SQL = 16384, SST = 32768, STAGE = 32768;

    {
#pragma unroll
        for (int i = 0; i < 4; i++) {
            int idx = tid + (i << 8);
            int r = idx >> 3, ch = idx & 7;
            uint32_t so = r * 128 + ((ch ^ (r & 7)) << 4);
            CP_ASYNC16(sb + SQH + so, Qh + qbase + r * 64 + ch * 8);
            CP_ASYNC16(sb + SQL + so, Ql + qbase + r * 64 + ch * 8);
        }
        CP_COMMIT();
    }
    auto fillkv = [&](int kt, int st) {
        const uint32_t s0 = sb + SST + st * STAGE;
        const size_t kb = kbase + (size_t)kt * 64 * 64;
#pragma unroll
        for (int i = 0; i < 2; i++) {
            int idx = tid + (i << 8);
            int r = idx >> 3, ch = idx & 7;
            uint32_t so = r * 128 + ((ch ^ (r & 7)) << 4);
            size_t go = kb + r * 64 + ch * 8;
            CP_ASYNC16(s0 +         so, Kh + go);
            CP_ASYNC16(s0 +  8192 + so, Kl + go);
            CP_ASYNC16(s0 + 16384 + so, Vh + go);
            CP_ASYNC16(s0 + 24576 + so, Vl + go);
        }
        CP_COMMIT();
    };
    const int nkt = (qt + 1) * 2;
    fillkv(0, 0);
    fillkv(1, 1);

    uint32_t qoff[4];
    {
        const int row = wrow + (lane & 7) + ((lane >> 3) & 1) * 8;
        const int chb = lane >> 4;
#pragma unroll
        for (int ks = 0; ks < 4; ks++)
            qoff[ks] = row * 128 + (((ks * 2 + chb) ^ (row & 7)) << 4);
    }

    float oac[8][4];
#pragma unroll
    for (int i = 0; i < 8; i++)
#pragma unroll
        for (int j = 0; j < 4; j++) oac[i][j] = 0.f;
    float ls0 = 0.f, ls1 = 0.f;
    const float slope8 = exp2f(-(float)(h + 1) * 0.25f) * 0.125f;
    const int qr = q0 + wrow + (lane >> 2);

    const int klrow = (lane & 7) + ((lane >> 4) << 3);
    const int klchb = (lane >> 3) & 1;
    const int vlrow = (lane & 7) + (((lane >> 3) & 1) << 3);
    const int vlchb = lane >> 4;

    for (int kt = 0; kt < nkt; kt++) {
        const int st = kt & 1;
        const uint32_t sK = sb + SST + st * STAGE;
        CP_WAIT1();
        __syncthreads();

        if ((kt << 6) <= q0 + wrow + 15) {
            float sc[8][4];
#pragma unroll
            for (int i = 0; i < 8; i++)
#pragma unroll
                for (int j = 0; j < 4; j++) sc[i][j] = 0.f;

#pragma unroll
            for (int ks = 0; ks < 4; ks++) {
                uint32_t qh_t[4], ql_t[4];
                ldsm4(qh_t, sb + SQH + qoff[ks]);
                ldsm4(ql_t, sb + SQL + qoff[ks]);
#pragma unroll
                for (int ng = 0; ng < 4; ng++) {
                    const int row = ng * 16 + klrow;
                    const uint32_t so = row * 128 + (((ks * 2 + klchb) ^ (row & 7)) << 4);
                    uint32_t kfh[4], kfl[4];
                    ldsm4(kfh, sK + so);
                    ldsm4(kfl, sK + 8192 + so);
                    mma16816(sc[ng * 2],     qh_t, kfh);
                    mma16816(sc[ng * 2],     qh_t, kfl);
                    mma16816(sc[ng * 2],     ql_t, kfh);
                    mma16816(sc[ng * 2 + 1], qh_t, kfh + 2);
                    mma16816(sc[ng * 2 + 1], qh_t, kfl + 2);
                    mma16816(sc[ng * 2 + 1], ql_t, kfh + 2);
                }
            }

            const int kcol0 = (kt << 6) + (lane & 3) * 2;
            const bool tail = ((kt << 6) + 63 > q0 + wrow);
#pragma unroll
            for (int nf = 0; nf < 8; nf++) {
                const int kc = kcol0 + nf * 8;
                const float bias0 = slope8 * (float)(kc - qr);
                float p0 = softmax_p(fmaf(sc[nf][0], 0.125f, bias0));
                float p1 = softmax_p(fmaf(sc[nf][1], 0.125f, bias0 + slope8));
                float p2 = softmax_p(fmaf(sc[nf][2], 0.125f, bias0 - 8.f * slope8));
                float p3 = softmax_p(fmaf(sc[nf][3], 0.125f, bias0 - 7.f * slope8));
                if (tail) {
                    if (kc > qr)         p0 = 0.f;
                    if (kc + 1 > qr)     p1 = 0.f;
                    if (kc > qr + 8)     p2 = 0.f;
                    if (kc + 1 > qr + 8) p3 = 0.f;
                }
                ls0 += p0 + p1;
                ls1 += p2 + p3;
                sc[nf][0] = p0; sc[nf][1] = p1; sc[nf][2] = p2; sc[nf][3] = p3;
            }

#pragma unroll
            for (int j = 0; j < 4; j++) {
                uint32_t pah[4], pal[4];
#pragma unroll
                for (int u = 0; u < 2; u++) {
                    const float* p = sc[2 * j + u];
                    split_pair(p[0], p[1], pah[2 * u],     pal[2 * u]);
                    split_pair(p[2], p[3], pah[2 * u + 1], pal[2 * u + 1]);
                }
#pragma unroll
                for (int gD = 0; gD < 4; gD++) {
                    const int row = j * 16 + vlrow;
                    const uint32_t so = row * 128 + (((gD * 2 + vlchb) ^ (row & 7)) << 4);
                    uint32_t vfh[4], vfl[4];
                    ldsm4t(vfh, sK + 16384 + so);
                    ldsm4t(vfl, sK + 24576 + so);
                    mma16816(oac[gD * 2],     pah, vfh);
                    mma16816(oac[gD * 2],     pah, vfl);
                    mma16816(oac[gD * 2],     pal, vfh);
                    mma16816(oac[gD * 2 + 1], pah, vfh + 2);
                    mma16816(oac[gD * 2 + 1], pah, vfl + 2);
                    mma16816(oac[gD * 2 + 1], pal, vfh + 2);
                }
            }
        }
        __syncthreads();
        if (kt + 2 < nkt) fillkv(kt + 2, st); else CP_COMMIT();
    }

    ls0 += __shfl_xor_sync(0xffffffffu, ls0, 1);
    ls0 += __shfl_xor_sync(0xffffffffu, ls0, 2);
    ls1 += __shfl_xor_sync(0xffffffffu, ls1, 1);
    ls1 += __shfl_xor_sync(0xffffffffu, ls1, 2);
    const float inv0 = 1.f / ls0, inv1 = 1.f / ls1;

    const size_t rowM0 = (size_t)b * SEQ + qr;
#pragma unroll
    for (int nf = 0; nf < 8; nf++) {
        const int col = h * 64 + nf * 8 + (lane & 3) * 2;
        float x0 = oac[nf][0] * inv0, x1 = oac[nf][1] * inv0;
        float y0 = oac[nf][2] * inv1, y1 = oac[nf][3] * inv1;
        __nv_bfloat16 hx0 = __float2bfloat16_rn(x0), hx1 = __float2bfloat16_rn(x1);
        __nv_bfloat16 hy0 = __float2bfloat16_rn(y0), hy1 = __float2bfloat16_rn(y1);
        size_t o0 = (rowM0 * DM + col) >> 1;
        size_t o1 = ((rowM0 + 8) * DM + col) >> 1;
        reinterpret_cast<uint32_t*>(Ch)[o0] = packbf(__bfloat162float(hx0), __bfloat162float(hx1));
        reinterpret_cast<uint32_t*>(Cl)[o0] = packbf(x0 - __bfloat162float(hx0), x1 - __bfloat162float(hx1));
        reinterpret_cast<uint32_t*>(Ch)[o1] = packbf(__bfloat162float(hy0), __bfloat162float(hy1));
        reinterpret_cast<uint32_t*>(Cl)[o1] = packbf(y0 - __bfloat162float(hy0), y1 - __bfloat162float(hy1));
    }
}

// ---------------------------------------------------------------------------
extern "C" void kernel_launch(void* const* d_in, const int* in_sizes, int n_in,
                              void* d_out, int out_size)
{
    const float* hs = (const float*)d_in[0];
    const float* Wq = (const float*)d_in[1];
    const float* Wk = (const float*)d_in[2];
    const float* Wv = (const float*)d_in[3];
    const float* Wo = (const float*)d_in[4];
    const float* bo = (const float*)d_in[5];
    float* out = (float*)d_out;

    __nv_bfloat16 *ah, *al, *wch, *wcl, *woh, *wol;
    __nv_bfloat16 *qh, *ql, *kh, *kl, *vh, *vl;
    float2* rope;
    cudaGetSymbolAddress((void**)&ah,  g_ah);
    cudaGetSymbolAddress((void**)&al,  g_al);
    cudaGetSymbolAddress((void**)&wch, g_wch);
    cudaGetSymbolAddress((void**)&wcl, g_wcl);
    cudaGetSymbolAddress((void**)&woh, g_woh);
    cudaGetSymbolAddress((void**)&wol, g_wol);
    cudaGetSymbolAddress((void**)&qh,  g_qh);
    cudaGetSymbolAddress((void**)&ql,  g_ql);
    cudaGetSymbolAddress((void**)&kh,  g_kh);
    cudaGetSymbolAddress((void**)&kl,  g_kl);
    cudaGetSymbolAddress((void**)&vh,  g_vh);
    cudaGetSymbolAddress((void**)&vl,  g_vl);
    cudaGetSymbolAddress((void**)&rope, g_rope);

    const int gemm_smem = 3 * 32768;   // 96 KB, 3-stage ring
    cudaFuncSetAttribute(gemm_mma, cudaFuncAttributeMaxDynamicSharedMemorySize, gemm_smem);
    const int attn_smem = 32768 + 2 * 32768;   // 96 KB -> 2 CTAs/SM
    cudaFuncSetAttribute(attn_mma, cudaFuncAttributeMaxDynamicSharedMemorySize, attn_smem);

    // launch 1: split hs
    {
        int n4 = MROWS * DM / 4;
        split_kernel<<<(n4 + 255) / 256, 256>>>(hs, ah, al, n4);
    }
    // launch 2: all weight transposes + rope table
    prep_weights<<<dim3(161, 64), dim3(32, 8)>>>(Wq, Wk, Wv, Wo, wch, wcl, woh, wol, rope);

    // launch 3: combined QKV projection (rope + split epilogue)
    gemm_mma<<<dim3(NQKV / 128, MROWS / 128), 256, gemm_smem>>>(
        ah, al, wch, wcl, nullptr, qh, ql, kh, kl, vh, vl, rope, NQKV, 3, nullptr);

    // launch 4: attention (PROFILED SLOT)
    attn_mma<<<dim3(16 * 64), 256, attn_smem>>>(
        qh, ql, kh, kl, vh, vl, ah, al);

    // launch 5: output projection + bias
    gemm_mma<<<dim3(DM / 128, MROWS / 128), 256, gemm_smem>>>(
        ah, al, woh, wol, out, nullptr, nullptr, nullptr, nullptr, nullptr, nullptr,
        nullptr, DM, 0, bo);
}

// round 11
// speedup vs baseline: 4.4396x; 1.0547x over previous
#include <cuda_runtime.h>
#include <cuda_bf16.h>
#include <math.h>
#include <stdint.h>

#define DM    2048
#define SEQ   2048
#define BATCH 2
#define NH    32
#define NG    8
#define DH    64
#define MROWS (BATCH*SEQ)   // 4096
#define NQKV  3072          // combined projection width

// ---------------- scratch (__device__ globals; no allocs allowed) ----------
__device__ __nv_bfloat16 g_ah[(size_t)MROWS*DM];   // A split (hs, later ctx)
__device__ __nv_bfloat16 g_al[(size_t)MROWS*DM];
__device__ __nv_bfloat16 g_wch[(size_t)NQKV*DM], g_wcl[(size_t)NQKV*DM];
__device__ __nv_bfloat16 g_woh[(size_t)DM*DM],   g_wol[(size_t)DM*DM];
__device__ __nv_bfloat16 g_qh[(size_t)BATCH*NH*SEQ*DH], g_ql[(size_t)BATCH*NH*SEQ*DH];
__device__ __nv_bfloat16 g_kh[(size_t)BATCH*NG*SEQ*DH], g_kl[(size_t)BATCH*NG*SEQ*DH];
__device__ __nv_bfloat16 g_vh[(size_t)BATCH*NG*SEQ*DH], g_vl[(size_t)BATCH*NG*SEQ*DH];
__device__ float2 g_rope[SEQ * 32];
__device__ int g_flagM[32];   // per 128-row block: QKV N-tile arrivals (target 24)
__device__ int g_flagA[32];   // per 128-row block: attention head arrivals (target 32)

// ---------------- helpers ---------------------------------------------------
__device__ __forceinline__ uint32_t smem_u32(const void* p) {
    uint32_t a;
    asm("{ .reg .u64 t; cvta.to.shared.u64 t, %1; cvt.u32.u64 %0, t; }" : "=r"(a) : "l"(p));
    return a;
}
__device__ __forceinline__ void ldsm4(uint32_t* r, uint32_t addr) {
    asm volatile("ldmatrix.sync.aligned.m8n8.x4.shared.b16 {%0,%1,%2,%3}, [%4];"
                 : "=r"(r[0]), "=r"(r[1]), "=r"(r[2]), "=r"(r[3]) : "r"(addr));
}
__device__ __forceinline__ void ldsm4t(uint32_t* r, uint32_t addr) {
    asm volatile("ldmatrix.sync.aligned.m8n8.x4.trans.shared.b16 {%0,%1,%2,%3}, [%4];"
                 : "=r"(r[0]), "=r"(r[1]), "=r"(r[2]), "=r"(r[3]) : "r"(addr));
}
__device__ __forceinline__ void mma16816(float* c, const uint32_t* a, const uint32_t* b) {
    asm volatile("mma.sync.aligned.m16n8k16.row.col.f32.bf16.bf16.f32 "
                 "{%0,%1,%2,%3}, {%4,%5,%6,%7}, {%8,%9}, {%0,%1,%2,%3};"
                 : "+f"(c[0]), "+f"(c[1]), "+f"(c[2]), "+f"(c[3])
                 : "r"(a[0]), "r"(a[1]), "r"(a[2]), "r"(a[3]), "r"(b[0]), "r"(b[1]));
}
#define CP_ASYNC16(s, g) \
    asm volatile("cp.async.cg.shared.global [%0], [%1], 16;" :: "r"(s), "l"(g))
#define CP_COMMIT() asm volatile("cp.async.commit_group;" ::: "memory")
#define CP_WAIT1()  asm volatile("cp.async.wait_group 1;" ::: "memory")

__device__ __forceinline__ uint32_t packbf(float lo, float hi) {
    __nv_bfloat162 t = __floats2bfloat162_rn(lo, hi);
    return *reinterpret_cast<uint32_t*>(&t);
}
__device__ __forceinline__ float ex2f(float x) {
    float r;
    asm("ex2.approx.ftz.f32 %0, %1;" : "=f"(r) : "f"(x));
    return r;
}
__device__ __forceinline__ void split_pair(float p0, float p1,
                                           uint32_t& hi, uint32_t& lo) {
    uint32_t b0 = __float_as_uint(p0), b1 = __float_as_uint(p1);
    asm("prmt.b32 %0, %1, %2, 0x7632;" : "=r"(hi) : "r"(b0), "r"(b1));
    float h0 = __uint_as_float(b0 & 0xffff0000u);
    float h1 = __uint_as_float(b1 & 0xffff0000u);
    lo = packbf(p0 - h0, p1 - h1);
}
// p = exp(30*tanh(s/30) - 30) with log2e folded into Taylor constants.
__device__ __forceinline__ float softmax_p(float sv) {
    const float s2 = sv * sv;
    const float P = fmaf(s2, fmaf(s2, 2.3748002e-7f, -5.3433150e-4f), 1.44269504f);
    return ex2f(fmaf(sv, P, -43.2808512f));
}
// acquire spin: all threads poll; release side = threadfence + atomicAdd.
__device__ __forceinline__ void spin_ge(const int* f, int target) {
    const volatile int* vf = (const volatile int*)f;
    while (*vf < target) __nanosleep(128);
    __threadfence();
}

// ---------------------------------------------------------------------------
// bf16x3 HMMA GEMM tile (device fn): 128x128 CTA tile, BK=32, 256 thr,
// 3-stage cp.async ring (fill-ahead-2, wait_group 1, one sync/iter).
// mode 0: fp32 row-major + bias.  mode 3: combined QKV epilogue.
// ---------------------------------------------------------------------------
__device__ __forceinline__ void gemm_tile(
    const __nv_bfloat16* __restrict__ Ah, const __nv_bfloat16* __restrict__ Al,
    const __nv_bfloat16* __restrict__ Bh, const __nv_bfloat16* __restrict__ Bl,
    float* __restrict__ Cf,
    __nv_bfloat16* __restrict__ Qh, __nv_bfloat16* __restrict__ Ql,
    __nv_bfloat16* __restrict__ Kh, __nv_bfloat16* __restrict__ Kl,
    __nv_bfloat16* __restrict__ Vh, __nv_bfloat16* __restrict__ Vl,
    const float2* __restrict__ rope,
    int Ntot, int mode, const float* __restrict__ bias,
    int m0, int n0, char* smc)
{
    const uint32_t sbase = smem_u32(smc);
    const int tid = threadIdx.x, lane = tid & 31, wid = tid >> 5;
    const int wm = wid >> 2, wn = wid & 3;
    const int fr = tid >> 2;
    const int fc = tid & 3;

    uint32_t offA[4][2], offB[2][2];
#pragma unroll
    for (int mf = 0; mf < 4; mf++)
#pragma unroll
        for (int ks = 0; ks < 2; ks++) {
            int row = wm * 64 + mf * 16 + (lane & 7) + ((lane >> 3) & 1) * 8;
            int ch  = ks * 2 + (lane >> 4);
            offA[mf][ks] = row * 64 + ((ch ^ ((row >> 1) & 3)) << 4);
        }
#pragma unroll
    for (int np = 0; np < 2; np++)
#pragma unroll
        for (int ks = 0; ks < 2; ks++) {
            int row = wn * 32 + np * 16 + (lane & 7) + (lane >> 4) * 8;
            int ch  = ks * 2 + ((lane >> 3) & 1);
            offB[np][ks] = row * 64 + ((ch ^ ((row >> 1) & 3)) << 4);
        }

    float acc[4][4][4];
#pragma unroll
    for (int i = 0; i < 4; i++)
#pragma unroll
        for (int j = 0; j < 4; j++)
#pragma unroll
            for (int l = 0; l < 4; l++) acc[i][j][l] = 0.f;

    auto fill = [&](int kc, int stage) {
        const uint32_t sb = sbase + stage * 32768;
#pragma unroll
        for (int i = 0; i < 2; i++) {
            const int r = fr + i * 64;
            const uint32_t so = r * 64 + ((fc ^ ((r >> 1) & 3)) << 4);
            const size_t gA = (size_t)(m0 + r) * DM + kc * 32 + fc * 8;
            const size_t gB = (size_t)(n0 + r) * DM + kc * 32 + fc * 8;
            CP_ASYNC16(sb +         so, Ah + gA);
            CP_ASYNC16(sb +  8192 + so, Al + gA);
            CP_ASYNC16(sb + 16384 + so, Bh + gB);
            CP_ASYNC16(sb + 24576 + so, Bl + gB);
        }
        CP_COMMIT();
    };

    fill(0, 0);
    fill(1, 1);

    const int NKC = DM / 32;
    int rd = 0, wr = 2;
    for (int kc = 0; kc < NKC; kc++) {
        CP_WAIT1();
        __syncthreads();
        const uint32_t sA = sbase + rd * 32768;
#pragma unroll
        for (int ks = 0; ks < 2; ks++) {
            uint32_t bh[2][4], bl[2][4];
#pragma unroll
            for (int np = 0; np < 2; np++) {
                ldsm4(bh[np], sA + 16384 + offB[np][ks]);
                ldsm4(bl[np], sA + 24576 + offB[np][ks]);
            }
#pragma unroll
            for (int mf = 0; mf < 4; mf++) {
                uint32_t ah[4], al[4];
                ldsm4(ah, sA +        offA[mf][ks]);
                ldsm4(al, sA + 8192 + offA[mf][ks]);
#pragma unroll
                for (int nf = 0; nf < 4; nf++) {
                    const uint32_t* bhp = &bh[nf >> 1][(nf & 1) * 2];
                    const uint32_t* blp = &bl[nf >> 1][(nf & 1) * 2];
                    mma16816(acc[mf][nf], ah, bhp);
                    mma16816(acc[mf][nf], ah, blp);
                    mma16816(acc[mf][nf], al, bhp);
                }
            }
        }
        if (kc + 2 < NKC) fill(kc + 2, wr);
        else CP_COMMIT();
        rd = (rd == 2) ? 0 : rd + 1;
        wr = (wr == 2) ? 0 : wr + 1;
    }

    const int g4 = lane >> 2, t4 = lane & 3;
#pragma unroll
    for (int mf = 0; mf < 4; mf++) {
#pragma unroll
        for (int nf = 0; nf < 4; nf++) {
            const int row = m0 + wm * 64 + mf * 16 + g4;
            const int col = n0 + wn * 32 + nf * 8 + t4 * 2;
            float2 v0 = make_float2(acc[mf][nf][0], acc[mf][nf][1]);
            float2 v1 = make_float2(acc[mf][nf][2], acc[mf][nf][3]);
            if (mode == 0) {
                const float b0 = bias[col], b1 = bias[col + 1];
                v0.x += b0; v0.y += b1; v1.x += b0; v1.y += b1;
                *reinterpret_cast<float2*>(Cf + (size_t)row * Ntot + col)       = v0;
                *reinterpret_cast<float2*>(Cf + (size_t)(row + 8) * Ntot + col) = v1;
            } else {
                __nv_bfloat16 *Oh, *Ol;
                int hh, hcount;
                bool dorope;
                if (col < 2048)      { Oh = Qh; Ol = Ql; hh = col >> 6;          hcount = NH; dorope = true; }
                else if (col < 2560) { Oh = Kh; Ol = Kl; hh = (col - 2048) >> 6; hcount = NG; dorope = true; }
                else                 { Oh = Vh; Ol = Vl; hh = (col - 2560) >> 6; hcount = NG; dorope = false; }
                const int pair = (col & 63) >> 1;
                float2 vv[2] = {v0, v1};
#pragma unroll
                for (int t = 0; t < 2; t++) {
                    const int r = row + t * 8;
                    const int bb = r >> 11, s = r & (SEQ - 1);
                    float x0 = vv[t].x, x1 = vv[t].y;
                    if (dorope) {
                        float2 cs = rope[s * 32 + pair];
                        float r0 = x0 * cs.x - x1 * cs.y;
                        x1 = x1 * cs.x + x0 * cs.y;
                        x0 = r0;
                    }
                    __nv_bfloat16 h0 = __float2bfloat16_rn(x0);
                    __nv_bfloat16 h1 = __float2bfloat16_rn(x1);
                    float l0f = x0 - __bfloat162float(h0);
                    float l1f = x1 - __bfloat162float(h1);
                    size_t o32 = ((size_t)(bb * hcount + hh) * SEQ + s) * 32 + pair;
                    reinterpret_cast<uint32_t*>(Oh)[o32] =
                        packbf(__bfloat162float(h0), __bfloat162float(h1));
                    reinterpret_cast<uint32_t*>(Ol)[o32] = packbf(l0f, l1f);
                }
            }
        }
    }
}

// ---------------------------------------------------------------------------
// Attention tile (device fn): 128 q-rows, 64-row KV tiles, kt DESCENDING
// (fixed-max softmax has no sequential state), spinning on producer flags.
// ---------------------------------------------------------------------------
__device__ __forceinline__ void attn_tile(
    int a,
    const __nv_bfloat16* __restrict__ Qh, const __nv_bfloat16* __restrict__ Ql,
    const __nv_bfloat16* __restrict__ Kh, const __nv_bfloat16* __restrict__ Kl,
    const __nv_bfloat16* __restrict__ Vh, const __nv_bfloat16* __restrict__ Vl,
    __nv_bfloat16* __restrict__ Ch, __nv_bfloat16* __restrict__ Cl, char* smc)
{
    const uint32_t sb = smem_u32(smc);
    const int tid = threadIdx.x, lane = tid & 31, wid = tid >> 5;
    const int qt  = (SEQ / 128 - 1) - (a >> 6);   // work-sorted, longest first
    const int sub = a & 63;
    const int h = sub >> 1, b = sub & 1;
    const int g = h >> 2;
    const int q0 = qt << 7;
    const int wrow = wid * 16;

    const size_t qbase = ((size_t)(b * NH + h) * SEQ + q0) * DH;
    const size_t kbase = ((size_t)(b * NG + g) * SEQ) * DH;

    constexpr uint32_t SQH = 0, SQL = 16384, SST = 32768, STAGE = 32768;

    // Q available?
    spin_ge(&g_flagM[(b << 4) + qt], 24);
    {
#pragma unroll
        for (int i = 0; i < 4; i++) {
            int idx = tid + (i << 8);
            int r = idx >> 3, ch = idx & 7;
            uint32_t so = r * 128 + ((ch ^ (r & 7)) << 4);
            CP_ASYNC16(sb + SQH + so, Qh + qbase + r * 64 + ch * 8);
            CP_ASYNC16(sb + SQL + so, Ql + qbase + r * 64 + ch * 8);
        }
        CP_COMMIT();
    }
    auto fillkv = [&](int kt, int st) {
        const uint32_t s0 = sb + SST + st * STAGE;
        const size_t kb = kbase + (size_t)kt * 64 * 64;
#pragma unroll
        for (int i = 0; i < 2; i++) {
            int idx = tid + (i << 8);
            int r = idx >> 3, ch = idx & 7;
            uint32_t so = r * 128 + ((ch ^ (r & 7)) << 4);
            size_t go = kb + r * 64 + ch * 8;
            CP_ASYNC16(s0 +         so, Kh + go);
            CP_ASYNC16(s0 +  8192 + so, Kl + go);
            CP_ASYNC16(s0 + 16384 + so, Vh + go);
            CP_ASYNC16(s0 + 24576 + so, Vl + go);
        }
        CP_COMMIT();
    };
    const int nkt = (qt + 1) * 2;
    const int hi = nkt - 1;
    spin_ge(&g_flagM[(b << 4) + (hi >> 1)], 24);
    fillkv(hi, hi & 1);
    if (hi >= 1) {
        spin_ge(&g_flagM[(b << 4) + ((hi - 1) >> 1)], 24);
        fillkv(hi - 1, (hi - 1) & 1);
    } else CP_COMMIT();

    uint32_t qoff[4];
    {
        const int row = wrow + (lane & 7) + ((lane >> 3) & 1) * 8;
        const int chb = lane >> 4;
#pragma unroll
        for (int ks = 0; ks < 4; ks++)
            qoff[ks] = row * 128 + (((ks * 2 + chb) ^ (row & 7)) << 4);
    }

    float oac[8][4];
#pragma unroll
    for (int i = 0; i < 8; i++)
#pragma unroll
        for (int j = 0; j < 4; j++) oac[i][j] = 0.f;
    float ls0 = 0.f, ls1 = 0.f;
    const float slope8 = exp2f(-(float)(h + 1) * 0.25f) * 0.125f;
    const int qr = q0 + wrow + (lane >> 2);

    const int klrow = (lane & 7) + ((lane >> 4) << 3);
    const int klchb = (lane >> 3) & 1;
    const int vlrow = (lane & 7) + (((lane >> 3) & 1) << 3);
    const int vlchb = lane >> 4;

    for (int kt = hi; kt >= 0; kt--) {
        const int st = kt & 1;
        const uint32_t sK = sb + SST + st * STAGE;
        CP_WAIT1();
        __syncthreads();

        if ((kt << 6) <= q0 + wrow + 15) {
            float sc[8][4];
#pragma unroll
            for (int i = 0; i < 8; i++)
#pragma unroll
                for (int j = 0; j < 4; j++) sc[i][j] = 0.f;

#pragma unroll
            for (int ks = 0; ks < 4; ks++) {
                uint32_t qh_t[4], ql_t[4];
                ldsm4(qh_t, sb + SQH + qoff[ks]);
                ldsm4(ql_t, sb + SQL + qoff[ks]);
#pragma unroll
                for (int ng = 0; ng < 4; ng++) {
                    const int row = ng * 16 + klrow;
                    const uint32_t so = row * 128 + (((ks * 2 + klchb) ^ (row & 7)) << 4);
                    uint32_t kfh[4], kfl[4];
                    ldsm4(kfh, sK + so);
                    ldsm4(kfl, sK + 8192 + so);
                    mma16816(sc[ng * 2],     qh_t, kfh);
                    mma16816(sc[ng * 2],     qh_t, kfl);
                    mma16816(sc[ng * 2],     ql_t, kfh);
                    mma16816(sc[ng * 2 + 1], qh_t, kfh + 2);
                    mma16816(sc[ng * 2 + 1], qh_t, kfl + 2);
                    mma16816(sc[ng * 2 + 1], ql_t, kfh + 2);
                }
            }

            const int kcol0 = (kt << 6) + (lane & 3) * 2;
            const bool tail = ((kt << 6) + 63 > q0 + wrow);
#pragma unroll
            for (int nf = 0; nf < 8; nf++) {
                const int kc = kcol0 + nf * 8;
                const float bias0 = slope8 * (float)(kc - qr);
                float p0 = softmax_p(fmaf(sc[nf][0], 0.125f, bias0));
                float p1 = softmax_p(fmaf(sc[nf][1], 0.125f, bias0 + slope8));
                float p2 = softmax_p(fmaf(sc[nf][2], 0.125f, bias0 - 8.f * slope8));
                float p3 = softmax_p(fmaf(sc[nf][3], 0.125f, bias0 - 7.f * slope8));
                if (tail) {
                    if (kc > qr)         p0 = 0.f;
                    if (kc + 1 > qr)     p1 = 0.f;
                    if (kc > qr + 8)     p2 = 0.f;
                    if (kc + 1 > qr + 8) p3 = 0.f;
                }
                ls0 += p0 + p1;
                ls1 += p2 + p3;
                sc[nf][0] = p0; sc[nf][1] = p1; sc[nf][2] = p2; sc[nf][3] = p3;
            }

#pragma unroll
            for (int j = 0; j < 4; j++) {
                uint32_t pah[4], pal[4];
#pragma unroll
                for (int u = 0; u < 2; u++) {
                    const float* p = sc[2 * j + u];
                    split_pair(p[0], p[1], pah[2 * u],     pal[2 * u]);
                    split_pair(p[2], p[3], pah[2 * u + 1], pal[2 * u + 1]);
                }
#pragma unroll
                for (int gD = 0; gD < 4; gD++) {
                    const int row = j * 16 + vlrow;
                    const uint32_t so = row * 128 + (((gD * 2 + vlchb) ^ (row & 7)) << 4);
                    uint32_t vfh[4], vfl[4];
                    ldsm4t(vfh, sK + 16384 + so);
                    ldsm4t(vfl, sK + 24576 + so);
                    mma16816(oac[gD * 2],     pah, vfh);
                    mma16816(oac[gD * 2],     pah, vfl);
                    mma16816(oac[gD * 2],     pal, vfh);
                    mma16816(oac[gD * 2 + 1], pah, vfh + 2);
                    mma16816(oac[gD * 2 + 1], pah, vfl + 2);
                    mma16816(oac[gD * 2 + 1], pal, vfh + 2);
                }
            }
        }
        __syncthreads();
        if (kt - 2 >= 0) {
            spin_ge(&g_flagM[(b << 4) + ((kt - 2) >> 1)], 24);
            fillkv(kt - 2, st);
        } else CP_COMMIT();
    }

    ls0 += __shfl_xor_sync(0xffffffffu, ls0, 1);
    ls0 += __shfl_xor_sync(0xffffffffu, ls0, 2);
    ls1 += __shfl_xor_sync(0xffffffffu, ls1, 1);
    ls1 += __shfl_xor_sync(0xffffffffu, ls1, 2);
    const float inv0 = 1.f / ls0, inv1 = 1.f / ls1;

    const size_t rowM0 = (size_t)b * SEQ + qr;
#pragma unroll
    for (int nf = 0; nf < 8; nf++) {
        const int col = h * 64 + nf * 8 + (lane & 3) * 2;
        float x0 = oac[nf][0] * inv0, x1 = oac[nf][1] * inv0;
        float y0 = oac[nf][2] * inv1, y1 = oac[nf][3] * inv1;
        __nv_bfloat16 hx0 = __float2bfloat16_rn(x0), hx1 = __float2bfloat16_rn(x1);
        __nv_bfloat16 hy0 = __float2bfloat16_rn(y0), hy1 = __float2bfloat16_rn(y1);
        size_t o0 = (rowM0 * DM + col) >> 1;
        size_t o1 = ((rowM0 + 8) * DM + col) >> 1;
        reinterpret_cast<uint32_t*>(Ch)[o0] = packbf(__bfloat162float(hx0), __bfloat162float(hx1));
        reinterpret_cast<uint32_t*>(Cl)[o0] = packbf(x0 - __bfloat162float(hx0), x1 - __bfloat162float(hx1));
        reinterpret_cast<uint32_t*>(Ch)[o1] = packbf(__bfloat162float(hy0), __bfloat162float(hy1));
        reinterpret_cast<uint32_t*>(Cl)[o1] = packbf(y0 - __bfloat162float(hy0), y1 - __bfloat162float(hy1));
    }
    // release ctx row-block
    __threadfence();
    __syncthreads();
    if (tid == 0) atomicAdd(&g_flagA[(b << 4) + qt], 1);
}

// ---------------------------------------------------------------------------
// Fused mega-kernel: QKV gemm tiles -> attention -> out-proj, flag-synced.
// bid 0..767: QKV (M-tiles produced high-s first, x-major N).
// bid 768..1791: attention (qt desc, kt loop desc to track production order).
// bid 1792..2303: out-proj (m-tiles ordered to match attention completion).
// ---------------------------------------------------------------------------
__global__ __launch_bounds__(256, 2)
void fused_mega(const float* __restrict__ bo, float* __restrict__ out)
{
    extern __shared__ __align__(128) char smc[];
    const int bid = blockIdx.x;

    if (bid < 768) {
        const int nt = bid % 24, y = bid / 24;
        const int sblk = 15 - (y >> 1), bq = y & 1;
        const int m0 = ((bq << 4) + sblk) << 7;
        gemm_tile(g_ah, g_al, g_wch, g_wcl, nullptr,
                  g_qh, g_ql, g_kh, g_kl, g_vh, g_vl, g_rope,
                  NQKV, 3, nullptr, m0, nt << 7, smc);
        __threadfence();
        __syncthreads();
        if (threadIdx.x == 0) atomicAdd(&g_flagM[m0 >> 7], 1);
    } else if (bid < 1792) {
        attn_tile(bid - 768, g_qh, g_ql, g_kh, g_kl, g_vh, g_vl, g_ah, g_al, smc);
    } else {
        const int o = bid - 1792;
        const int mi = o >> 4, nb = o & 15;
        const int qtm = 15 - (mi >> 1), bm = mi & 1;
        const int m0 = ((bm << 4) + qtm) << 7;
        spin_ge(&g_flagA[m0 >> 7], 32);
        gemm_tile(g_ah, g_al, g_woh, g_wol, out,
                  nullptr, nullptr, nullptr, nullptr, nullptr, nullptr, nullptr,
                  DM, 0, bo, m0, nb << 7, smc);
    }
}

// ---------------------------------------------------------------------------
// fp32 -> bf16 hi/lo split (hidden states)
// ---------------------------------------------------------------------------
__global__ void split_kernel(const float* __restrict__ x,
                             __nv_bfloat16* __restrict__ hi,
                             __nv_bfloat16* __restrict__ lo, int n4)
{
    int i = blockIdx.x * blockDim.x + threadIdx.x;
    if (i >= n4) return;
    float4 v = reinterpret_cast<const float4*>(x)[i];
    float f[4] = {v.x, v.y, v.z, v.w};
    __nv_bfloat16 h[4], l[4];
#pragma unroll
    for (int j = 0; j < 4; j++) {
        h[j] = __float2bfloat16_rn(f[j]);
        l[j] = __float2bfloat16_rn(f[j] - __bfloat162float(h[j]));
    }
    reinterpret_cast<uint2*>(hi)[i] = *reinterpret_cast<uint2*>(h);
    reinterpret_cast<uint2*>(lo)[i] = *reinterpret_cast<uint2*>(l);
}

// ---------------------------------------------------------------------------
// All weight transposes + rope table + FLAG ZEROING in ONE launch.
// ---------------------------------------------------------------------------
__global__ void prep_weights(const float* __restrict__ Wq, const float* __restrict__ Wk,
                             const float* __restrict__ Wv, const float* __restrict__ Wo,
                             __nv_bfloat16* __restrict__ Tch, __nv_bfloat16* __restrict__ Tcl,
                             __nv_bfloat16* __restrict__ Toh, __nv_bfloat16* __restrict__ Tol,
                             float2* __restrict__ rope)
{
    int bx = blockIdx.x;
    const int tid = threadIdx.y * 32 + threadIdx.x;
    if (bx == 160) {
        if (blockIdx.y == 0) {          // zero the producer/consumer flags
            if (tid < 32)              g_flagM[tid] = 0;
            else if (tid < 64)         g_flagA[tid - 32] = 0;
        }
        int idx = (blockIdx.y * 256 + tid) * 4;
#pragma unroll
        for (int j = 0; j < 4; j++) {
            int id = idx + j;
            int s = id >> 5, pair = id & 31;
            float inv = powf(10000.f, -(float)(2 * pair) * (1.f / 64.f));
            float sn, c;
            sincosf((float)s * inv, &sn, &c);
            rope[id] = make_float2(c, sn);
        }
        return;
    }
    __shared__ float t[32][33];
    const float* W;
    __nv_bfloat16 *Th, *Tl;
    int N, rowoff;
    if (bx < 64)       { W = Wq; N = 2048; rowoff = 0;    Th = Tch; Tl = Tcl; }
    else if (bx < 80)  { W = Wk; N = 512;  rowoff = 2048; Th = Tch; Tl = Tcl; bx -= 64; }
    else if (bx < 96)  { W = Wv; N = 512;  rowoff = 2560; Th = Tch; Tl = Tcl; bx -= 80; }
    else               { W = Wo; N = 2048; rowoff = 0;    Th = Toh; Tl = Tol; bx -= 96; }
    const int n0 = bx * 32, k0 = blockIdx.y * 32;
    const int tx = threadIdx.x, ty = threadIdx.y;
#pragma unroll
    for (int i = 0; i < 4; i++)
        t[ty + 8 * i][tx] = W[(size_t)(k0 + ty + 8 * i) * N + n0 + tx];
    __syncthreads();
#pragma unroll
    for (int i = 0; i < 4; i++) {
        float v = t[tx][ty + 8 * i];
        __nv_bfloat16 h = __float2bfloat16_rn(v);
        __nv_bfloat16 l = __float2bfloat16_rn(v - __bfloat162float(h));
        size_t o = (size_t)(rowoff + n0 + ty + 8 * i) * DM + k0 + tx;
        Th[o] = h; Tl[o] = l;
    }
}

// ---------------------------------------------------------------------------
extern "C" void kernel_launch(void* const* d_in, const int* in_sizes, int n_in,
                              void* d_out, int out_size)
{
    const float* hs = (const float*)d_in[0];
    const float* Wq = (const float*)d_in[1];
    const float* Wk = (const float*)d_in[2];
    const float* Wv = (const float*)d_in[3];
    const float* Wo = (const float*)d_in[4];
    const float* bo = (const float*)d_in[5];
    float* out = (float*)d_out;

    __nv_bfloat16 *ah, *al, *wch, *wcl, *woh, *wol;
    float2* rope;
    cudaGetSymbolAddress((void**)&ah,  g_ah);
    cudaGetSymbolAddress((void**)&al,  g_al);
    cudaGetSymbolAddress((void**)&wch, g_wch);
    cudaGetSymbolAddress((void**)&wcl, g_wcl);
    cudaGetSymbolAddress((void**)&woh, g_woh);
    cudaGetSymbolAddress((void**)&wol, g_wol);
    cudaGetSymbolAddress((void**)&rope, g_rope);

    const int mega_smem = 3 * 32768;   // 96 KB (same for all three phases)
    cudaFuncSetAttribute(fused_mega, cudaFuncAttributeMaxDynamicSharedMemorySize, mega_smem);

    // launch 1: split hs into bf16 hi/lo
    {
        int n4 = MROWS * DM / 4;
        split_kernel<<<(n4 + 255) / 256, 256>>>(hs, ah, al, n4);
    }
    // launch 2: weight transposes + rope table + flag zeroing
    prep_weights<<<dim3(161, 64), dim3(32, 8)>>>(Wq, Wk, Wv, Wo, wch, wcl, woh, wol, rope);

    // launch 3: fused QKV-gemm -> attention -> out-proj (flag-synchronized)
    fused_mega<<<dim3(768 + 1024 + 512), 256, mega_smem>>>(bo, out);
}